// round 3
// baseline (speedup 1.0000x reference)
#include <cuda_runtime.h>
#include <cuda_bf16.h>
#include <cstdint>
#include <cstdio>

// Problem constants
#define NN_   8192
#define T_    32
#define IN_   256
#define H_    256
#define H3_   768
#define E_    1024
#define NNZ_  65536
#define GCN_  256

// ---------------------------------------------------------------------------
// Scratch (static device globals; no runtime allocation)
// ---------------------------------------------------------------------------
__device__ float g_xgall[(size_t)NN_ * T_ * H3_];   // 805 MB precomputed input gates
__device__ float g_h [NN_ * H_];                    // GRU hidden ping
__device__ float g_h2[NN_ * H_];                    // GRU hidden pong
__device__ float g_fa[NN_ * H_];                    // feature ping (last / o2)
__device__ float g_fb[NN_ * H_];                    // feature pong (o1 / o3)
__device__ float g_xw[NN_ * H_];                    // HGC x@W
__device__ float g_agg[NN_ * H_];                   // HGC node aggregation
__device__ float g_eb[E_ * H_];                     // HGC edge accumulator
__device__ float g_x2[NN_ * GCN_];                  // o3 @ gcn_w
__device__ float g_y [NN_ * GCN_];                  // dis_j * x2_j
__device__ unsigned char g_mask[(size_t)NN_ * NN_]; // 64 MB adjacency mask bytes
__device__ float g_deg[NN_];
__device__ float g_Dcnt[NN_];
__device__ float g_Dinv[NN_];
__device__ float g_Bcnt[E_];
__device__ float g_Binv[E_];
__device__ float g_dis[NN_];

// ---------------------------------------------------------------------------
// Packed fp32x2 helpers (Blackwell sm_103a)
// ---------------------------------------------------------------------------
__device__ __forceinline__ void fma2(unsigned long long& d,
                                     unsigned long long a,
                                     unsigned long long b)
{
    asm("fma.rn.f32x2 %0, %1, %2, %0;" : "+l"(d) : "l"(a), "l"(b));
}

__device__ __forceinline__ unsigned long long dup2(float x)
{
    unsigned long long r;
    unsigned u = __float_as_uint(x);
    asm("mov.b64 %0, {%1, %1};" : "=l"(r) : "r"(u));
    return r;
}

__device__ __forceinline__ void unpack2(unsigned long long v, float& lo, float& hi)
{
    unsigned a, b;
    asm("mov.b64 {%0, %1}, %2;" : "=r"(a), "=r"(b) : "l"(v));
    lo = __uint_as_float(a);
    hi = __uint_as_float(b);
}

__device__ __forceinline__ float sigf(float x)
{
    return 1.f / (1.f + __expf(-x));
}

// ---------------------------------------------------------------------------
// Tiled SGEMM with packed f32x2 FMA + double-buffered smem.
// C[M,N] = A[M,K] * op(B) (+bias)
//   TRANSB=true : B is [N,K] row-major (use B^T)  -> NT
//   TRANSB=false: B is [K,N] row-major            -> NN
// BM=BN=128, BK=16, 256 threads, 8x8 microtile, 2 CTAs/SM.
// ---------------------------------------------------------------------------
template<bool TRANSB, bool BIAS>
__global__ __launch_bounds__(256, 2)
void sgemm_f2(const float* __restrict__ A, int lda,
              const float* __restrict__ B, int ldb,
              float* __restrict__ C, int ldc,
              int K, const float* __restrict__ bias)
{
    __shared__ __align__(16) float As[2][16][132];
    __shared__ __align__(16) float Bs[2][16][132];

    const int bm = blockIdx.y * 128;
    const int bn = blockIdx.x * 128;
    const int tid = threadIdx.x;
    const int tx = tid & 15;
    const int ty = tid >> 4;
    const int ar  = tid >> 2;          // 0..63
    const int ac4 = (tid & 3) * 4;     // 0,4,8,12
    const int bkr = tid >> 5;          // 0..7   (NN loader)
    const int bc4 = (tid & 31) * 4;    // 0..124 (NN loader)

    unsigned long long acc[8][4];
#pragma unroll
    for (int i = 0; i < 8; i++)
#pragma unroll
        for (int j = 0; j < 4; j++) acc[i][j] = 0ull;

    float4 a0v, a1v, b0v, b1v;

#define LOAD_TILE(k0)                                                         \
    do {                                                                      \
        const float* Ap = A + (size_t)(bm + ar) * lda + (k0) + ac4;          \
        a0v = *(const float4*)Ap;                                             \
        a1v = *(const float4*)(Ap + (size_t)64 * lda);                        \
        if (TRANSB) {                                                         \
            const float* Bp = B + (size_t)(bn + ar) * ldb + (k0) + ac4;      \
            b0v = *(const float4*)Bp;                                         \
            b1v = *(const float4*)(Bp + (size_t)64 * ldb);                    \
        } else {                                                              \
            const float* Bp = B + (size_t)((k0) + bkr) * ldb + bn + bc4;      \
            b0v = *(const float4*)Bp;                                         \
            b1v = *(const float4*)(Bp + (size_t)8 * ldb);                     \
        }                                                                     \
    } while (0)

#define STORE_TILE(buf)                                                       \
    do {                                                                      \
        As[buf][ac4 + 0][ar] = a0v.x; As[buf][ac4 + 1][ar] = a0v.y;           \
        As[buf][ac4 + 2][ar] = a0v.z; As[buf][ac4 + 3][ar] = a0v.w;           \
        As[buf][ac4 + 0][ar + 64] = a1v.x; As[buf][ac4 + 1][ar + 64] = a1v.y; \
        As[buf][ac4 + 2][ar + 64] = a1v.z; As[buf][ac4 + 3][ar + 64] = a1v.w; \
        if (TRANSB) {                                                         \
            Bs[buf][ac4 + 0][ar] = b0v.x; Bs[buf][ac4 + 1][ar] = b0v.y;       \
            Bs[buf][ac4 + 2][ar] = b0v.z; Bs[buf][ac4 + 3][ar] = b0v.w;       \
            Bs[buf][ac4 + 0][ar + 64] = b1v.x; Bs[buf][ac4 + 1][ar + 64] = b1v.y; \
            Bs[buf][ac4 + 2][ar + 64] = b1v.z; Bs[buf][ac4 + 3][ar + 64] = b1v.w; \
        } else {                                                              \
            *(float4*)&Bs[buf][bkr][bc4] = b0v;                               \
            *(float4*)&Bs[buf][bkr + 8][bc4] = b1v;                           \
        }                                                                     \
    } while (0)

    LOAD_TILE(0);
    STORE_TILE(0);
    __syncthreads();

    const int nk = K >> 4;
    for (int kt = 0; kt < nk; kt++) {
        const int cur = kt & 1;
        if (kt + 1 < nk) LOAD_TILE((kt + 1) * 16);

#pragma unroll
        for (int kk = 0; kk < 16; kk++) {
            float av[8];
            *(float4*)&av[0] = *(const float4*)&As[cur][kk][ty * 8];
            *(float4*)&av[4] = *(const float4*)&As[cur][kk][ty * 8 + 4];
            ulonglong2 bp0 = *(const ulonglong2*)&Bs[cur][kk][tx * 8];
            ulonglong2 bp1 = *(const ulonglong2*)&Bs[cur][kk][tx * 8 + 4];
#pragma unroll
            for (int i = 0; i < 8; i++) {
                unsigned long long ad = dup2(av[i]);
                fma2(acc[i][0], ad, bp0.x);
                fma2(acc[i][1], ad, bp0.y);
                fma2(acc[i][2], ad, bp1.x);
                fma2(acc[i][3], ad, bp1.y);
            }
        }
        if (kt + 1 < nk) STORE_TILE((kt + 1) & 1);
        __syncthreads();
    }
#undef LOAD_TILE
#undef STORE_TILE

    float bv[8];
    if (BIAS) {
        *(float4*)&bv[0] = *(const float4*)(bias + bn + tx * 8);
        *(float4*)&bv[4] = *(const float4*)(bias + bn + tx * 8 + 4);
    }

#pragma unroll
    for (int i = 0; i < 8; i++) {
        int row = bm + ty * 8 + i;
        float o[8];
#pragma unroll
        for (int j = 0; j < 4; j++) unpack2(acc[i][j], o[2 * j], o[2 * j + 1]);
        if (BIAS) {
#pragma unroll
            for (int j = 0; j < 8; j++) o[j] += bv[j];
        }
        float* Cp = C + (size_t)row * ldc + bn + tx * 8;
        *(float4*)Cp = *(float4*)&o[0];
        *(float4*)(Cp + 4) = *(float4*)&o[4];
    }
}

// ---------------------------------------------------------------------------
// Fused GRU step: hg = h_in @ W_hh^T + b_hh for all 3 gates, then gate math,
// writes h_out (and `last` at t == slen-1). 512 threads, 128x128 tile,
// 3 gate accumulator sets per thread (8 rows x 4 cols each as f32x2 pairs).
// Dynamic smem: As[2][16][132] + Bs[2][3][16][132] = 67584 bytes.
// ---------------------------------------------------------------------------
__global__ __launch_bounds__(512)
void gru_step_fused(const float* __restrict__ Wh,
                    const float* __restrict__ bhh,
                    const float* __restrict__ xgall,
                    const float* __restrict__ hin,
                    float* __restrict__ hout,
                    const int* __restrict__ slen,
                    float* __restrict__ last, int t)
{
    extern __shared__ __align__(16) float smx[];
    float* Asp = smx;                      // [2][16][132]
    float* Bsp = smx + 2 * 16 * 132;       // [2][3][16][132]
#define AS_(b,k,m)   Asp[((b) * 16 + (k)) * 132 + (m)]
#define BS_(b,g,k,m) Bsp[(((b) * 3 + (g)) * 16 + (k)) * 132 + (m)]

    const int bm = blockIdx.y * 128;
    const int bn = blockIdx.x * 128;       // 0 or 128
    const int tid = threadIdx.x;
    const int tx = tid & 31;               // 32 -> 4 cols each
    const int ty = tid >> 5;               // 16 -> 8 rows each
    const int ar  = tid >> 2;              // 0..127
    const int ac4 = (tid & 3) * 4;

    unsigned long long acc[3][8][2];
#pragma unroll
    for (int g = 0; g < 3; g++)
#pragma unroll
        for (int i = 0; i < 8; i++) { acc[g][i][0] = 0ull; acc[g][i][1] = 0ull; }

    float4 aav, bbv0, bbv1, bbv2;

#define GLOAD(k0)                                                             \
    do {                                                                      \
        aav  = *(const float4*)(hin + (size_t)(bm + ar) * H_ + (k0) + ac4);   \
        bbv0 = *(const float4*)(Wh + (size_t)(bn + ar) * H_ + (k0) + ac4);    \
        bbv1 = *(const float4*)(Wh + (size_t)(256 + bn + ar) * H_ + (k0) + ac4); \
        bbv2 = *(const float4*)(Wh + (size_t)(512 + bn + ar) * H_ + (k0) + ac4); \
    } while (0)

#define GSTORE(buf)                                                           \
    do {                                                                      \
        AS_(buf, ac4 + 0, ar) = aav.x; AS_(buf, ac4 + 1, ar) = aav.y;         \
        AS_(buf, ac4 + 2, ar) = aav.z; AS_(buf, ac4 + 3, ar) = aav.w;         \
        BS_(buf, 0, ac4 + 0, ar) = bbv0.x; BS_(buf, 0, ac4 + 1, ar) = bbv0.y; \
        BS_(buf, 0, ac4 + 2, ar) = bbv0.z; BS_(buf, 0, ac4 + 3, ar) = bbv0.w; \
        BS_(buf, 1, ac4 + 0, ar) = bbv1.x; BS_(buf, 1, ac4 + 1, ar) = bbv1.y; \
        BS_(buf, 1, ac4 + 2, ar) = bbv1.z; BS_(buf, 1, ac4 + 3, ar) = bbv1.w; \
        BS_(buf, 2, ac4 + 0, ar) = bbv2.x; BS_(buf, 2, ac4 + 1, ar) = bbv2.y; \
        BS_(buf, 2, ac4 + 2, ar) = bbv2.z; BS_(buf, 2, ac4 + 3, ar) = bbv2.w; \
    } while (0)

    GLOAD(0);
    GSTORE(0);
    __syncthreads();

    const int nk = H_ >> 4;   // 16
    for (int kt = 0; kt < nk; kt++) {
        const int cur = kt & 1;
        if (kt + 1 < nk) GLOAD((kt + 1) * 16);

#pragma unroll
        for (int kk = 0; kk < 16; kk++) {
            float av[8];
            *(float4*)&av[0] = *(const float4*)&AS_(cur, kk, ty * 8);
            *(float4*)&av[4] = *(const float4*)&AS_(cur, kk, ty * 8 + 4);
            ulonglong2 bp0 = *(const ulonglong2*)&BS_(cur, 0, kk, tx * 4);
            ulonglong2 bp1 = *(const ulonglong2*)&BS_(cur, 1, kk, tx * 4);
            ulonglong2 bp2 = *(const ulonglong2*)&BS_(cur, 2, kk, tx * 4);
#pragma unroll
            for (int i = 0; i < 8; i++) {
                unsigned long long ad = dup2(av[i]);
                fma2(acc[0][i][0], ad, bp0.x); fma2(acc[0][i][1], ad, bp0.y);
                fma2(acc[1][i][0], ad, bp1.x); fma2(acc[1][i][1], ad, bp1.y);
                fma2(acc[2][i][0], ad, bp2.x); fma2(acc[2][i][1], ad, bp2.y);
            }
        }
        if (kt + 1 < nk) GSTORE((kt + 1) & 1);
        __syncthreads();
    }
#undef GLOAD
#undef GSTORE
#undef AS_
#undef BS_

    // epilogue: gate nonlinearity
    const int c = bn + tx * 4;
    float4 br = *(const float4*)(bhh + c);
    float4 bz = *(const float4*)(bhh + 256 + c);
    float4 bq = *(const float4*)(bhh + 512 + c);

#pragma unroll
    for (int i = 0; i < 8; i++) {
        int row = bm + ty * 8 + i;
        float hr[4], hz[4], hq[4];
        unpack2(acc[0][i][0], hr[0], hr[1]); unpack2(acc[0][i][1], hr[2], hr[3]);
        unpack2(acc[1][i][0], hz[0], hz[1]); unpack2(acc[1][i][1], hz[2], hz[3]);
        unpack2(acc[2][i][0], hq[0], hq[1]); unpack2(acc[2][i][1], hq[2], hq[3]);

        size_t xb = ((size_t)row * T_ + t) * H3_ + c;
        float4 xr = *(const float4*)(xgall + xb);
        float4 xz = *(const float4*)(xgall + xb + 256);
        float4 xq = *(const float4*)(xgall + xb + 512);
        float4 hold = *(const float4*)(hin + (size_t)row * H_ + c);

        float4 hn;
        {
            float r0 = sigf(xr.x + hr[0] + br.x);
            float z0 = sigf(xz.x + hz[0] + bz.x);
            float q0 = tanhf(xq.x + r0 * (hq[0] + bq.x));
            hn.x = (1.f - z0) * q0 + z0 * hold.x;
            float r1 = sigf(xr.y + hr[1] + br.y);
            float z1 = sigf(xz.y + hz[1] + bz.y);
            float q1 = tanhf(xq.y + r1 * (hq[1] + bq.y));
            hn.y = (1.f - z1) * q1 + z1 * hold.y;
            float r2 = sigf(xr.z + hr[2] + br.z);
            float z2 = sigf(xz.z + hz[2] + bz.z);
            float q2 = tanhf(xq.z + r2 * (hq[2] + bq.z));
            hn.z = (1.f - z2) * q2 + z2 * hold.z;
            float r3 = sigf(xr.w + hr[3] + br.w);
            float z3 = sigf(xz.w + hz[3] + bz.w);
            float q3 = tanhf(xq.w + r3 * (hq[3] + bq.w));
            hn.w = (1.f - z3) * q3 + z3 * hold.w;
        }
        *(float4*)(hout + (size_t)row * H_ + c) = hn;
        if (t == slen[row] - 1)
            *(float4*)(last + (size_t)row * H_ + c) = hn;
    }
}

// ---------------------------------------------------------------------------
// GRU support
// ---------------------------------------------------------------------------
__global__ void init_h_kernel(float* __restrict__ h, const float* __restrict__ h0)
{
    int idx = blockIdx.x * 256 + threadIdx.x;
    h[idx] = h0[idx & (H_ - 1)];
}

// ---------------------------------------------------------------------------
// Hypergraph conv support
// ---------------------------------------------------------------------------
__global__ void zero_kernel(float* __restrict__ p, int n4)
{
    int i = blockIdx.x * 256 + threadIdx.x;
    if (i < n4) ((float4*)p)[i] = make_float4(0.f, 0.f, 0.f, 0.f);
}

__global__ void count_deg_kernel(const int* __restrict__ node_idx,
                                 const int* __restrict__ edge_idx,
                                 float* __restrict__ D, float* __restrict__ B)
{
    int i = blockIdx.x * 256 + threadIdx.x;
    if (i < NNZ_) {
        atomicAdd(&D[node_idx[i]], 1.f);
        atomicAdd(&B[edge_idx[i]], 1.f);
    }
}

__global__ void make_inv_kernel(const float* __restrict__ cnt, float* __restrict__ inv, int n)
{
    int i = blockIdx.x * 256 + threadIdx.x;
    if (i < n) {
        float c = cnt[i];
        inv[i] = c > 0.f ? 1.f / c : 0.f;
    }
}

__global__ void scatter_edge_kernel(const float* __restrict__ xw,
                                    const int* __restrict__ node_idx,
                                    const int* __restrict__ edge_idx,
                                    float* __restrict__ eb)
{
    int idx = blockIdx.x * 256 + threadIdx.x;   // NNZ * 64
    int nz = idx >> 6;
    int c4 = (idx & 63) << 2;
    int n = node_idx[nz];
    int e = edge_idx[nz];
    float4 v = *(const float4*)(xw + (size_t)n * H_ + c4);
    float* dst = eb + (size_t)e * H_ + c4;
    atomicAdd(dst + 0, v.x); atomicAdd(dst + 1, v.y);
    atomicAdd(dst + 2, v.z); atomicAdd(dst + 3, v.w);
}

__global__ void scatter_node_kernel(const float* __restrict__ eb,
                                    const int* __restrict__ node_idx,
                                    const int* __restrict__ edge_idx,
                                    const float* __restrict__ Binv,
                                    float* __restrict__ agg)
{
    int idx = blockIdx.x * 256 + threadIdx.x;   // NNZ * 64
    int nz = idx >> 6;
    int c4 = (idx & 63) << 2;
    int n = node_idx[nz];
    int e = edge_idx[nz];
    float be = Binv[e];
    float4 v = *(const float4*)(eb + (size_t)e * H_ + c4);
    float* dst = agg + (size_t)n * H_ + c4;
    atomicAdd(dst + 0, v.x * be); atomicAdd(dst + 1, v.y * be);
    atomicAdd(dst + 2, v.z * be); atomicAdd(dst + 3, v.w * be);
}

__global__ void hgc_finish_kernel(const float* __restrict__ agg,
                                  const float* __restrict__ Dinv,
                                  const float* __restrict__ bias,
                                  const float* __restrict__ resid,
                                  float* __restrict__ out)
{
    int idx = blockIdx.x * 256 + threadIdx.x;   // N*H
    int n = idx >> 8;
    int c = idx & 255;
    out[idx] = agg[idx] * Dinv[n] + bias[c] + resid[idx];
}

// ---------------------------------------------------------------------------
// Symmetric gram + mask + degree. Upper-triangle block tiles only
// (2080 blocks for 64x64 block grid). Epilogue writes the 0/1 byte mask for
// both (i,j) and (j,i) orientations and accumulates row degrees atomically.
// ---------------------------------------------------------------------------
__global__ __launch_bounds__(256, 2)
void gram_sym_kernel(const float* __restrict__ X,
                     unsigned char* __restrict__ mask,
                     float* __restrict__ deg,
                     const float* __restrict__ phi_p)
{
    __shared__ __align__(16) float As[2][16][132];
    __shared__ __align__(16) float Bs[2][16][132];

    // decode upper-triangle pair (bi <= bj)
    int k = blockIdx.x;
    int bi = 0;
    while (k >= 64 - bi) { k -= 64 - bi; bi++; }
    const int bj = bi + k;
    const int bm = bi * 128;
    const int bn = bj * 128;

    const int tid = threadIdx.x;
    const int tx = tid & 15;
    const int ty = tid >> 4;
    const int ar  = tid >> 2;
    const int ac4 = (tid & 3) * 4;

    unsigned long long acc[8][4];
#pragma unroll
    for (int i = 0; i < 8; i++)
#pragma unroll
        for (int j = 0; j < 4; j++) acc[i][j] = 0ull;

    float4 a0v, a1v, b0v, b1v;

#define GRLOAD(k0)                                                            \
    do {                                                                      \
        const float* Ap = X + (size_t)(bm + ar) * H_ + (k0) + ac4;            \
        a0v = *(const float4*)Ap;                                             \
        a1v = *(const float4*)(Ap + (size_t)64 * H_);                         \
        const float* Bp = X + (size_t)(bn + ar) * H_ + (k0) + ac4;            \
        b0v = *(const float4*)Bp;                                             \
        b1v = *(const float4*)(Bp + (size_t)64 * H_);                         \
    } while (0)

#define GRSTORE(buf)                                                          \
    do {                                                                      \
        As[buf][ac4 + 0][ar] = a0v.x; As[buf][ac4 + 1][ar] = a0v.y;           \
        As[buf][ac4 + 2][ar] = a0v.z; As[buf][ac4 + 3][ar] = a0v.w;           \
        As[buf][ac4 + 0][ar + 64] = a1v.x; As[buf][ac4 + 1][ar + 64] = a1v.y; \
        As[buf][ac4 + 2][ar + 64] = a1v.z; As[buf][ac4 + 3][ar + 64] = a1v.w; \
        Bs[buf][ac4 + 0][ar] = b0v.x; Bs[buf][ac4 + 1][ar] = b0v.y;           \
        Bs[buf][ac4 + 2][ar] = b0v.z; Bs[buf][ac4 + 3][ar] = b0v.w;           \
        Bs[buf][ac4 + 0][ar + 64] = b1v.x; Bs[buf][ac4 + 1][ar + 64] = b1v.y; \
        Bs[buf][ac4 + 2][ar + 64] = b1v.z; Bs[buf][ac4 + 3][ar + 64] = b1v.w; \
    } while (0)

    GRLOAD(0);
    GRSTORE(0);
    __syncthreads();

    const int nk = H_ >> 4;
    for (int kt = 0; kt < nk; kt++) {
        const int cur = kt & 1;
        if (kt + 1 < nk) GRLOAD((kt + 1) * 16);
#pragma unroll
        for (int kk = 0; kk < 16; kk++) {
            float av[8];
            *(float4*)&av[0] = *(const float4*)&As[cur][kk][ty * 8];
            *(float4*)&av[4] = *(const float4*)&As[cur][kk][ty * 8 + 4];
            ulonglong2 bp0 = *(const ulonglong2*)&Bs[cur][kk][tx * 8];
            ulonglong2 bp1 = *(const ulonglong2*)&Bs[cur][kk][tx * 8 + 4];
#pragma unroll
            for (int i = 0; i < 8; i++) {
                unsigned long long ad = dup2(av[i]);
                fma2(acc[i][0], ad, bp0.x);
                fma2(acc[i][1], ad, bp0.y);
                fma2(acc[i][2], ad, bp1.x);
                fma2(acc[i][3], ad, bp1.y);
            }
        }
        if (kt + 1 < nk) GRSTORE((kt + 1) & 1);
        __syncthreads();
    }
#undef GRLOAD
#undef GRSTORE

    const float thr = phi_p[0] * 65536.0f;
    unsigned m[8][8];
    float colcnt[8];
#pragma unroll
    for (int j = 0; j < 8; j++) colcnt[j] = 0.f;

#pragma unroll
    for (int i = 0; i < 8; i++) {
        int row = bm + ty * 8 + i;
        float v[8];
#pragma unroll
        for (int j = 0; j < 4; j++) unpack2(acc[i][j], v[2 * j], v[2 * j + 1]);
        unsigned long long pack = 0ull;
        float rowcnt = 0.f;
#pragma unroll
        for (int j = 0; j < 8; j++) {
            int col = bn + tx * 8 + j;
            unsigned b = (v[j] >= thr || row == col) ? 1u : 0u;
            m[i][j] = b;
            pack |= (unsigned long long)b << (8 * j);
            rowcnt += (float)b;
            colcnt[j] += (float)b;
        }
        *(unsigned long long*)(mask + (size_t)row * NN_ + bn + tx * 8) = pack;
        atomicAdd(&deg[row], rowcnt);
    }

    if (bi != bj) {
        // transposed orientation
#pragma unroll
        for (int j = 0; j < 8; j++) {
            int col = bn + tx * 8 + j;
            unsigned long long pack = 0ull;
#pragma unroll
            for (int i = 0; i < 8; i++)
                pack |= (unsigned long long)m[i][j] << (8 * i);
            *(unsigned long long*)(mask + (size_t)col * NN_ + bm + ty * 8) = pack;
            atomicAdd(&deg[col], colcnt[j]);
        }
    }
}

__global__ void dis_kernel(const float* __restrict__ deg, float* __restrict__ dis)
{
    int i = blockIdx.x * 256 + threadIdx.x;
    if (i < NN_) {
        float d = deg[i];
        dis[i] = d > 0.f ? rsqrtf(d) : 0.f;
    }
}

__global__ void yscale_kernel(const float* __restrict__ x2,
                              const float* __restrict__ dis,
                              float* __restrict__ y)
{
    int idx = blockIdx.x * 256 + threadIdx.x;   // N*GCN
    int n = idx >> 8;
    y[idx] = x2[idx] * dis[n];
}

// ---------------------------------------------------------------------------
// Masked GCN GEMM from byte mask: out[i,d] = dis_i * sum_j mask_ij * Y[j,d] + b[d]
// ---------------------------------------------------------------------------
__global__ __launch_bounds__(256, 2)
void gcn_gemm_b(const unsigned char* __restrict__ mask,
                const float* __restrict__ Y,
                const float* __restrict__ dis,
                const float* __restrict__ bias,
                float* __restrict__ out)
{
    __shared__ __align__(16) float As[2][16][132];
    __shared__ __align__(16) float Bs[2][16][132];

    const int bm = blockIdx.y * 128;
    const int bn = blockIdx.x * 128;
    const int tid = threadIdx.x;
    const int tx = tid & 15;
    const int ty = tid >> 4;
    const int ar2  = tid >> 1;         // 0..127
    const int half = tid & 1;
    const int bkr = tid >> 5;
    const int bc4 = (tid & 31) * 4;

    unsigned long long acc[8][4];
#pragma unroll
    for (int i = 0; i < 8; i++)
#pragma unroll
        for (int j = 0; j < 4; j++) acc[i][j] = 0ull;

    unsigned long long am;
    float4 b0v, b1v;

#define MLOAD(k0)                                                             \
    do {                                                                      \
        am = *(const unsigned long long*)(mask + (size_t)(bm + ar2) * NN_ + (k0) + half * 8); \
        const float* Bp = Y + (size_t)((k0) + bkr) * GCN_ + bn + bc4;         \
        b0v = *(const float4*)Bp;                                             \
        b1v = *(const float4*)(Bp + (size_t)8 * GCN_);                        \
    } while (0)

#define MSTORE(buf)                                                           \
    do {                                                                      \
        _Pragma("unroll")                                                     \
        for (int b = 0; b < 8; b++)                                           \
            As[buf][half * 8 + b][ar2] = (float)((am >> (8 * b)) & 0xFFull);  \
        *(float4*)&Bs[buf][bkr][bc4] = b0v;                                   \
        *(float4*)&Bs[buf][bkr + 8][bc4] = b1v;                               \
    } while (0)

    MLOAD(0);
    MSTORE(0);
    __syncthreads();

    const int nk = NN_ >> 4;
    for (int kt = 0; kt < nk; kt++) {
        const int cur = kt & 1;
        if (kt + 1 < nk) MLOAD((kt + 1) * 16);
#pragma unroll
        for (int kk = 0; kk < 16; kk++) {
            float av[8];
            *(float4*)&av[0] = *(const float4*)&As[cur][kk][ty * 8];
            *(float4*)&av[4] = *(const float4*)&As[cur][kk][ty * 8 + 4];
            ulonglong2 bp0 = *(const ulonglong2*)&Bs[cur][kk][tx * 8];
            ulonglong2 bp1 = *(const ulonglong2*)&Bs[cur][kk][tx * 8 + 4];
#pragma unroll
            for (int i = 0; i < 8; i++) {
                unsigned long long ad = dup2(av[i]);
                fma2(acc[i][0], ad, bp0.x);
                fma2(acc[i][1], ad, bp0.y);
                fma2(acc[i][2], ad, bp1.x);
                fma2(acc[i][3], ad, bp1.y);
            }
        }
        if (kt + 1 < nk) MSTORE((kt + 1) & 1);
        __syncthreads();
    }
#undef MLOAD
#undef MSTORE

    float bv[8];
    *(float4*)&bv[0] = *(const float4*)(bias + bn + tx * 8);
    *(float4*)&bv[4] = *(const float4*)(bias + bn + tx * 8 + 4);

#pragma unroll
    for (int i = 0; i < 8; i++) {
        int row = bm + ty * 8 + i;
        float di = dis[row];
        float o[8];
#pragma unroll
        for (int j = 0; j < 4; j++) unpack2(acc[i][j], o[2 * j], o[2 * j + 1]);
#pragma unroll
        for (int j = 0; j < 8; j++) o[j] = di * o[j] + bv[j];
        float* Cp = out + (size_t)row * GCN_ + bn + tx * 8;
        *(float4*)Cp = *(float4*)&o[0];
        *(float4*)(Cp + 4) = *(float4*)&o[4];
    }
}

// ---------------------------------------------------------------------------
// Host orchestration
// ---------------------------------------------------------------------------
static void hgc_layer(const float* in, const float* W, const float* b,
                      const int* node_idx, const int* edge_idx,
                      float* xw, float* eb, float* agg,
                      const float* Dinv, const float* Binv, float* outbuf)
{
    sgemm_f2<false, false><<<dim3(H_ / 128, NN_ / 128), 256>>>(
        in, H_, W, H_, xw, H_, H_, nullptr);
    zero_kernel<<<(E_ * H_ / 4 + 255) / 256, 256>>>(eb, E_ * H_ / 4);
    scatter_edge_kernel<<<NNZ_ * 64 / 256, 256>>>(xw, node_idx, edge_idx, eb);
    zero_kernel<<<(NN_ * H_ / 4 + 255) / 256, 256>>>(agg, NN_ * H_ / 4);
    scatter_node_kernel<<<NNZ_ * 64 / 256, 256>>>(eb, node_idx, edge_idx, Binv, agg);
    hgc_finish_kernel<<<NN_ * H_ / 256, 256>>>(agg, Dinv, b, in, outbuf);
}

extern "C" void kernel_launch(void* const* d_in, const int* in_sizes, int n_in,
                              void* d_out, int out_size)
{
    (void)in_sizes; (void)n_in; (void)out_size;

    const float* x        = (const float*)d_in[0];
    const int*   hei      = (const int*)d_in[1];
    const int*   node_idx = hei;
    const int*   edge_idx = hei + NNZ_;
    const int*   slen     = (const int*)d_in[2];
    const float* h0       = (const float*)d_in[3];
    const float* W_ih     = (const float*)d_in[4];
    const float* W_hh     = (const float*)d_in[5];
    const float* b_ih     = (const float*)d_in[6];
    const float* b_hh     = (const float*)d_in[7];
    const float* w1 = (const float*)d_in[8];  const float* bb1 = (const float*)d_in[9];
    const float* w2 = (const float*)d_in[10]; const float* bb2 = (const float*)d_in[11];
    const float* w3 = (const float*)d_in[12]; const float* bb3 = (const float*)d_in[13];
    const float* phi = (const float*)d_in[14];
    const float* gw  = (const float*)d_in[15];
    const float* gb  = (const float*)d_in[16];
    float* out = (float*)d_out;

    float *xgall, *h, *h2, *fa, *fb, *xw, *eb, *agg, *x2, *y;
    float *deg, *Dcnt, *Dinv, *Bcnt, *Binv, *dis;
    unsigned char* mask;
    cudaGetSymbolAddress((void**)&xgall, g_xgall);
    cudaGetSymbolAddress((void**)&h,     g_h);
    cudaGetSymbolAddress((void**)&h2,    g_h2);
    cudaGetSymbolAddress((void**)&fa,    g_fa);
    cudaGetSymbolAddress((void**)&fb,    g_fb);
    cudaGetSymbolAddress((void**)&xw,    g_xw);
    cudaGetSymbolAddress((void**)&eb,    g_eb);
    cudaGetSymbolAddress((void**)&agg,   g_agg);
    cudaGetSymbolAddress((void**)&x2,    g_x2);
    cudaGetSymbolAddress((void**)&y,     g_y);
    cudaGetSymbolAddress((void**)&mask,  g_mask);
    cudaGetSymbolAddress((void**)&deg,   g_deg);
    cudaGetSymbolAddress((void**)&Dcnt,  g_Dcnt);
    cudaGetSymbolAddress((void**)&Dinv,  g_Dinv);
    cudaGetSymbolAddress((void**)&Bcnt,  g_Bcnt);
    cudaGetSymbolAddress((void**)&Binv,  g_Binv);
    cudaGetSymbolAddress((void**)&dis,   g_dis);

    // Allow >48KB dynamic smem for the fused GRU step (idempotent).
    const int GRU_SMEM = (2 * 16 * 132 + 2 * 3 * 16 * 132) * 4;   // 67584 B
    cudaFuncSetAttribute(gru_step_fused,
                         cudaFuncAttributeMaxDynamicSharedMemorySize, GRU_SMEM);

    // ---------------- GRU ----------------
    init_h_kernel<<<NN_ * H_ / 256, 256>>>(h, h0);

    // All input gates in one large GEMM: x viewed as [N*T, IN].
    sgemm_f2<true, true><<<dim3(H3_ / 128, NN_ * T_ / 128), 256>>>(
        x, IN_, W_ih, IN_, xgall, H3_, IN_, b_ih);

    float* hr = h;
    float* hw = h2;
    for (int t = 0; t < T_; t++) {
        gru_step_fused<<<dim3(H_ / 128, NN_ / 128), 512, GRU_SMEM>>>(
            W_hh, b_hh, xgall, hr, hw, slen, fa, t);
        float* tmp = hr; hr = hw; hw = tmp;
    }
    // fa now holds `last` [N,H]

    // ---------------- degrees (shared by 3 HGC layers) ----------------
    zero_kernel<<<(NN_ / 4 + 255) / 256, 256>>>(Dcnt, NN_ / 4);
    zero_kernel<<<(E_ / 4 + 255) / 256, 256>>>(Bcnt, E_ / 4);
    count_deg_kernel<<<NNZ_ / 256, 256>>>(node_idx, edge_idx, Dcnt, Bcnt);
    make_inv_kernel<<<(NN_ + 255) / 256, 256>>>(Dcnt, Dinv, NN_);
    make_inv_kernel<<<(E_ + 255) / 256, 256>>>(Bcnt, Binv, E_);

    // ---------------- 3 hypergraph conv layers with residuals ----------------
    hgc_layer(fa, w1, bb1, node_idx, edge_idx, xw, eb, agg, Dinv, Binv, fb); // o1 = fb
    hgc_layer(fb, w2, bb2, node_idx, edge_idx, xw, eb, agg, Dinv, Binv, fa); // o2 = fa
    hgc_layer(fa, w3, bb3, node_idx, edge_idx, xw, eb, agg, Dinv, Binv, fb); // o3 = fb

    // ---------------- final dense GCN ----------------
    // x2 = o3 @ gcn_w
    sgemm_f2<false, false><<<dim3(GCN_ / 128, NN_ / 128), 256>>>(
        fb, H_, gw, GCN_, x2, GCN_, H_, nullptr);

    // symmetric gram -> byte mask + degrees (adj never materialized)
    zero_kernel<<<(NN_ / 4 + 255) / 256, 256>>>(deg, NN_ / 4);
    gram_sym_kernel<<<64 * 65 / 2, 256>>>(fb, mask, deg, phi);
    dis_kernel<<<(NN_ + 255) / 256, 256>>>(deg, dis);
    yscale_kernel<<<NN_ * GCN_ / 256, 256>>>(x2, dis, y);
    gcn_gemm_b<<<dim3(GCN_ / 128, NN_ / 128), 256>>>(mask, y, dis, gb, out);
}

// round 4
// speedup vs baseline: 1.6882x; 1.6882x over previous
#include <cuda_runtime.h>
#include <cuda_bf16.h>
#include <cstdint>
#include <cstdio>

// Problem constants
#define NN_   8192
#define T_    32
#define IN_   256
#define H_    256
#define H3_   768
#define E_    1024
#define NNZ_  65536
#define GCN_  256

// ---------------------------------------------------------------------------
// Scratch (static device globals; no runtime allocation)
// ---------------------------------------------------------------------------
__device__ float g_xgall[(size_t)NN_ * T_ * H3_];   // [t][pos][768] t-major, sorted rows
__device__ float g_h [NN_ * H_];                    // GRU hidden ping (sorted order)
__device__ float g_h2[NN_ * H_];                    // GRU hidden pong (sorted order)
__device__ float g_fa[NN_ * H_];                    // feature ping (last / o2)
__device__ float g_fb[NN_ * H_];                    // feature pong (o1 / o3)
__device__ float g_xw[NN_ * H_];                    // HGC x@W
__device__ float g_agg[NN_ * H_];                   // HGC node aggregation
__device__ float g_eb[E_ * H_];                     // HGC edge accumulator
__device__ float g_x2[NN_ * GCN_];                  // o3 @ gcn_w
__device__ float g_y [NN_ * GCN_];                  // dis_j * x2_j
__device__ unsigned char g_mask[(size_t)NN_ * NN_]; // 64 MB adjacency mask bytes
__device__ float g_deg[NN_];
__device__ float g_Dcnt[NN_];
__device__ float g_Dinv[NN_];
__device__ float g_Bcnt[E_];
__device__ float g_Binv[E_];
__device__ float g_dis[NN_];
// sort machinery
__device__ int g_perm[NN_];    // perm[pos] = original row
__device__ int g_hist[32];
__device__ int g_cur[32];
__device__ int g_start[32];
__device__ int g_cnt[T_ + 1];  // cnt[t] = #rows active at step t (slen >= t+1); cnt[32]=0

// ---------------------------------------------------------------------------
// Packed fp32x2 helpers (Blackwell sm_103a)
// ---------------------------------------------------------------------------
__device__ __forceinline__ void fma2(unsigned long long& d,
                                     unsigned long long a,
                                     unsigned long long b)
{
    asm("fma.rn.f32x2 %0, %1, %2, %0;" : "+l"(d) : "l"(a), "l"(b));
}

__device__ __forceinline__ unsigned long long dup2(float x)
{
    unsigned long long r;
    unsigned u = __float_as_uint(x);
    asm("mov.b64 %0, {%1, %1};" : "=l"(r) : "r"(u));
    return r;
}

__device__ __forceinline__ void unpack2(unsigned long long v, float& lo, float& hi)
{
    unsigned a, b;
    asm("mov.b64 {%0, %1}, %2;" : "=r"(a), "=r"(b) : "l"(v));
    lo = __uint_as_float(a);
    hi = __uint_as_float(b);
}

__device__ __forceinline__ float sigf(float x)
{
    return 1.f / (1.f + __expf(-x));
}

// ---------------------------------------------------------------------------
// Tiled SGEMM with packed f32x2 FMA + double-buffered smem.
// C[M,N] = A[M,K] * op(B) (+bias)
// BM=BN=128, BK=16, 256 threads, 8x8 microtile, 2 CTAs/SM.
// ---------------------------------------------------------------------------
template<bool TRANSB, bool BIAS>
__global__ __launch_bounds__(256, 2)
void sgemm_f2(const float* __restrict__ A, int lda,
              const float* __restrict__ B, int ldb,
              float* __restrict__ C, int ldc,
              int K, const float* __restrict__ bias)
{
    __shared__ __align__(16) float As[2][16][132];
    __shared__ __align__(16) float Bs[2][16][132];

    const int bm = blockIdx.y * 128;
    const int bn = blockIdx.x * 128;
    const int tid = threadIdx.x;
    const int tx = tid & 15;
    const int ty = tid >> 4;
    const int ar  = tid >> 2;          // 0..63
    const int ac4 = (tid & 3) * 4;     // 0,4,8,12
    const int bkr = tid >> 5;          // 0..7   (NN loader)
    const int bc4 = (tid & 31) * 4;    // 0..124 (NN loader)

    unsigned long long acc[8][4];
#pragma unroll
    for (int i = 0; i < 8; i++)
#pragma unroll
        for (int j = 0; j < 4; j++) acc[i][j] = 0ull;

    float4 a0v, a1v, b0v, b1v;

#define LOAD_TILE(k0)                                                         \
    do {                                                                      \
        const float* Ap = A + (size_t)(bm + ar) * lda + (k0) + ac4;          \
        a0v = *(const float4*)Ap;                                             \
        a1v = *(const float4*)(Ap + (size_t)64 * lda);                        \
        if (TRANSB) {                                                         \
            const float* Bp = B + (size_t)(bn + ar) * ldb + (k0) + ac4;      \
            b0v = *(const float4*)Bp;                                         \
            b1v = *(const float4*)(Bp + (size_t)64 * ldb);                    \
        } else {                                                              \
            const float* Bp = B + (size_t)((k0) + bkr) * ldb + bn + bc4;      \
            b0v = *(const float4*)Bp;                                         \
            b1v = *(const float4*)(Bp + (size_t)8 * ldb);                     \
        }                                                                     \
    } while (0)

#define STORE_TILE(buf)                                                       \
    do {                                                                      \
        As[buf][ac4 + 0][ar] = a0v.x; As[buf][ac4 + 1][ar] = a0v.y;           \
        As[buf][ac4 + 2][ar] = a0v.z; As[buf][ac4 + 3][ar] = a0v.w;           \
        As[buf][ac4 + 0][ar + 64] = a1v.x; As[buf][ac4 + 1][ar + 64] = a1v.y; \
        As[buf][ac4 + 2][ar + 64] = a1v.z; As[buf][ac4 + 3][ar + 64] = a1v.w; \
        if (TRANSB) {                                                         \
            Bs[buf][ac4 + 0][ar] = b0v.x; Bs[buf][ac4 + 1][ar] = b0v.y;       \
            Bs[buf][ac4 + 2][ar] = b0v.z; Bs[buf][ac4 + 3][ar] = b0v.w;       \
            Bs[buf][ac4 + 0][ar + 64] = b1v.x; Bs[buf][ac4 + 1][ar + 64] = b1v.y; \
            Bs[buf][ac4 + 2][ar + 64] = b1v.z; Bs[buf][ac4 + 3][ar + 64] = b1v.w; \
        } else {                                                              \
            *(float4*)&Bs[buf][bkr][bc4] = b0v;                               \
            *(float4*)&Bs[buf][bkr + 8][bc4] = b1v;                           \
        }                                                                     \
    } while (0)

    LOAD_TILE(0);
    STORE_TILE(0);
    __syncthreads();

    const int nk = K >> 4;
    for (int kt = 0; kt < nk; kt++) {
        const int cur = kt & 1;
        if (kt + 1 < nk) LOAD_TILE((kt + 1) * 16);

#pragma unroll
        for (int kk = 0; kk < 16; kk++) {
            float av[8];
            *(float4*)&av[0] = *(const float4*)&As[cur][kk][ty * 8];
            *(float4*)&av[4] = *(const float4*)&As[cur][kk][ty * 8 + 4];
            ulonglong2 bp0 = *(const ulonglong2*)&Bs[cur][kk][tx * 8];
            ulonglong2 bp1 = *(const ulonglong2*)&Bs[cur][kk][tx * 8 + 4];
#pragma unroll
            for (int i = 0; i < 8; i++) {
                unsigned long long ad = dup2(av[i]);
                fma2(acc[i][0], ad, bp0.x);
                fma2(acc[i][1], ad, bp0.y);
                fma2(acc[i][2], ad, bp1.x);
                fma2(acc[i][3], ad, bp1.y);
            }
        }
        if (kt + 1 < nk) STORE_TILE((kt + 1) & 1);
        __syncthreads();
    }
#undef LOAD_TILE
#undef STORE_TILE

    float bv[8];
    if (BIAS) {
        *(float4*)&bv[0] = *(const float4*)(bias + bn + tx * 8);
        *(float4*)&bv[4] = *(const float4*)(bias + bn + tx * 8 + 4);
    }

#pragma unroll
    for (int i = 0; i < 8; i++) {
        int row = bm + ty * 8 + i;
        float o[8];
#pragma unroll
        for (int j = 0; j < 4; j++) unpack2(acc[i][j], o[2 * j], o[2 * j + 1]);
        if (BIAS) {
#pragma unroll
            for (int j = 0; j < 8; j++) o[j] += bv[j];
        }
        float* Cp = C + (size_t)row * ldc + bn + tx * 8;
        *(float4*)Cp = *(float4*)&o[0];
        *(float4*)(Cp + 4) = *(float4*)&o[4];
    }
}

// ---------------------------------------------------------------------------
// Input-gate GEMM over sorted rows with dead-block skipping.
// C row (t*NN + pos): xgall[t][pos] = x[perm[pos], t, :] @ W_ih^T + b_ih
// Grid: (H3/128, T*NN/128). Block covers one t (NN % 128 == 0).
// Skips the block entirely if its row slab is past cnt[t].
// ---------------------------------------------------------------------------
__global__ __launch_bounds__(256, 2)
void xg_gemm(const float* __restrict__ x,
             const float* __restrict__ Wih,
             const float* __restrict__ bih,
             const int* __restrict__ perm,
             const int* __restrict__ cnt,
             float* __restrict__ xgall)
{
    const int bm = blockIdx.y * 128;
    const int t = bm >> 13;             // / NN_
    const int pos0 = bm & (NN_ - 1);
    if (pos0 >= cnt[t]) return;

    __shared__ __align__(16) float As[2][16][132];
    __shared__ __align__(16) float Bs[2][16][132];

    const int bn = blockIdx.x * 128;
    const int tid = threadIdx.x;
    const int tx = tid & 15;
    const int ty = tid >> 4;
    const int ar  = tid >> 2;
    const int ac4 = (tid & 3) * 4;

    // gather row pointers (hoisted; constant over k)
    const float* Arow0 = x + (size_t)perm[pos0 + ar] * (T_ * IN_) + t * IN_;
    const float* Arow1 = x + (size_t)perm[pos0 + ar + 64] * (T_ * IN_) + t * IN_;
    const float* Brow0 = Wih + (size_t)(bn + ar) * IN_;
    const float* Brow1 = Wih + (size_t)(bn + ar + 64) * IN_;

    unsigned long long acc[8][4];
#pragma unroll
    for (int i = 0; i < 8; i++)
#pragma unroll
        for (int j = 0; j < 4; j++) acc[i][j] = 0ull;

    float4 a0v, a1v, b0v, b1v;

#define XLOAD(k0)                                                             \
    do {                                                                      \
        a0v = *(const float4*)(Arow0 + (k0) + ac4);                           \
        a1v = *(const float4*)(Arow1 + (k0) + ac4);                           \
        b0v = *(const float4*)(Brow0 + (k0) + ac4);                           \
        b1v = *(const float4*)(Brow1 + (k0) + ac4);                           \
    } while (0)

#define XSTORE(buf)                                                           \
    do {                                                                      \
        As[buf][ac4 + 0][ar] = a0v.x; As[buf][ac4 + 1][ar] = a0v.y;           \
        As[buf][ac4 + 2][ar] = a0v.z; As[buf][ac4 + 3][ar] = a0v.w;           \
        As[buf][ac4 + 0][ar + 64] = a1v.x; As[buf][ac4 + 1][ar + 64] = a1v.y; \
        As[buf][ac4 + 2][ar + 64] = a1v.z; As[buf][ac4 + 3][ar + 64] = a1v.w; \
        Bs[buf][ac4 + 0][ar] = b0v.x; Bs[buf][ac4 + 1][ar] = b0v.y;           \
        Bs[buf][ac4 + 2][ar] = b0v.z; Bs[buf][ac4 + 3][ar] = b0v.w;           \
        Bs[buf][ac4 + 0][ar + 64] = b1v.x; Bs[buf][ac4 + 1][ar + 64] = b1v.y; \
        Bs[buf][ac4 + 2][ar + 64] = b1v.z; Bs[buf][ac4 + 3][ar + 64] = b1v.w; \
    } while (0)

    XLOAD(0);
    XSTORE(0);
    __syncthreads();

    const int nk = IN_ >> 4;
    for (int kt = 0; kt < nk; kt++) {
        const int cur = kt & 1;
        if (kt + 1 < nk) XLOAD((kt + 1) * 16);
#pragma unroll
        for (int kk = 0; kk < 16; kk++) {
            float av[8];
            *(float4*)&av[0] = *(const float4*)&As[cur][kk][ty * 8];
            *(float4*)&av[4] = *(const float4*)&As[cur][kk][ty * 8 + 4];
            ulonglong2 bp0 = *(const ulonglong2*)&Bs[cur][kk][tx * 8];
            ulonglong2 bp1 = *(const ulonglong2*)&Bs[cur][kk][tx * 8 + 4];
#pragma unroll
            for (int i = 0; i < 8; i++) {
                unsigned long long ad = dup2(av[i]);
                fma2(acc[i][0], ad, bp0.x);
                fma2(acc[i][1], ad, bp0.y);
                fma2(acc[i][2], ad, bp1.x);
                fma2(acc[i][3], ad, bp1.y);
            }
        }
        if (kt + 1 < nk) XSTORE((kt + 1) & 1);
        __syncthreads();
    }
#undef XLOAD
#undef XSTORE

    float bv[8];
    *(float4*)&bv[0] = *(const float4*)(bih + bn + tx * 8);
    *(float4*)&bv[4] = *(const float4*)(bih + bn + tx * 8 + 4);

#pragma unroll
    for (int i = 0; i < 8; i++) {
        int row = bm + ty * 8 + i;
        float o[8];
#pragma unroll
        for (int j = 0; j < 4; j++) unpack2(acc[i][j], o[2 * j], o[2 * j + 1]);
#pragma unroll
        for (int j = 0; j < 8; j++) o[j] += bv[j];
        float* Cp = xgall + (size_t)row * H3_ + bn + tx * 8;
        *(float4*)Cp = *(float4*)&o[0];
        *(float4*)(Cp + 4) = *(float4*)&o[4];
    }
}

// ---------------------------------------------------------------------------
// Fused GRU step v2 over sorted rows: BM=64 rows, BN=64 h-cols, 3 gates.
// 256 threads, grid (4, 128) = 512 blocks, 2 CTAs/SM. Early exit past cnt[t].
// `last` write condition: cnt[t+1] <= pos < cnt[t]  (exactly slen-1 == t).
// ---------------------------------------------------------------------------
__global__ __launch_bounds__(256, 2)
void gru_step2(const float* __restrict__ Wh,
               const float* __restrict__ bhh,
               const float* __restrict__ xgall,
               const float* __restrict__ hin,
               float* __restrict__ hout,
               const int* __restrict__ perm,
               const int* __restrict__ cnt,
               float* __restrict__ last, int t)
{
    const int bm = blockIdx.y * 64;
    const int c0 = cnt[t];
    if (bm >= c0) return;
    const int c1 = cnt[t + 1];

    __shared__ __align__(16) float As[2][16][68];
    __shared__ __align__(16) float Bs[2][3][16][68];

    const int bn = blockIdx.x * 64;
    const int tid = threadIdx.x;
    const int tx = tid & 15;            // 16 x 4 cols
    const int ty = tid >> 4;            // 16 x 4 rows
    const int ar  = tid >> 2;           // 0..63
    const int ac4 = (tid & 3) * 4;

    unsigned long long acc[3][4][2];
#pragma unroll
    for (int g = 0; g < 3; g++)
#pragma unroll
        for (int i = 0; i < 4; i++) { acc[g][i][0] = 0ull; acc[g][i][1] = 0ull; }

    float4 aav, bbv0, bbv1, bbv2;

#define GLOAD(k0)                                                             \
    do {                                                                      \
        aav  = *(const float4*)(hin + (size_t)(bm + ar) * H_ + (k0) + ac4);   \
        bbv0 = *(const float4*)(Wh + (size_t)(bn + ar) * H_ + (k0) + ac4);    \
        bbv1 = *(const float4*)(Wh + (size_t)(256 + bn + ar) * H_ + (k0) + ac4); \
        bbv2 = *(const float4*)(Wh + (size_t)(512 + bn + ar) * H_ + (k0) + ac4); \
    } while (0)

#define GSTORE(buf)                                                           \
    do {                                                                      \
        As[buf][ac4 + 0][ar] = aav.x; As[buf][ac4 + 1][ar] = aav.y;           \
        As[buf][ac4 + 2][ar] = aav.z; As[buf][ac4 + 3][ar] = aav.w;           \
        Bs[buf][0][ac4 + 0][ar] = bbv0.x; Bs[buf][0][ac4 + 1][ar] = bbv0.y;   \
        Bs[buf][0][ac4 + 2][ar] = bbv0.z; Bs[buf][0][ac4 + 3][ar] = bbv0.w;   \
        Bs[buf][1][ac4 + 0][ar] = bbv1.x; Bs[buf][1][ac4 + 1][ar] = bbv1.y;   \
        Bs[buf][1][ac4 + 2][ar] = bbv1.z; Bs[buf][1][ac4 + 3][ar] = bbv1.w;   \
        Bs[buf][2][ac4 + 0][ar] = bbv2.x; Bs[buf][2][ac4 + 1][ar] = bbv2.y;   \
        Bs[buf][2][ac4 + 2][ar] = bbv2.z; Bs[buf][2][ac4 + 3][ar] = bbv2.w;   \
    } while (0)

    GLOAD(0);
    GSTORE(0);
    __syncthreads();

    const int nk = H_ >> 4;   // 16
    for (int kt = 0; kt < nk; kt++) {
        const int cur = kt & 1;
        if (kt + 1 < nk) GLOAD((kt + 1) * 16);
#pragma unroll
        for (int kk = 0; kk < 16; kk++) {
            float av[4];
            *(float4*)&av[0] = *(const float4*)&As[cur][kk][ty * 4];
            ulonglong2 bp0 = *(const ulonglong2*)&Bs[cur][0][kk][tx * 4];
            ulonglong2 bp1 = *(const ulonglong2*)&Bs[cur][1][kk][tx * 4];
            ulonglong2 bp2 = *(const ulonglong2*)&Bs[cur][2][kk][tx * 4];
#pragma unroll
            for (int i = 0; i < 4; i++) {
                unsigned long long ad = dup2(av[i]);
                fma2(acc[0][i][0], ad, bp0.x); fma2(acc[0][i][1], ad, bp0.y);
                fma2(acc[1][i][0], ad, bp1.x); fma2(acc[1][i][1], ad, bp1.y);
                fma2(acc[2][i][0], ad, bp2.x); fma2(acc[2][i][1], ad, bp2.y);
            }
        }
        if (kt + 1 < nk) GSTORE((kt + 1) & 1);
        __syncthreads();
    }
#undef GLOAD
#undef GSTORE

    // epilogue: gate nonlinearity
    const int c = bn + tx * 4;
    float4 br = *(const float4*)(bhh + c);
    float4 bz = *(const float4*)(bhh + 256 + c);
    float4 bq = *(const float4*)(bhh + 512 + c);

#pragma unroll
    for (int i = 0; i < 4; i++) {
        int row = bm + ty * 4 + i;
        float hr[4], hz[4], hq[4];
        unpack2(acc[0][i][0], hr[0], hr[1]); unpack2(acc[0][i][1], hr[2], hr[3]);
        unpack2(acc[1][i][0], hz[0], hz[1]); unpack2(acc[1][i][1], hz[2], hz[3]);
        unpack2(acc[2][i][0], hq[0], hq[1]); unpack2(acc[2][i][1], hq[2], hq[3]);

        size_t xb = ((size_t)t * NN_ + row) * H3_ + c;
        float4 xr = *(const float4*)(xgall + xb);
        float4 xz = *(const float4*)(xgall + xb + 256);
        float4 xq = *(const float4*)(xgall + xb + 512);
        float4 hold = *(const float4*)(hin + (size_t)row * H_ + c);

        float4 hn;
        {
            float r0 = sigf(xr.x + hr[0] + br.x);
            float z0 = sigf(xz.x + hz[0] + bz.x);
            float q0 = tanhf(xq.x + r0 * (hq[0] + bq.x));
            hn.x = (1.f - z0) * q0 + z0 * hold.x;
            float r1 = sigf(xr.y + hr[1] + br.y);
            float z1 = sigf(xz.y + hz[1] + bz.y);
            float q1 = tanhf(xq.y + r1 * (hq[1] + bq.y));
            hn.y = (1.f - z1) * q1 + z1 * hold.y;
            float r2 = sigf(xr.z + hr[2] + br.z);
            float z2 = sigf(xz.z + hz[2] + bz.z);
            float q2 = tanhf(xq.z + r2 * (hq[2] + bq.z));
            hn.z = (1.f - z2) * q2 + z2 * hold.z;
            float r3 = sigf(xr.w + hr[3] + br.w);
            float z3 = sigf(xz.w + hz[3] + bz.w);
            float q3 = tanhf(xq.w + r3 * (hq[3] + bq.w));
            hn.w = (1.f - z3) * q3 + z3 * hold.w;
        }
        *(float4*)(hout + (size_t)row * H_ + c) = hn;
        if (row >= c1 && row < c0)
            *(float4*)(last + (size_t)perm[row] * H_ + c) = hn;
    }
}

// ---------------------------------------------------------------------------
// Sorting by sequence length (counting sort, 32 bins, descending)
// ---------------------------------------------------------------------------
__global__ void zero_int_kernel(int* __restrict__ p, int n)
{
    int i = blockIdx.x * 256 + threadIdx.x;
    if (i < n) p[i] = 0;
}

__global__ void hist_kernel(const int* __restrict__ slen, int* __restrict__ hist)
{
    int i = blockIdx.x * 256 + threadIdx.x;
    if (i < NN_) atomicAdd(&hist[slen[i] - 1], 1);
}

__global__ void scan_kernel(const int* __restrict__ hist,
                            int* __restrict__ cnt, int* __restrict__ start)
{
    if (threadIdx.x == 0) {
        int run = 0;
        cnt[T_] = 0;
        for (int s = T_ - 1; s >= 0; s--) {
            start[s] = run;          // rows with larger slen come first
            run += hist[s];
            cnt[s] = run;            // #rows with slen-1 >= s
        }
    }
}

__global__ void scatter_perm_kernel(const int* __restrict__ slen,
                                    const int* __restrict__ start,
                                    int* __restrict__ cur,
                                    int* __restrict__ perm)
{
    int i = blockIdx.x * 256 + threadIdx.x;
    if (i < NN_) {
        int s = slen[i] - 1;
        int pos = start[s] + atomicAdd(&cur[s], 1);
        perm[pos] = i;
    }
}

// ---------------------------------------------------------------------------
// GRU support
// ---------------------------------------------------------------------------
__global__ void init_h_kernel(float* __restrict__ h, const float* __restrict__ h0)
{
    int idx = blockIdx.x * 256 + threadIdx.x;
    h[idx] = h0[idx & (H_ - 1)];
}

// ---------------------------------------------------------------------------
// Hypergraph conv support
// ---------------------------------------------------------------------------
__global__ void zero_kernel(float* __restrict__ p, int n4)
{
    int i = blockIdx.x * 256 + threadIdx.x;
    if (i < n4) ((float4*)p)[i] = make_float4(0.f, 0.f, 0.f, 0.f);
}

__global__ void count_deg_kernel(const int* __restrict__ node_idx,
                                 const int* __restrict__ edge_idx,
                                 float* __restrict__ D, float* __restrict__ B)
{
    int i = blockIdx.x * 256 + threadIdx.x;
    if (i < NNZ_) {
        atomicAdd(&D[node_idx[i]], 1.f);
        atomicAdd(&B[edge_idx[i]], 1.f);
    }
}

__global__ void make_inv_kernel(const float* __restrict__ cnt, float* __restrict__ inv, int n)
{
    int i = blockIdx.x * 256 + threadIdx.x;
    if (i < n) {
        float c = cnt[i];
        inv[i] = c > 0.f ? 1.f / c : 0.f;
    }
}

__global__ void scatter_edge_kernel(const float* __restrict__ xw,
                                    const int* __restrict__ node_idx,
                                    const int* __restrict__ edge_idx,
                                    float* __restrict__ eb)
{
    int idx = blockIdx.x * 256 + threadIdx.x;   // NNZ * 64
    int nz = idx >> 6;
    int c4 = (idx & 63) << 2;
    int n = node_idx[nz];
    int e = edge_idx[nz];
    float4 v = *(const float4*)(xw + (size_t)n * H_ + c4);
    float* dst = eb + (size_t)e * H_ + c4;
    atomicAdd(dst + 0, v.x); atomicAdd(dst + 1, v.y);
    atomicAdd(dst + 2, v.z); atomicAdd(dst + 3, v.w);
}

__global__ void scatter_node_kernel(const float* __restrict__ eb,
                                    const int* __restrict__ node_idx,
                                    const int* __restrict__ edge_idx,
                                    const float* __restrict__ Binv,
                                    float* __restrict__ agg)
{
    int idx = blockIdx.x * 256 + threadIdx.x;   // NNZ * 64
    int nz = idx >> 6;
    int c4 = (idx & 63) << 2;
    int n = node_idx[nz];
    int e = edge_idx[nz];
    float be = Binv[e];
    float4 v = *(const float4*)(eb + (size_t)e * H_ + c4);
    float* dst = agg + (size_t)n * H_ + c4;
    atomicAdd(dst + 0, v.x * be); atomicAdd(dst + 1, v.y * be);
    atomicAdd(dst + 2, v.z * be); atomicAdd(dst + 3, v.w * be);
}

__global__ void hgc_finish_kernel(const float* __restrict__ agg,
                                  const float* __restrict__ Dinv,
                                  const float* __restrict__ bias,
                                  const float* __restrict__ resid,
                                  float* __restrict__ out)
{
    int idx = blockIdx.x * 256 + threadIdx.x;   // N*H
    int n = idx >> 8;
    int c = idx & 255;
    out[idx] = agg[idx] * Dinv[n] + bias[c] + resid[idx];
}

// ---------------------------------------------------------------------------
// Symmetric gram + mask + degree (upper-triangle block tiles).
// ---------------------------------------------------------------------------
__global__ __launch_bounds__(256, 2)
void gram_sym_kernel(const float* __restrict__ X,
                     unsigned char* __restrict__ mask,
                     float* __restrict__ deg,
                     const float* __restrict__ phi_p)
{
    __shared__ __align__(16) float As[2][16][132];
    __shared__ __align__(16) float Bs[2][16][132];

    int k = blockIdx.x;
    int bi = 0;
    while (k >= 64 - bi) { k -= 64 - bi; bi++; }
    const int bj = bi + k;
    const int bm = bi * 128;
    const int bn = bj * 128;

    const int tid = threadIdx.x;
    const int tx = tid & 15;
    const int ty = tid >> 4;
    const int ar  = tid >> 2;
    const int ac4 = (tid & 3) * 4;

    unsigned long long acc[8][4];
#pragma unroll
    for (int i = 0; i < 8; i++)
#pragma unroll
        for (int j = 0; j < 4; j++) acc[i][j] = 0ull;

    float4 a0v, a1v, b0v, b1v;

#define GRLOAD(k0)                                                            \
    do {                                                                      \
        const float* Ap = X + (size_t)(bm + ar) * H_ + (k0) + ac4;            \
        a0v = *(const float4*)Ap;                                             \
        a1v = *(const float4*)(Ap + (size_t)64 * H_);                         \
        const float* Bp = X + (size_t)(bn + ar) * H_ + (k0) + ac4;            \
        b0v = *(const float4*)Bp;                                             \
        b1v = *(const float4*)(Bp + (size_t)64 * H_);                         \
    } while (0)

#define GRSTORE(buf)                                                          \
    do {                                                                      \
        As[buf][ac4 + 0][ar] = a0v.x; As[buf][ac4 + 1][ar] = a0v.y;           \
        As[buf][ac4 + 2][ar] = a0v.z; As[buf][ac4 + 3][ar] = a0v.w;           \
        As[buf][ac4 + 0][ar + 64] = a1v.x; As[buf][ac4 + 1][ar + 64] = a1v.y; \
        As[buf][ac4 + 2][ar + 64] = a1v.z; As[buf][ac4 + 3][ar + 64] = a1v.w; \
        Bs[buf][ac4 + 0][ar] = b0v.x; Bs[buf][ac4 + 1][ar] = b0v.y;           \
        Bs[buf][ac4 + 2][ar] = b0v.z; Bs[buf][ac4 + 3][ar] = b0v.w;           \
        Bs[buf][ac4 + 0][ar + 64] = b1v.x; Bs[buf][ac4 + 1][ar + 64] = b1v.y; \
        Bs[buf][ac4 + 2][ar + 64] = b1v.z; Bs[buf][ac4 + 3][ar + 64] = b1v.w; \
    } while (0)

    GRLOAD(0);
    GRSTORE(0);
    __syncthreads();

    const int nk = H_ >> 4;
    for (int kt = 0; kt < nk; kt++) {
        const int cur = kt & 1;
        if (kt + 1 < nk) GRLOAD((kt + 1) * 16);
#pragma unroll
        for (int kk = 0; kk < 16; kk++) {
            float av[8];
            *(float4*)&av[0] = *(const float4*)&As[cur][kk][ty * 8];
            *(float4*)&av[4] = *(const float4*)&As[cur][kk][ty * 8 + 4];
            ulonglong2 bp0 = *(const ulonglong2*)&Bs[cur][kk][tx * 8];
            ulonglong2 bp1 = *(const ulonglong2*)&Bs[cur][kk][tx * 8 + 4];
#pragma unroll
            for (int i = 0; i < 8; i++) {
                unsigned long long ad = dup2(av[i]);
                fma2(acc[i][0], ad, bp0.x);
                fma2(acc[i][1], ad, bp0.y);
                fma2(acc[i][2], ad, bp1.x);
                fma2(acc[i][3], ad, bp1.y);
            }
        }
        if (kt + 1 < nk) GRSTORE((kt + 1) & 1);
        __syncthreads();
    }
#undef GRLOAD
#undef GRSTORE

    const float thr = phi_p[0] * 65536.0f;
    unsigned m[8][8];
    float colcnt[8];
#pragma unroll
    for (int j = 0; j < 8; j++) colcnt[j] = 0.f;

#pragma unroll
    for (int i = 0; i < 8; i++) {
        int row = bm + ty * 8 + i;
        float v[8];
#pragma unroll
        for (int j = 0; j < 4; j++) unpack2(acc[i][j], v[2 * j], v[2 * j + 1]);
        unsigned long long pack = 0ull;
        float rowcnt = 0.f;
#pragma unroll
        for (int j = 0; j < 8; j++) {
            int col = bn + tx * 8 + j;
            unsigned b = (v[j] >= thr || row == col) ? 1u : 0u;
            m[i][j] = b;
            pack |= (unsigned long long)b << (8 * j);
            rowcnt += (float)b;
            colcnt[j] += (float)b;
        }
        *(unsigned long long*)(mask + (size_t)row * NN_ + bn + tx * 8) = pack;
        atomicAdd(&deg[row], rowcnt);
    }

    if (bi != bj) {
#pragma unroll
        for (int j = 0; j < 8; j++) {
            int col = bn + tx * 8 + j;
            unsigned long long pack = 0ull;
#pragma unroll
            for (int i = 0; i < 8; i++)
                pack |= (unsigned long long)m[i][j] << (8 * i);
            *(unsigned long long*)(mask + (size_t)col * NN_ + bm + ty * 8) = pack;
            atomicAdd(&deg[col], colcnt[j]);
        }
    }
}

__global__ void dis_kernel(const float* __restrict__ deg, float* __restrict__ dis)
{
    int i = blockIdx.x * 256 + threadIdx.x;
    if (i < NN_) {
        float d = deg[i];
        dis[i] = d > 0.f ? rsqrtf(d) : 0.f;
    }
}

__global__ void yscale_kernel(const float* __restrict__ x2,
                              const float* __restrict__ dis,
                              float* __restrict__ y)
{
    int idx = blockIdx.x * 256 + threadIdx.x;   // N*GCN
    int n = idx >> 8;
    y[idx] = x2[idx] * dis[n];
}

// ---------------------------------------------------------------------------
// Masked GCN GEMM from byte mask
// ---------------------------------------------------------------------------
__global__ __launch_bounds__(256, 2)
void gcn_gemm_b(const unsigned char* __restrict__ mask,
                const float* __restrict__ Y,
                const float* __restrict__ dis,
                const float* __restrict__ bias,
                float* __restrict__ out)
{
    __shared__ __align__(16) float As[2][16][132];
    __shared__ __align__(16) float Bs[2][16][132];

    const int bm = blockIdx.y * 128;
    const int bn = blockIdx.x * 128;
    const int tid = threadIdx.x;
    const int tx = tid & 15;
    const int ty = tid >> 4;
    const int ar2  = tid >> 1;
    const int half = tid & 1;
    const int bkr = tid >> 5;
    const int bc4 = (tid & 31) * 4;

    unsigned long long acc[8][4];
#pragma unroll
    for (int i = 0; i < 8; i++)
#pragma unroll
        for (int j = 0; j < 4; j++) acc[i][j] = 0ull;

    unsigned long long am;
    float4 b0v, b1v;

#define MLOAD(k0)                                                             \
    do {                                                                      \
        am = *(const unsigned long long*)(mask + (size_t)(bm + ar2) * NN_ + (k0) + half * 8); \
        const float* Bp = Y + (size_t)((k0) + bkr) * GCN_ + bn + bc4;         \
        b0v = *(const float4*)Bp;                                             \
        b1v = *(const float4*)(Bp + (size_t)8 * GCN_);                        \
    } while (0)

#define MSTORE(buf)                                                           \
    do {                                                                      \
        _Pragma("unroll")                                                     \
        for (int b = 0; b < 8; b++)                                           \
            As[buf][half * 8 + b][ar2] = (float)((am >> (8 * b)) & 0xFFull);  \
        *(float4*)&Bs[buf][bkr][bc4] = b0v;                                   \
        *(float4*)&Bs[buf][bkr + 8][bc4] = b1v;                               \
    } while (0)

    MLOAD(0);
    MSTORE(0);
    __syncthreads();

    const int nk = NN_ >> 4;
    for (int kt = 0; kt < nk; kt++) {
        const int cur = kt & 1;
        if (kt + 1 < nk) MLOAD((kt + 1) * 16);
#pragma unroll
        for (int kk = 0; kk < 16; kk++) {
            float av[8];
            *(float4*)&av[0] = *(const float4*)&As[cur][kk][ty * 8];
            *(float4*)&av[4] = *(const float4*)&As[cur][kk][ty * 8 + 4];
            ulonglong2 bp0 = *(const ulonglong2*)&Bs[cur][kk][tx * 8];
            ulonglong2 bp1 = *(const ulonglong2*)&Bs[cur][kk][tx * 8 + 4];
#pragma unroll
            for (int i = 0; i < 8; i++) {
                unsigned long long ad = dup2(av[i]);
                fma2(acc[i][0], ad, bp0.x);
                fma2(acc[i][1], ad, bp0.y);
                fma2(acc[i][2], ad, bp1.x);
                fma2(acc[i][3], ad, bp1.y);
            }
        }
        if (kt + 1 < nk) MSTORE((kt + 1) & 1);
        __syncthreads();
    }
#undef MLOAD
#undef MSTORE

    float bv[8];
    *(float4*)&bv[0] = *(const float4*)(bias + bn + tx * 8);
    *(float4*)&bv[4] = *(const float4*)(bias + bn + tx * 8 + 4);

#pragma unroll
    for (int i = 0; i < 8; i++) {
        int row = bm + ty * 8 + i;
        float di = dis[row];
        float o[8];
#pragma unroll
        for (int j = 0; j < 4; j++) unpack2(acc[i][j], o[2 * j], o[2 * j + 1]);
#pragma unroll
        for (int j = 0; j < 8; j++) o[j] = di * o[j] + bv[j];
        float* Cp = out + (size_t)row * GCN_ + bn + tx * 8;
        *(float4*)Cp = *(float4*)&o[0];
        *(float4*)(Cp + 4) = *(float4*)&o[4];
    }
}

// ---------------------------------------------------------------------------
// Host orchestration
// ---------------------------------------------------------------------------
static void hgc_layer(const float* in, const float* W, const float* b,
                      const int* node_idx, const int* edge_idx,
                      float* xw, float* eb, float* agg,
                      const float* Dinv, const float* Binv, float* outbuf)
{
    sgemm_f2<false, false><<<dim3(H_ / 128, NN_ / 128), 256>>>(
        in, H_, W, H_, xw, H_, H_, nullptr);
    zero_kernel<<<(E_ * H_ / 4 + 255) / 256, 256>>>(eb, E_ * H_ / 4);
    scatter_edge_kernel<<<NNZ_ * 64 / 256, 256>>>(xw, node_idx, edge_idx, eb);
    zero_kernel<<<(NN_ * H_ / 4 + 255) / 256, 256>>>(agg, NN_ * H_ / 4);
    scatter_node_kernel<<<NNZ_ * 64 / 256, 256>>>(eb, node_idx, edge_idx, Binv, agg);
    hgc_finish_kernel<<<NN_ * H_ / 256, 256>>>(agg, Dinv, b, in, outbuf);
}

extern "C" void kernel_launch(void* const* d_in, const int* in_sizes, int n_in,
                              void* d_out, int out_size)
{
    (void)in_sizes; (void)n_in; (void)out_size;

    const float* x        = (const float*)d_in[0];
    const int*   hei      = (const int*)d_in[1];
    const int*   node_idx = hei;
    const int*   edge_idx = hei + NNZ_;
    const int*   slen     = (const int*)d_in[2];
    const float* h0       = (const float*)d_in[3];
    const float* W_ih     = (const float*)d_in[4];
    const float* W_hh     = (const float*)d_in[5];
    const float* b_ih     = (const float*)d_in[6];
    const float* b_hh     = (const float*)d_in[7];
    const float* w1 = (const float*)d_in[8];  const float* bb1 = (const float*)d_in[9];
    const float* w2 = (const float*)d_in[10]; const float* bb2 = (const float*)d_in[11];
    const float* w3 = (const float*)d_in[12]; const float* bb3 = (const float*)d_in[13];
    const float* phi = (const float*)d_in[14];
    const float* gw  = (const float*)d_in[15];
    const float* gb  = (const float*)d_in[16];
    float* out = (float*)d_out;

    float *xgall, *h, *h2, *fa, *fb, *xw, *eb, *agg, *x2, *y;
    float *deg, *Dcnt, *Dinv, *Bcnt, *Binv, *dis;
    unsigned char* mask;
    int *perm, *histb, *curb, *startb, *cntb;
    cudaGetSymbolAddress((void**)&xgall, g_xgall);
    cudaGetSymbolAddress((void**)&h,     g_h);
    cudaGetSymbolAddress((void**)&h2,    g_h2);
    cudaGetSymbolAddress((void**)&fa,    g_fa);
    cudaGetSymbolAddress((void**)&fb,    g_fb);
    cudaGetSymbolAddress((void**)&xw,    g_xw);
    cudaGetSymbolAddress((void**)&eb,    g_eb);
    cudaGetSymbolAddress((void**)&agg,   g_agg);
    cudaGetSymbolAddress((void**)&x2,    g_x2);
    cudaGetSymbolAddress((void**)&y,     g_y);
    cudaGetSymbolAddress((void**)&mask,  g_mask);
    cudaGetSymbolAddress((void**)&deg,   g_deg);
    cudaGetSymbolAddress((void**)&Dcnt,  g_Dcnt);
    cudaGetSymbolAddress((void**)&Dinv,  g_Dinv);
    cudaGetSymbolAddress((void**)&Bcnt,  g_Bcnt);
    cudaGetSymbolAddress((void**)&Binv,  g_Binv);
    cudaGetSymbolAddress((void**)&dis,   g_dis);
    cudaGetSymbolAddress((void**)&perm,  g_perm);
    cudaGetSymbolAddress((void**)&histb, g_hist);
    cudaGetSymbolAddress((void**)&curb,  g_cur);
    cudaGetSymbolAddress((void**)&startb,g_start);
    cudaGetSymbolAddress((void**)&cntb,  g_cnt);

    // ---------------- sort rows by slen (descending) ----------------
    zero_int_kernel<<<1, 256>>>(histb, 32);
    zero_int_kernel<<<1, 256>>>(curb, 32);
    hist_kernel<<<NN_ / 256, 256>>>(slen, histb);
    scan_kernel<<<1, 32>>>(histb, cntb, startb);
    scatter_perm_kernel<<<NN_ / 256, 256>>>(slen, startb, curb, perm);

    // ---------------- GRU ----------------
    init_h_kernel<<<NN_ * H_ / 256, 256>>>(h, h0);

    // Input gates for active (pos, t) pairs only; t-major layout.
    xg_gemm<<<dim3(H3_ / 128, T_ * NN_ / 128), 256>>>(
        x, W_ih, b_ih, perm, cntb, xgall);

    float* hrd = h;
    float* hwr = h2;
    for (int t = 0; t < T_; t++) {
        gru_step2<<<dim3(H_ / 64, NN_ / 64), 256>>>(
            W_hh, b_hh, xgall, hrd, hwr, perm, cntb, fa, t);
        float* tmp = hrd; hrd = hwr; hwr = tmp;
    }
    // fa now holds `last` [N,H] in ORIGINAL row order

    // ---------------- degrees (shared by 3 HGC layers) ----------------
    zero_kernel<<<(NN_ / 4 + 255) / 256, 256>>>(Dcnt, NN_ / 4);
    zero_kernel<<<(E_ / 4 + 255) / 256, 256>>>(Bcnt, E_ / 4);
    count_deg_kernel<<<NNZ_ / 256, 256>>>(node_idx, edge_idx, Dcnt, Bcnt);
    make_inv_kernel<<<(NN_ + 255) / 256, 256>>>(Dcnt, Dinv, NN_);
    make_inv_kernel<<<(E_ + 255) / 256, 256>>>(Bcnt, Binv, E_);

    // ---------------- 3 hypergraph conv layers with residuals ----------------
    hgc_layer(fa, w1, bb1, node_idx, edge_idx, xw, eb, agg, Dinv, Binv, fb); // o1 = fb
    hgc_layer(fb, w2, bb2, node_idx, edge_idx, xw, eb, agg, Dinv, Binv, fa); // o2 = fa
    hgc_layer(fa, w3, bb3, node_idx, edge_idx, xw, eb, agg, Dinv, Binv, fb); // o3 = fb

    // ---------------- final dense GCN ----------------
    sgemm_f2<false, false><<<dim3(GCN_ / 128, NN_ / 128), 256>>>(
        fb, H_, gw, GCN_, x2, GCN_, H_, nullptr);

    zero_kernel<<<(NN_ / 4 + 255) / 256, 256>>>(deg, NN_ / 4);
    gram_sym_kernel<<<64 * 65 / 2, 256>>>(fb, mask, deg, phi);
    dis_kernel<<<(NN_ + 255) / 256, 256>>>(deg, dis);
    yscale_kernel<<<NN_ * GCN_ / 256, 256>>>(x2, dis, y);
    gcn_gemm_b<<<dim3(GCN_ / 128, NN_ / 128), 256>>>(mask, y, dis, gb, out);
}

// round 6
// speedup vs baseline: 1.8447x; 1.0927x over previous
#include <cuda_runtime.h>
#include <cuda_bf16.h>
#include <cstdint>
#include <cstdio>

// Problem constants
#define NN_   8192
#define T_    32
#define IN_   256
#define H_    256
#define H3_   768
#define E_    1024
#define NNZ_  65536
#define GCN_  256

// ---------------------------------------------------------------------------
// Scratch (static device globals; no runtime allocation)
// ---------------------------------------------------------------------------
__device__ float g_xgall[(size_t)NN_ * T_ * H3_];   // [t][pos][768] t-major, sorted rows
__device__ float g_h [NN_ * H_];                    // GRU hidden ping (sorted order)
__device__ float g_h2[NN_ * H_];                    // GRU hidden pong (sorted order)
__device__ float g_fa[NN_ * H_];                    // feature ping (last / o2)
__device__ float g_fb[NN_ * H_];                    // feature pong (o1 / o3)
__device__ float g_xw[NN_ * H_];                    // HGC x@W
__device__ float g_agg[NN_ * H_];                   // HGC node aggregation
__device__ float g_eb[E_ * H_];                     // HGC edge accumulator
__device__ float g_x2[NN_ * GCN_];                  // o3 @ gcn_w
__device__ float g_y [NN_ * GCN_];                  // dis_j * x2_j
__device__ unsigned char g_mask[(size_t)NN_ * NN_]; // 64 MB adjacency mask bytes
__device__ float g_deg[NN_];
__device__ float g_Dcnt[NN_];
__device__ float g_Dinv[NN_];
__device__ float g_Bcnt[E_];
__device__ float g_Binv[E_];
__device__ float g_dis[NN_];
// sort machinery
__device__ int g_perm[NN_];
__device__ int g_hist[32];
__device__ int g_cur[32];
__device__ int g_start[32];
__device__ int g_cnt[T_ + 1];

// ---------------------------------------------------------------------------
// Packed fp32x2 helpers
// ---------------------------------------------------------------------------
__device__ __forceinline__ void fma2(unsigned long long& d,
                                     unsigned long long a,
                                     unsigned long long b)
{
    asm("fma.rn.f32x2 %0, %1, %2, %0;" : "+l"(d) : "l"(a), "l"(b));
}

__device__ __forceinline__ unsigned long long dup2(float x)
{
    unsigned long long r;
    unsigned u = __float_as_uint(x);
    asm("mov.b64 %0, {%1, %1};" : "=l"(r) : "r"(u));
    return r;
}

__device__ __forceinline__ void unpack2(unsigned long long v, float& lo, float& hi)
{
    unsigned a, b;
    asm("mov.b64 {%0, %1}, %2;" : "=r"(a), "=r"(b) : "l"(v));
    lo = __uint_as_float(a);
    hi = __uint_as_float(b);
}

__device__ __forceinline__ float sigf(float x)
{
    return 1.f / (1.f + __expf(-x));
}

// ---------------------------------------------------------------------------
// bf16 split + warp MMA helpers (mma.sync m16n8k16, base-ISA, compiles sm_103)
// ---------------------------------------------------------------------------
__device__ __forceinline__ void split8(const float* __restrict__ s, uint4& hi, uint4& lo)
{
    float4 v0 = *(const float4*)s;
    float4 v1 = *(const float4*)(s + 4);
    float vv[8] = {v0.x, v0.y, v0.z, v0.w, v1.x, v1.y, v1.z, v1.w};
    unsigned hw[4], lw[4];
#pragma unroll
    for (int p = 0; p < 4; p++) {
        __nv_bfloat16 h0 = __float2bfloat16(vv[2 * p]);
        __nv_bfloat16 h1 = __float2bfloat16(vv[2 * p + 1]);
        __nv_bfloat16 l0 = __float2bfloat16(vv[2 * p] - __bfloat162float(h0));
        __nv_bfloat16 l1 = __float2bfloat16(vv[2 * p + 1] - __bfloat162float(h1));
        __nv_bfloat162 hp = __halves2bfloat162(h0, h1);
        __nv_bfloat162 lp = __halves2bfloat162(l0, l1);
        hw[p] = *(unsigned*)&hp;
        lw[p] = *(unsigned*)&lp;
    }
    hi = make_uint4(hw[0], hw[1], hw[2], hw[3]);
    lo = make_uint4(lw[0], lw[1], lw[2], lw[3]);
}

__device__ __forceinline__ void mma_bf16(float* c, const uint32_t* a, const uint32_t* b)
{
    asm volatile(
        "mma.sync.aligned.m16n8k16.row.col.f32.bf16.bf16.f32 "
        "{%0,%1,%2,%3}, {%4,%5,%6,%7}, {%8,%9}, {%0,%1,%2,%3};"
        : "+f"(c[0]), "+f"(c[1]), "+f"(c[2]), "+f"(c[3])
        : "r"(a[0]), "r"(a[1]), "r"(a[2]), "r"(a[3]), "r"(b[0]), "r"(b[1]));
}

// ---------------------------------------------------------------------------
// Tensor-core (HMMA) input-gate GEMM with bf16x3 split.
// xgall[t*NN+pos][bn..bn+128) = x[perm[pos], t, :] @ W_ih^T + b_ih
// CTA: 128x128x256 tile, 256 threads, 8 warps (4m x 2n), warp = 32x64.
// SMEM: Ah/Al/Bh/Bl, each [128][88] bf16 (stride 88 => conflict-free frags).
// Dead-block skip on cnt[t].
// ---------------------------------------------------------------------------
#define XS_ 88
__global__ __launch_bounds__(256, 2)
void xg_gemm_mma(const float* __restrict__ x,
                 const float* __restrict__ Wih,
                 const float* __restrict__ bih,
                 const int* __restrict__ perm,
                 const int* __restrict__ cnt,
                 float* __restrict__ xgall)
{
    const int bm = blockIdx.y * 128;
    const int t = bm >> 13;
    const int pos0 = bm & (NN_ - 1);
    if (pos0 >= cnt[t]) return;
    const int bn = blockIdx.x * 128;

    extern __shared__ __align__(16) __nv_bfloat16 smx[];
    __nv_bfloat16* Ah = smx;
    __nv_bfloat16* Al = smx + 128 * XS_;
    __nv_bfloat16* Bh = smx + 2 * 128 * XS_;
    __nv_bfloat16* Bl = smx + 3 * 128 * XS_;

    const int tid = threadIdx.x;
    const int wid = tid >> 5;
    const int lane = tid & 31;
    const int wm = (wid & 3) * 32;
    const int wn = (wid >> 2) * 64;
    const int grp = lane >> 2;      // 0..7
    const int tig = lane & 3;       // 0..3

    float acc[2][8][4];
#pragma unroll
    for (int mt = 0; mt < 2; mt++)
#pragma unroll
        for (int nt = 0; nt < 8; nt++)
#pragma unroll
            for (int e = 0; e < 4; e++) acc[mt][nt][e] = 0.f;

    for (int kc = 0; kc < 4; kc++) {
        // cooperative load + split: 256 rows (128 A + 128 B) x 64 k-floats
#pragma unroll
        for (int i = 0; i < 8; i++) {
            int u = i * 256 + tid;
            int r = u >> 3;
            int cg = u & 7;
            const float* src;
            __nv_bfloat16 *dh, *dl;
            int lr;
            if (r < 128) {
                src = x + (size_t)perm[pos0 + r] * (T_ * IN_) + t * IN_ + kc * 64 + cg * 8;
                dh = Ah; dl = Al; lr = r;
            } else {
                lr = r - 128;
                src = Wih + (size_t)(bn + lr) * IN_ + kc * 64 + cg * 8;
                dh = Bh; dl = Bl;
            }
            uint4 hi, lo;
            split8(src, hi, lo);
            *(uint4*)(dh + lr * XS_ + cg * 8) = hi;
            *(uint4*)(dl + lr * XS_ + cg * 8) = lo;
        }
        __syncthreads();

#pragma unroll
        for (int ks = 0; ks < 4; ks++) {
            const int kk = ks * 16;
            uint32_t ah[2][4], al[2][4];
#pragma unroll
            for (int mt = 0; mt < 2; mt++) {
                int r0 = wm + mt * 16 + grp;
                ah[mt][0] = *(const uint32_t*)(Ah + (size_t)r0 * XS_ + kk + tig * 2);
                ah[mt][1] = *(const uint32_t*)(Ah + (size_t)(r0 + 8) * XS_ + kk + tig * 2);
                ah[mt][2] = *(const uint32_t*)(Ah + (size_t)r0 * XS_ + kk + 8 + tig * 2);
                ah[mt][3] = *(const uint32_t*)(Ah + (size_t)(r0 + 8) * XS_ + kk + 8 + tig * 2);
                al[mt][0] = *(const uint32_t*)(Al + (size_t)r0 * XS_ + kk + tig * 2);
                al[mt][1] = *(const uint32_t*)(Al + (size_t)(r0 + 8) * XS_ + kk + tig * 2);
                al[mt][2] = *(const uint32_t*)(Al + (size_t)r0 * XS_ + kk + 8 + tig * 2);
                al[mt][3] = *(const uint32_t*)(Al + (size_t)(r0 + 8) * XS_ + kk + 8 + tig * 2);
            }
#pragma unroll
            for (int nt = 0; nt < 8; nt++) {
                int nr = wn + nt * 8 + grp;
                uint32_t bh[2], bl[2];
                bh[0] = *(const uint32_t*)(Bh + (size_t)nr * XS_ + kk + tig * 2);
                bh[1] = *(const uint32_t*)(Bh + (size_t)nr * XS_ + kk + 8 + tig * 2);
                bl[0] = *(const uint32_t*)(Bl + (size_t)nr * XS_ + kk + tig * 2);
                bl[1] = *(const uint32_t*)(Bl + (size_t)nr * XS_ + kk + 8 + tig * 2);
#pragma unroll
                for (int mt = 0; mt < 2; mt++) {
                    mma_bf16(acc[mt][nt], ah[mt], bh);
                    mma_bf16(acc[mt][nt], ah[mt], bl);
                    mma_bf16(acc[mt][nt], al[mt], bh);
                }
            }
        }
        __syncthreads();
    }

    // epilogue
#pragma unroll
    for (int mt = 0; mt < 2; mt++) {
#pragma unroll
        for (int nt = 0; nt < 8; nt++) {
            int row0 = bm + wm + mt * 16 + grp;
            int col = bn + wn + nt * 8 + tig * 2;
            float2 bv = *(const float2*)(bih + col);
            float2 o0 = make_float2(acc[mt][nt][0] + bv.x, acc[mt][nt][1] + bv.y);
            float2 o1 = make_float2(acc[mt][nt][2] + bv.x, acc[mt][nt][3] + bv.y);
            *(float2*)(xgall + (size_t)row0 * H3_ + col) = o0;
            *(float2*)(xgall + (size_t)(row0 + 8) * H3_ + col) = o1;
        }
    }
}

// ---------------------------------------------------------------------------
// Fused GRU step (fp32 f32x2, round-4 proven): BM=64, BN=64, 3 gates.
// ---------------------------------------------------------------------------
__global__ __launch_bounds__(256, 2)
void gru_step2(const float* __restrict__ Wh,
               const float* __restrict__ bhh,
               const float* __restrict__ xgall,
               const float* __restrict__ hin,
               float* __restrict__ hout,
               const int* __restrict__ perm,
               const int* __restrict__ cnt,
               float* __restrict__ last, int t)
{
    const int bm = blockIdx.y * 64;
    const int c0 = cnt[t];
    if (bm >= c0) return;
    const int c1 = cnt[t + 1];

    __shared__ __align__(16) float As[2][16][68];
    __shared__ __align__(16) float Bs[2][3][16][68];

    const int bn = blockIdx.x * 64;
    const int tid = threadIdx.x;
    const int tx = tid & 15;
    const int ty = tid >> 4;
    const int ar  = tid >> 2;
    const int ac4 = (tid & 3) * 4;

    unsigned long long acc[3][4][2];
#pragma unroll
    for (int g = 0; g < 3; g++)
#pragma unroll
        for (int i = 0; i < 4; i++) { acc[g][i][0] = 0ull; acc[g][i][1] = 0ull; }

    float4 aav, bbv0, bbv1, bbv2;

#define GLOAD(k0)                                                             \
    do {                                                                      \
        aav  = *(const float4*)(hin + (size_t)(bm + ar) * H_ + (k0) + ac4);   \
        bbv0 = *(const float4*)(Wh + (size_t)(bn + ar) * H_ + (k0) + ac4);    \
        bbv1 = *(const float4*)(Wh + (size_t)(256 + bn + ar) * H_ + (k0) + ac4); \
        bbv2 = *(const float4*)(Wh + (size_t)(512 + bn + ar) * H_ + (k0) + ac4); \
    } while (0)

#define GSTORE(buf)                                                           \
    do {                                                                      \
        As[buf][ac4 + 0][ar] = aav.x; As[buf][ac4 + 1][ar] = aav.y;           \
        As[buf][ac4 + 2][ar] = aav.z; As[buf][ac4 + 3][ar] = aav.w;           \
        Bs[buf][0][ac4 + 0][ar] = bbv0.x; Bs[buf][0][ac4 + 1][ar] = bbv0.y;   \
        Bs[buf][0][ac4 + 2][ar] = bbv0.z; Bs[buf][0][ac4 + 3][ar] = bbv0.w;   \
        Bs[buf][1][ac4 + 0][ar] = bbv1.x; Bs[buf][1][ac4 + 1][ar] = bbv1.y;   \
        Bs[buf][1][ac4 + 2][ar] = bbv1.z; Bs[buf][1][ac4 + 3][ar] = bbv1.w;   \
        Bs[buf][2][ac4 + 0][ar] = bbv2.x; Bs[buf][2][ac4 + 1][ar] = bbv2.y;   \
        Bs[buf][2][ac4 + 2][ar] = bbv2.z; Bs[buf][2][ac4 + 3][ar] = bbv2.w;   \
    } while (0)

    GLOAD(0);
    GSTORE(0);
    __syncthreads();

    const int nk = H_ >> 4;
    for (int kt = 0; kt < nk; kt++) {
        const int cur = kt & 1;
        if (kt + 1 < nk) GLOAD((kt + 1) * 16);
#pragma unroll
        for (int kk = 0; kk < 16; kk++) {
            float av[4];
            *(float4*)&av[0] = *(const float4*)&As[cur][kk][ty * 4];
            ulonglong2 bp0 = *(const ulonglong2*)&Bs[cur][0][kk][tx * 4];
            ulonglong2 bp1 = *(const ulonglong2*)&Bs[cur][1][kk][tx * 4];
            ulonglong2 bp2 = *(const ulonglong2*)&Bs[cur][2][kk][tx * 4];
#pragma unroll
            for (int i = 0; i < 4; i++) {
                unsigned long long ad = dup2(av[i]);
                fma2(acc[0][i][0], ad, bp0.x); fma2(acc[0][i][1], ad, bp0.y);
                fma2(acc[1][i][0], ad, bp1.x); fma2(acc[1][i][1], ad, bp1.y);
                fma2(acc[2][i][0], ad, bp2.x); fma2(acc[2][i][1], ad, bp2.y);
            }
        }
        if (kt + 1 < nk) GSTORE((kt + 1) & 1);
        __syncthreads();
    }
#undef GLOAD
#undef GSTORE

    const int c = bn + tx * 4;
    float4 br = *(const float4*)(bhh + c);
    float4 bz = *(const float4*)(bhh + 256 + c);
    float4 bq = *(const float4*)(bhh + 512 + c);

#pragma unroll
    for (int i = 0; i < 4; i++) {
        int row = bm + ty * 4 + i;
        float hr[4], hz[4], hq[4];
        unpack2(acc[0][i][0], hr[0], hr[1]); unpack2(acc[0][i][1], hr[2], hr[3]);
        unpack2(acc[1][i][0], hz[0], hz[1]); unpack2(acc[1][i][1], hz[2], hz[3]);
        unpack2(acc[2][i][0], hq[0], hq[1]); unpack2(acc[2][i][1], hq[2], hq[3]);

        size_t xb = ((size_t)t * NN_ + row) * H3_ + c;
        float4 xr = *(const float4*)(xgall + xb);
        float4 xz = *(const float4*)(xgall + xb + 256);
        float4 xq = *(const float4*)(xgall + xb + 512);
        float4 hold = *(const float4*)(hin + (size_t)row * H_ + c);

        float4 hn;
        {
            float r0 = sigf(xr.x + hr[0] + br.x);
            float z0 = sigf(xz.x + hz[0] + bz.x);
            float q0 = tanhf(xq.x + r0 * (hq[0] + bq.x));
            hn.x = (1.f - z0) * q0 + z0 * hold.x;
            float r1 = sigf(xr.y + hr[1] + br.y);
            float z1 = sigf(xz.y + hz[1] + bz.y);
            float q1 = tanhf(xq.y + r1 * (hq[1] + bq.y));
            hn.y = (1.f - z1) * q1 + z1 * hold.y;
            float r2 = sigf(xr.z + hr[2] + br.z);
            float z2 = sigf(xz.z + hz[2] + bz.z);
            float q2 = tanhf(xq.z + r2 * (hq[2] + bq.z));
            hn.z = (1.f - z2) * q2 + z2 * hold.z;
            float r3 = sigf(xr.w + hr[3] + br.w);
            float z3 = sigf(xz.w + hz[3] + bz.w);
            float q3 = tanhf(xq.w + r3 * (hq[3] + bq.w));
            hn.w = (1.f - z3) * q3 + z3 * hold.w;
        }
        *(float4*)(hout + (size_t)row * H_ + c) = hn;
        if (row >= c1 && row < c0)
            *(float4*)(last + (size_t)perm[row] * H_ + c) = hn;
    }
}

// ---------------------------------------------------------------------------
// Tiled SGEMM with packed f32x2 FMA (fp32 path; HGC + x2)
// ---------------------------------------------------------------------------
template<bool TRANSB, bool BIAS>
__global__ __launch_bounds__(256, 2)
void sgemm_f2(const float* __restrict__ A, int lda,
              const float* __restrict__ B, int ldb,
              float* __restrict__ C, int ldc,
              int K, const float* __restrict__ bias)
{
    __shared__ __align__(16) float As[2][16][132];
    __shared__ __align__(16) float Bs[2][16][132];

    const int bm = blockIdx.y * 128;
    const int bn = blockIdx.x * 128;
    const int tid = threadIdx.x;
    const int tx = tid & 15;
    const int ty = tid >> 4;
    const int ar  = tid >> 2;
    const int ac4 = (tid & 3) * 4;
    const int bkr = tid >> 5;
    const int bc4 = (tid & 31) * 4;

    unsigned long long acc[8][4];
#pragma unroll
    for (int i = 0; i < 8; i++)
#pragma unroll
        for (int j = 0; j < 4; j++) acc[i][j] = 0ull;

    float4 a0v, a1v, b0v, b1v;

#define LOAD_TILE(k0)                                                         \
    do {                                                                      \
        const float* Ap = A + (size_t)(bm + ar) * lda + (k0) + ac4;          \
        a0v = *(const float4*)Ap;                                             \
        a1v = *(const float4*)(Ap + (size_t)64 * lda);                        \
        if (TRANSB) {                                                         \
            const float* Bp = B + (size_t)(bn + ar) * ldb + (k0) + ac4;      \
            b0v = *(const float4*)Bp;                                         \
            b1v = *(const float4*)(Bp + (size_t)64 * ldb);                    \
        } else {                                                              \
            const float* Bp = B + (size_t)((k0) + bkr) * ldb + bn + bc4;      \
            b0v = *(const float4*)Bp;                                         \
            b1v = *(const float4*)(Bp + (size_t)8 * ldb);                     \
        }                                                                     \
    } while (0)

#define STORE_TILE(buf)                                                       \
    do {                                                                      \
        As[buf][ac4 + 0][ar] = a0v.x; As[buf][ac4 + 1][ar] = a0v.y;           \
        As[buf][ac4 + 2][ar] = a0v.z; As[buf][ac4 + 3][ar] = a0v.w;           \
        As[buf][ac4 + 0][ar + 64] = a1v.x; As[buf][ac4 + 1][ar + 64] = a1v.y; \
        As[buf][ac4 + 2][ar + 64] = a1v.z; As[buf][ac4 + 3][ar + 64] = a1v.w; \
        if (TRANSB) {                                                         \
            Bs[buf][ac4 + 0][ar] = b0v.x; Bs[buf][ac4 + 1][ar] = b0v.y;       \
            Bs[buf][ac4 + 2][ar] = b0v.z; Bs[buf][ac4 + 3][ar] = b0v.w;       \
            Bs[buf][ac4 + 0][ar + 64] = b1v.x; Bs[buf][ac4 + 1][ar + 64] = b1v.y; \
            Bs[buf][ac4 + 2][ar + 64] = b1v.z; Bs[buf][ac4 + 3][ar + 64] = b1v.w; \
        } else {                                                              \
            *(float4*)&Bs[buf][bkr][bc4] = b0v;                               \
            *(float4*)&Bs[buf][bkr + 8][bc4] = b1v;                           \
        }                                                                     \
    } while (0)

    LOAD_TILE(0);
    STORE_TILE(0);
    __syncthreads();

    const int nk = K >> 4;
    for (int kt = 0; kt < nk; kt++) {
        const int cur = kt & 1;
        if (kt + 1 < nk) LOAD_TILE((kt + 1) * 16);

#pragma unroll
        for (int kk = 0; kk < 16; kk++) {
            float av[8];
            *(float4*)&av[0] = *(const float4*)&As[cur][kk][ty * 8];
            *(float4*)&av[4] = *(const float4*)&As[cur][kk][ty * 8 + 4];
            ulonglong2 bp0 = *(const ulonglong2*)&Bs[cur][kk][tx * 8];
            ulonglong2 bp1 = *(const ulonglong2*)&Bs[cur][kk][tx * 8 + 4];
#pragma unroll
            for (int i = 0; i < 8; i++) {
                unsigned long long ad = dup2(av[i]);
                fma2(acc[i][0], ad, bp0.x);
                fma2(acc[i][1], ad, bp0.y);
                fma2(acc[i][2], ad, bp1.x);
                fma2(acc[i][3], ad, bp1.y);
            }
        }
        if (kt + 1 < nk) STORE_TILE((kt + 1) & 1);
        __syncthreads();
    }
#undef LOAD_TILE
#undef STORE_TILE

    float bv[8];
    if (BIAS) {
        *(float4*)&bv[0] = *(const float4*)(bias + bn + tx * 8);
        *(float4*)&bv[4] = *(const float4*)(bias + bn + tx * 8 + 4);
    }

#pragma unroll
    for (int i = 0; i < 8; i++) {
        int row = bm + ty * 8 + i;
        float o[8];
#pragma unroll
        for (int j = 0; j < 4; j++) unpack2(acc[i][j], o[2 * j], o[2 * j + 1]);
        if (BIAS) {
#pragma unroll
            for (int j = 0; j < 8; j++) o[j] += bv[j];
        }
        float* Cp = C + (size_t)row * ldc + bn + tx * 8;
        *(float4*)Cp = *(float4*)&o[0];
        *(float4*)(Cp + 4) = *(float4*)&o[4];
    }
}

// ---------------------------------------------------------------------------
// Sorting by sequence length (counting sort, descending)
// ---------------------------------------------------------------------------
__global__ void zero_int_kernel(int* __restrict__ p, int n)
{
    int i = blockIdx.x * 256 + threadIdx.x;
    if (i < n) p[i] = 0;
}

__global__ void hist_kernel(const int* __restrict__ slen, int* __restrict__ hist)
{
    int i = blockIdx.x * 256 + threadIdx.x;
    if (i < NN_) atomicAdd(&hist[slen[i] - 1], 1);
}

__global__ void scan_kernel(const int* __restrict__ hist,
                            int* __restrict__ cnt, int* __restrict__ start)
{
    if (threadIdx.x == 0) {
        int run = 0;
        cnt[T_] = 0;
        for (int s = T_ - 1; s >= 0; s--) {
            start[s] = run;
            run += hist[s];
            cnt[s] = run;
        }
    }
}

__global__ void scatter_perm_kernel(const int* __restrict__ slen,
                                    const int* __restrict__ start,
                                    int* __restrict__ cur,
                                    int* __restrict__ perm)
{
    int i = blockIdx.x * 256 + threadIdx.x;
    if (i < NN_) {
        int s = slen[i] - 1;
        int pos = start[s] + atomicAdd(&cur[s], 1);
        perm[pos] = i;
    }
}

__global__ void init_h_kernel(float* __restrict__ h, const float* __restrict__ h0)
{
    int idx = blockIdx.x * 256 + threadIdx.x;
    h[idx] = h0[idx & (H_ - 1)];
}

// ---------------------------------------------------------------------------
// Hypergraph conv support
// ---------------------------------------------------------------------------
__global__ void zero_kernel(float* __restrict__ p, int n4)
{
    int i = blockIdx.x * 256 + threadIdx.x;
    if (i < n4) ((float4*)p)[i] = make_float4(0.f, 0.f, 0.f, 0.f);
}

__global__ void count_deg_kernel(const int* __restrict__ node_idx,
                                 const int* __restrict__ edge_idx,
                                 float* __restrict__ D, float* __restrict__ B)
{
    int i = blockIdx.x * 256 + threadIdx.x;
    if (i < NNZ_) {
        atomicAdd(&D[node_idx[i]], 1.f);
        atomicAdd(&B[edge_idx[i]], 1.f);
    }
}

__global__ void make_inv_kernel(const float* __restrict__ cnt, float* __restrict__ inv, int n)
{
    int i = blockIdx.x * 256 + threadIdx.x;
    if (i < n) {
        float c = cnt[i];
        inv[i] = c > 0.f ? 1.f / c : 0.f;
    }
}

__global__ void scatter_edge_kernel(const float* __restrict__ xw,
                                    const int* __restrict__ node_idx,
                                    const int* __restrict__ edge_idx,
                                    float* __restrict__ eb)
{
    int idx = blockIdx.x * 256 + threadIdx.x;
    int nz = idx >> 6;
    int c4 = (idx & 63) << 2;
    int n = node_idx[nz];
    int e = edge_idx[nz];
    float4 v = *(const float4*)(xw + (size_t)n * H_ + c4);
    float* dst = eb + (size_t)e * H_ + c4;
    atomicAdd(dst + 0, v.x); atomicAdd(dst + 1, v.y);
    atomicAdd(dst + 2, v.z); atomicAdd(dst + 3, v.w);
}

__global__ void scatter_node_kernel(const float* __restrict__ eb,
                                    const int* __restrict__ node_idx,
                                    const int* __restrict__ edge_idx,
                                    const float* __restrict__ Binv,
                                    float* __restrict__ agg)
{
    int idx = blockIdx.x * 256 + threadIdx.x;
    int nz = idx >> 6;
    int c4 = (idx & 63) << 2;
    int n = node_idx[nz];
    int e = edge_idx[nz];
    float be = Binv[e];
    float4 v = *(const float4*)(eb + (size_t)e * H_ + c4);
    float* dst = agg + (size_t)n * H_ + c4;
    atomicAdd(dst + 0, v.x * be); atomicAdd(dst + 1, v.y * be);
    atomicAdd(dst + 2, v.z * be); atomicAdd(dst + 3, v.w * be);
}

__global__ void hgc_finish_kernel(const float* __restrict__ agg,
                                  const float* __restrict__ Dinv,
                                  const float* __restrict__ bias,
                                  const float* __restrict__ resid,
                                  float* __restrict__ out)
{
    int idx = blockIdx.x * 256 + threadIdx.x;
    int n = idx >> 8;
    int c = idx & 255;
    out[idx] = agg[idx] * Dinv[n] + bias[c] + resid[idx];
}

// ---------------------------------------------------------------------------
// Symmetric gram + mask + degree (upper-triangle block tiles), fp32 exact.
// ---------------------------------------------------------------------------
__global__ __launch_bounds__(256, 2)
void gram_sym_kernel(const float* __restrict__ X,
                     unsigned char* __restrict__ mask,
                     float* __restrict__ deg,
                     const float* __restrict__ phi_p)
{
    __shared__ __align__(16) float As[2][16][132];
    __shared__ __align__(16) float Bs[2][16][132];

    int k = blockIdx.x;
    int bi = 0;
    while (k >= 64 - bi) { k -= 64 - bi; bi++; }
    const int bj = bi + k;
    const int bm = bi * 128;
    const int bn = bj * 128;

    const int tid = threadIdx.x;
    const int tx = tid & 15;
    const int ty = tid >> 4;
    const int ar  = tid >> 2;
    const int ac4 = (tid & 3) * 4;

    unsigned long long acc[8][4];
#pragma unroll
    for (int i = 0; i < 8; i++)
#pragma unroll
        for (int j = 0; j < 4; j++) acc[i][j] = 0ull;

    float4 a0v, a1v, b0v, b1v;

#define GRLOAD(k0)                                                            \
    do {                                                                      \
        const float* Ap = X + (size_t)(bm + ar) * H_ + (k0) + ac4;            \
        a0v = *(const float4*)Ap;                                             \
        a1v = *(const float4*)(Ap + (size_t)64 * H_);                         \
        const float* Bp = X + (size_t)(bn + ar) * H_ + (k0) + ac4;            \
        b0v = *(const float4*)Bp;                                             \
        b1v = *(const float4*)(Bp + (size_t)64 * H_);                         \
    } while (0)

#define GRSTORE(buf)                                                          \
    do {                                                                      \
        As[buf][ac4 + 0][ar] = a0v.x; As[buf][ac4 + 1][ar] = a0v.y;           \
        As[buf][ac4 + 2][ar] = a0v.z; As[buf][ac4 + 3][ar] = a0v.w;           \
        As[buf][ac4 + 0][ar + 64] = a1v.x; As[buf][ac4 + 1][ar + 64] = a1v.y; \
        As[buf][ac4 + 2][ar + 64] = a1v.z; As[buf][ac4 + 3][ar + 64] = a1v.w; \
        Bs[buf][ac4 + 0][ar] = b0v.x; Bs[buf][ac4 + 1][ar] = b0v.y;           \
        Bs[buf][ac4 + 2][ar] = b0v.z; Bs[buf][ac4 + 3][ar] = b0v.w;           \
        Bs[buf][ac4 + 0][ar + 64] = b1v.x; Bs[buf][ac4 + 1][ar + 64] = b1v.y; \
        Bs[buf][ac4 + 2][ar + 64] = b1v.z; Bs[buf][ac4 + 3][ar + 64] = b1v.w; \
    } while (0)

    GRLOAD(0);
    GRSTORE(0);
    __syncthreads();

    const int nk = H_ >> 4;
    for (int kt = 0; kt < nk; kt++) {
        const int cur = kt & 1;
        if (kt + 1 < nk) GRLOAD((kt + 1) * 16);
#pragma unroll
        for (int kk = 0; kk < 16; kk++) {
            float av[8];
            *(float4*)&av[0] = *(const float4*)&As[cur][kk][ty * 8];
            *(float4*)&av[4] = *(const float4*)&As[cur][kk][ty * 8 + 4];
            ulonglong2 bp0 = *(const ulonglong2*)&Bs[cur][kk][tx * 8];
            ulonglong2 bp1 = *(const ulonglong2*)&Bs[cur][kk][tx * 8 + 4];
#pragma unroll
            for (int i = 0; i < 8; i++) {
                unsigned long long ad = dup2(av[i]);
                fma2(acc[i][0], ad, bp0.x);
                fma2(acc[i][1], ad, bp0.y);
                fma2(acc[i][2], ad, bp1.x);
                fma2(acc[i][3], ad, bp1.y);
            }
        }
        if (kt + 1 < nk) GRSTORE((kt + 1) & 1);
        __syncthreads();
    }
#undef GRLOAD
#undef GRSTORE

    const float thr = phi_p[0] * 65536.0f;
    unsigned m[8][8];
    float colcnt[8];
#pragma unroll
    for (int j = 0; j < 8; j++) colcnt[j] = 0.f;

#pragma unroll
    for (int i = 0; i < 8; i++) {
        int row = bm + ty * 8 + i;
        float v[8];
#pragma unroll
        for (int j = 0; j < 4; j++) unpack2(acc[i][j], v[2 * j], v[2 * j + 1]);
        unsigned long long pack = 0ull;
        float rowcnt = 0.f;
#pragma unroll
        for (int j = 0; j < 8; j++) {
            int col = bn + tx * 8 + j;
            unsigned b = (v[j] >= thr || row == col) ? 1u : 0u;
            m[i][j] = b;
            pack |= (unsigned long long)b << (8 * j);
            rowcnt += (float)b;
            colcnt[j] += (float)b;
        }
        *(unsigned long long*)(mask + (size_t)row * NN_ + bn + tx * 8) = pack;
        atomicAdd(&deg[row], rowcnt);
    }

    if (bi != bj) {
#pragma unroll
        for (int j = 0; j < 8; j++) {
            int col = bn + tx * 8 + j;
            unsigned long long pack = 0ull;
#pragma unroll
            for (int i = 0; i < 8; i++)
                pack |= (unsigned long long)m[i][j] << (8 * i);
            *(unsigned long long*)(mask + (size_t)col * NN_ + bm + ty * 8) = pack;
            atomicAdd(&deg[col], colcnt[j]);
        }
    }
}

__global__ void dis_kernel(const float* __restrict__ deg, float* __restrict__ dis)
{
    int i = blockIdx.x * 256 + threadIdx.x;
    if (i < NN_) {
        float d = deg[i];
        dis[i] = d > 0.f ? rsqrtf(d) : 0.f;
    }
}

__global__ void yscale_kernel(const float* __restrict__ x2,
                              const float* __restrict__ dis,
                              float* __restrict__ y)
{
    int idx = blockIdx.x * 256 + threadIdx.x;
    int n = idx >> 8;
    y[idx] = x2[idx] * dis[n];
}

// ---------------------------------------------------------------------------
// Masked GCN GEMM from byte mask (fp32)
// ---------------------------------------------------------------------------
__global__ __launch_bounds__(256, 2)
void gcn_gemm_b(const unsigned char* __restrict__ mask,
                const float* __restrict__ Y,
                const float* __restrict__ dis,
                const float* __restrict__ bias,
                float* __restrict__ out)
{
    __shared__ __align__(16) float As[2][16][132];
    __shared__ __align__(16) float Bs[2][16][132];

    const int bm = blockIdx.y * 128;
    const int bn = blockIdx.x * 128;
    const int tid = threadIdx.x;
    const int tx = tid & 15;
    const int ty = tid >> 4;
    const int ar2  = tid >> 1;
    const int half = tid & 1;
    const int bkr = tid >> 5;
    const int bc4 = (tid & 31) * 4;

    unsigned long long acc[8][4];
#pragma unroll
    for (int i = 0; i < 8; i++)
#pragma unroll
        for (int j = 0; j < 4; j++) acc[i][j] = 0ull;

    unsigned long long am;
    float4 b0v, b1v;

#define MLOAD(k0)                                                             \
    do {                                                                      \
        am = *(const unsigned long long*)(mask + (size_t)(bm + ar2) * NN_ + (k0) + half * 8); \
        const float* Bp = Y + (size_t)((k0) + bkr) * GCN_ + bn + bc4;         \
        b0v = *(const float4*)Bp;                                             \
        b1v = *(const float4*)(Bp + (size_t)8 * GCN_);                        \
    } while (0)

#define MSTORE(buf)                                                           \
    do {                                                                      \
        _Pragma("unroll")                                                     \
        for (int b = 0; b < 8; b++)                                           \
            As[buf][half * 8 + b][ar2] = (float)((am >> (8 * b)) & 0xFFull);  \
        *(float4*)&Bs[buf][bkr][bc4] = b0v;                                   \
        *(float4*)&Bs[buf][bkr + 8][bc4] = b1v;                               \
    } while (0)

    MLOAD(0);
    MSTORE(0);
    __syncthreads();

    const int nk = NN_ >> 4;
    for (int kt = 0; kt < nk; kt++) {
        const int cur = kt & 1;
        if (kt + 1 < nk) MLOAD((kt + 1) * 16);
#pragma unroll
        for (int kk = 0; kk < 16; kk++) {
            float av[8];
            *(float4*)&av[0] = *(const float4*)&As[cur][kk][ty * 8];
            *(float4*)&av[4] = *(const float4*)&As[cur][kk][ty * 8 + 4];
            ulonglong2 bp0 = *(const ulonglong2*)&Bs[cur][kk][tx * 8];
            ulonglong2 bp1 = *(const ulonglong2*)&Bs[cur][kk][tx * 8 + 4];
#pragma unroll
            for (int i = 0; i < 8; i++) {
                unsigned long long ad = dup2(av[i]);
                fma2(acc[i][0], ad, bp0.x);
                fma2(acc[i][1], ad, bp0.y);
                fma2(acc[i][2], ad, bp1.x);
                fma2(acc[i][3], ad, bp1.y);
            }
        }
        if (kt + 1 < nk) MSTORE((kt + 1) & 1);
        __syncthreads();
    }
#undef MLOAD
#undef MSTORE

    float bv[8];
    *(float4*)&bv[0] = *(const float4*)(bias + bn + tx * 8);
    *(float4*)&bv[4] = *(const float4*)(bias + bn + tx * 8 + 4);

#pragma unroll
    for (int i = 0; i < 8; i++) {
        int row = bm + ty * 8 + i;
        float di = dis[row];
        float o[8];
#pragma unroll
        for (int j = 0; j < 4; j++) unpack2(acc[i][j], o[2 * j], o[2 * j + 1]);
#pragma unroll
        for (int j = 0; j < 8; j++) o[j] = di * o[j] + bv[j];
        float* Cp = out + (size_t)row * GCN_ + bn + tx * 8;
        *(float4*)Cp = *(float4*)&o[0];
        *(float4*)(Cp + 4) = *(float4*)&o[4];
    }
}

// ---------------------------------------------------------------------------
// Host orchestration
// ---------------------------------------------------------------------------
static void hgc_layer(const float* in, const float* W, const float* b,
                      const int* node_idx, const int* edge_idx,
                      float* xw, float* eb, float* agg,
                      const float* Dinv, const float* Binv, float* outbuf)
{
    sgemm_f2<false, false><<<dim3(H_ / 128, NN_ / 128), 256>>>(
        in, H_, W, H_, xw, H_, H_, nullptr);
    zero_kernel<<<(E_ * H_ / 4 + 255) / 256, 256>>>(eb, E_ * H_ / 4);
    scatter_edge_kernel<<<NNZ_ * 64 / 256, 256>>>(xw, node_idx, edge_idx, eb);
    zero_kernel<<<(NN_ * H_ / 4 + 255) / 256, 256>>>(agg, NN_ * H_ / 4);
    scatter_node_kernel<<<NNZ_ * 64 / 256, 256>>>(eb, node_idx, edge_idx, Binv, agg);
    hgc_finish_kernel<<<NN_ * H_ / 256, 256>>>(agg, Dinv, b, in, outbuf);
}

extern "C" void kernel_launch(void* const* d_in, const int* in_sizes, int n_in,
                              void* d_out, int out_size)
{
    (void)in_sizes; (void)n_in; (void)out_size;

    const float* x        = (const float*)d_in[0];
    const int*   hei      = (const int*)d_in[1];
    const int*   node_idx = hei;
    const int*   edge_idx = hei + NNZ_;
    const int*   slen     = (const int*)d_in[2];
    const float* h0       = (const float*)d_in[3];
    const float* W_ih     = (const float*)d_in[4];
    const float* W_hh     = (const float*)d_in[5];
    const float* b_ih     = (const float*)d_in[6];
    const float* b_hh     = (const float*)d_in[7];
    const float* w1 = (const float*)d_in[8];  const float* bb1 = (const float*)d_in[9];
    const float* w2 = (const float*)d_in[10]; const float* bb2 = (const float*)d_in[11];
    const float* w3 = (const float*)d_in[12]; const float* bb3 = (const float*)d_in[13];
    const float* phi = (const float*)d_in[14];
    const float* gw  = (const float*)d_in[15];
    const float* gb  = (const float*)d_in[16];
    float* out = (float*)d_out;

    float *xgall, *h, *h2, *fa, *fb, *xw, *eb, *agg, *x2, *y;
    float *deg, *Dcnt, *Dinv, *Bcnt, *Binv, *dis;
    unsigned char* mask;
    int *perm, *histb, *curb, *startb, *cntb;
    cudaGetSymbolAddress((void**)&xgall, g_xgall);
    cudaGetSymbolAddress((void**)&h,     g_h);
    cudaGetSymbolAddress((void**)&h2,    g_h2);
    cudaGetSymbolAddress((void**)&fa,    g_fa);
    cudaGetSymbolAddress((void**)&fb,    g_fb);
    cudaGetSymbolAddress((void**)&xw,    g_xw);
    cudaGetSymbolAddress((void**)&eb,    g_eb);
    cudaGetSymbolAddress((void**)&agg,   g_agg);
    cudaGetSymbolAddress((void**)&x2,    g_x2);
    cudaGetSymbolAddress((void**)&y,     g_y);
    cudaGetSymbolAddress((void**)&mask,  g_mask);
    cudaGetSymbolAddress((void**)&deg,   g_deg);
    cudaGetSymbolAddress((void**)&Dcnt,  g_Dcnt);
    cudaGetSymbolAddress((void**)&Dinv,  g_Dinv);
    cudaGetSymbolAddress((void**)&Bcnt,  g_Bcnt);
    cudaGetSymbolAddress((void**)&Binv,  g_Binv);
    cudaGetSymbolAddress((void**)&dis,   g_dis);
    cudaGetSymbolAddress((void**)&perm,  g_perm);
    cudaGetSymbolAddress((void**)&histb, g_hist);
    cudaGetSymbolAddress((void**)&curb,  g_cur);
    cudaGetSymbolAddress((void**)&startb,g_start);
    cudaGetSymbolAddress((void**)&cntb,  g_cnt);

    const int XG_SMEM = 4 * 128 * XS_ * 2;   // 90112 B
    cudaFuncSetAttribute(xg_gemm_mma,
                         cudaFuncAttributeMaxDynamicSharedMemorySize, XG_SMEM);

    // ---------------- sort rows by slen (descending) ----------------
    zero_int_kernel<<<1, 256>>>(histb, 32);
    zero_int_kernel<<<1, 256>>>(curb, 32);
    hist_kernel<<<NN_ / 256, 256>>>(slen, histb);
    scan_kernel<<<1, 32>>>(histb, cntb, startb);
    scatter_perm_kernel<<<NN_ / 256, 256>>>(slen, startb, curb, perm);

    // ---------------- GRU ----------------
    init_h_kernel<<<NN_ * H_ / 256, 256>>>(h, h0);

    // Input gates via tensor cores (bf16x3 HMMA); t-major layout, dead-skip.
    xg_gemm_mma<<<dim3(H3_ / 128, T_ * NN_ / 128), 256, XG_SMEM>>>(
        x, W_ih, b_ih, perm, cntb, xgall);

    float* hrd = h;
    float* hwr = h2;
    for (int t = 0; t < T_; t++) {
        gru_step2<<<dim3(H_ / 64, NN_ / 64), 256>>>(
            W_hh, b_hh, xgall, hrd, hwr, perm, cntb, fa, t);
        float* tmp = hrd; hrd = hwr; hwr = tmp;
    }
    // fa now holds `last` [N,H] in ORIGINAL row order

    // ---------------- degrees (shared by 3 HGC layers) ----------------
    zero_kernel<<<(NN_ / 4 + 255) / 256, 256>>>(Dcnt, NN_ / 4);
    zero_kernel<<<(E_ / 4 + 255) / 256, 256>>>(Bcnt, E_ / 4);
    count_deg_kernel<<<NNZ_ / 256, 256>>>(node_idx, edge_idx, Dcnt, Bcnt);
    make_inv_kernel<<<(NN_ + 255) / 256, 256>>>(Dcnt, Dinv, NN_);
    make_inv_kernel<<<(E_ + 255) / 256, 256>>>(Bcnt, Binv, E_);

    // ---------------- 3 hypergraph conv layers with residuals ----------------
    hgc_layer(fa, w1, bb1, node_idx, edge_idx, xw, eb, agg, Dinv, Binv, fb); // o1
    hgc_layer(fb, w2, bb2, node_idx, edge_idx, xw, eb, agg, Dinv, Binv, fa); // o2
    hgc_layer(fa, w3, bb3, node_idx, edge_idx, xw, eb, agg, Dinv, Binv, fb); // o3

    // ---------------- final dense GCN ----------------
    sgemm_f2<false, false><<<dim3(GCN_ / 128, NN_ / 128), 256>>>(
        fb, H_, gw, GCN_, x2, GCN_, H_, nullptr);

    zero_kernel<<<(NN_ / 4 + 255) / 256, 256>>>(deg, NN_ / 4);
    gram_sym_kernel<<<64 * 65 / 2, 256>>>(fb, mask, deg, phi);
    dis_kernel<<<(NN_ + 255) / 256, 256>>>(deg, dis);
    yscale_kernel<<<NN_ * GCN_ / 256, 256>>>(x2, dis, y);
    gcn_gemm_b<<<dim3(GCN_ / 128, NN_ / 128), 256>>>(mask, y, dis, gb, out);
}

// round 7
// speedup vs baseline: 2.8590x; 1.5498x over previous
#include <cuda_runtime.h>
#include <cuda_bf16.h>
#include <cstdint>
#include <cstdio>

// Problem constants
#define NN_   8192
#define T_    32
#define IN_   256
#define H_    256
#define H3_   768
#define E_    1024
#define NNZ_  65536
#define GCN_  256

// ---------------------------------------------------------------------------
// Scratch (static device globals; no runtime allocation)
// ---------------------------------------------------------------------------
__device__ float g_xgall[(size_t)NN_ * T_ * H3_];   // [t][pos][768] t-major, sorted rows
__device__ float g_h [NN_ * H_];                    // GRU hidden ping (sorted order)
__device__ float g_h2[NN_ * H_];                    // GRU hidden pong (sorted order)
__device__ float g_fa[NN_ * H_];                    // feature ping (last / o2)
__device__ float g_fb[NN_ * H_];                    // feature pong (o1 / o3)
__device__ float g_xw[NN_ * H_];                    // HGC x@W
__device__ float g_agg[NN_ * H_];                   // HGC node aggregation
__device__ float g_eb[E_ * H_];                     // HGC edge accumulator
__device__ float g_x2[NN_ * GCN_];                  // o3 @ gcn_w
__device__ unsigned char g_mask[(size_t)NN_ * NN_]; // 64 MB adjacency mask bytes
__device__ float g_deg[NN_];
__device__ float g_Dcnt[NN_];
__device__ float g_Dinv[NN_];
__device__ float g_Bcnt[E_];
__device__ float g_Binv[E_];
__device__ float g_dis[NN_];
// bf16 pre-split buffers
__device__ __nv_bfloat16 g_whh_h[H3_ * H_];
__device__ __nv_bfloat16 g_whh_l[H3_ * H_];
__device__ __nv_bfloat16 g_yth[(size_t)GCN_ * NN_]; // Y^T hi  [n][k]
__device__ __nv_bfloat16 g_ytl[(size_t)GCN_ * NN_]; // Y^T lo
// sort machinery
__device__ int g_perm[NN_];
__device__ int g_hist[32];
__device__ int g_cur[32];
__device__ int g_start[32];
__device__ int g_cnt[T_ + 1];

// ---------------------------------------------------------------------------
// Packed fp32x2 helpers
// ---------------------------------------------------------------------------
__device__ __forceinline__ void fma2(unsigned long long& d,
                                     unsigned long long a,
                                     unsigned long long b)
{
    asm("fma.rn.f32x2 %0, %1, %2, %0;" : "+l"(d) : "l"(a), "l"(b));
}

__device__ __forceinline__ unsigned long long dup2(float x)
{
    unsigned long long r;
    unsigned u = __float_as_uint(x);
    asm("mov.b64 %0, {%1, %1};" : "=l"(r) : "r"(u));
    return r;
}

__device__ __forceinline__ void unpack2(unsigned long long v, float& lo, float& hi)
{
    unsigned a, b;
    asm("mov.b64 {%0, %1}, %2;" : "=r"(a), "=r"(b) : "l"(v));
    lo = __uint_as_float(a);
    hi = __uint_as_float(b);
}

__device__ __forceinline__ float sigf(float x)
{
    return 1.f / (1.f + __expf(-x));
}

// ---------------------------------------------------------------------------
// bf16 split + warp MMA helpers (mma.sync m16n8k16, base-ISA)
// ---------------------------------------------------------------------------
__device__ __forceinline__ void split8(const float* __restrict__ s, uint4& hi, uint4& lo)
{
    float4 v0 = *(const float4*)s;
    float4 v1 = *(const float4*)(s + 4);
    float vv[8] = {v0.x, v0.y, v0.z, v0.w, v1.x, v1.y, v1.z, v1.w};
    unsigned hw[4], lw[4];
#pragma unroll
    for (int p = 0; p < 4; p++) {
        __nv_bfloat16 h0 = __float2bfloat16(vv[2 * p]);
        __nv_bfloat16 h1 = __float2bfloat16(vv[2 * p + 1]);
        __nv_bfloat16 l0 = __float2bfloat16(vv[2 * p] - __bfloat162float(h0));
        __nv_bfloat16 l1 = __float2bfloat16(vv[2 * p + 1] - __bfloat162float(h1));
        __nv_bfloat162 hp = __halves2bfloat162(h0, h1);
        __nv_bfloat162 lp = __halves2bfloat162(l0, l1);
        hw[p] = *(unsigned*)&hp;
        lw[p] = *(unsigned*)&lp;
    }
    hi = make_uint4(hw[0], hw[1], hw[2], hw[3]);
    lo = make_uint4(lw[0], lw[1], lw[2], lw[3]);
}

__device__ __forceinline__ void mma_bf16(float* c, const uint32_t* a, const uint32_t* b)
{
    asm volatile(
        "mma.sync.aligned.m16n8k16.row.col.f32.bf16.bf16.f32 "
        "{%0,%1,%2,%3}, {%4,%5,%6,%7}, {%8,%9}, {%0,%1,%2,%3};"
        : "+f"(c[0]), "+f"(c[1]), "+f"(c[2]), "+f"(c[3])
        : "r"(a[0]), "r"(a[1]), "r"(a[2]), "r"(a[3]), "r"(b[0]), "r"(b[1]));
}

// ---------------------------------------------------------------------------
// One-time split kernels
// ---------------------------------------------------------------------------
__global__ void split_w_kernel(const float* __restrict__ W,
                               __nv_bfloat16* __restrict__ Wh,
                               __nv_bfloat16* __restrict__ Wl, int n)
{
    int i = blockIdx.x * 256 + threadIdx.x;
    if (i < n) {
        float v = W[i];
        __nv_bfloat16 h = __float2bfloat16(v);
        Wh[i] = h;
        Wl[i] = __float2bfloat16(v - __bfloat162float(h));
    }
}

// Y^T build: Yt[n][k] = dis[k] * x2[k][n], split hi/lo bf16.
// grid (NN/32, GCN/32), block (32,8).
__global__ void yt_split_kernel(const float* __restrict__ x2,
                                const float* __restrict__ dis,
                                __nv_bfloat16* __restrict__ Yth,
                                __nv_bfloat16* __restrict__ Ytl)
{
    __shared__ float tile[32][33];
    int kb = blockIdx.x * 32;
    int nb = blockIdx.y * 32;
    int tx = threadIdx.x, ty = threadIdx.y;
    for (int i = ty; i < 32; i += 8)
        tile[i][tx] = x2[(size_t)(kb + i) * GCN_ + nb + tx] * dis[kb + i];
    __syncthreads();
    for (int i = ty; i < 32; i += 8) {
        float v = tile[tx][i];
        __nv_bfloat16 h = __float2bfloat16(v);
        Yth[(size_t)(nb + i) * NN_ + kb + tx] = h;
        Ytl[(size_t)(nb + i) * NN_ + kb + tx] = __float2bfloat16(v - __bfloat162float(h));
    }
}

// ---------------------------------------------------------------------------
// Tensor-core input-gate GEMM with bf16x3 split (round-6 proven).
// ---------------------------------------------------------------------------
#define XS_ 88
__global__ __launch_bounds__(256, 2)
void xg_gemm_mma(const float* __restrict__ x,
                 const float* __restrict__ Wih,
                 const float* __restrict__ bih,
                 const int* __restrict__ perm,
                 const int* __restrict__ cnt,
                 float* __restrict__ xgall)
{
    const int bm = blockIdx.y * 128;
    const int t = bm >> 13;
    const int pos0 = bm & (NN_ - 1);
    if (pos0 >= cnt[t]) return;
    const int bn = blockIdx.x * 128;

    extern __shared__ __align__(16) __nv_bfloat16 smx[];
    __nv_bfloat16* Ah = smx;
    __nv_bfloat16* Al = smx + 128 * XS_;
    __nv_bfloat16* Bh = smx + 2 * 128 * XS_;
    __nv_bfloat16* Bl = smx + 3 * 128 * XS_;

    const int tid = threadIdx.x;
    const int wid = tid >> 5;
    const int lane = tid & 31;
    const int wm = (wid & 3) * 32;
    const int wn = (wid >> 2) * 64;
    const int grp = lane >> 2;
    const int tig = lane & 3;

    float acc[2][8][4];
#pragma unroll
    for (int mt = 0; mt < 2; mt++)
#pragma unroll
        for (int nt = 0; nt < 8; nt++)
#pragma unroll
            for (int e = 0; e < 4; e++) acc[mt][nt][e] = 0.f;

    for (int kc = 0; kc < 4; kc++) {
#pragma unroll
        for (int i = 0; i < 8; i++) {
            int u = i * 256 + tid;
            int r = u >> 3;
            int cg = u & 7;
            const float* src;
            __nv_bfloat16 *dh, *dl;
            int lr;
            if (r < 128) {
                src = x + (size_t)perm[pos0 + r] * (T_ * IN_) + t * IN_ + kc * 64 + cg * 8;
                dh = Ah; dl = Al; lr = r;
            } else {
                lr = r - 128;
                src = Wih + (size_t)(bn + lr) * IN_ + kc * 64 + cg * 8;
                dh = Bh; dl = Bl;
            }
            uint4 hi, lo;
            split8(src, hi, lo);
            *(uint4*)(dh + lr * XS_ + cg * 8) = hi;
            *(uint4*)(dl + lr * XS_ + cg * 8) = lo;
        }
        __syncthreads();

#pragma unroll
        for (int ks = 0; ks < 4; ks++) {
            const int kk = ks * 16;
            uint32_t ah[2][4], al[2][4];
#pragma unroll
            for (int mt = 0; mt < 2; mt++) {
                int r0 = wm + mt * 16 + grp;
                ah[mt][0] = *(const uint32_t*)(Ah + (size_t)r0 * XS_ + kk + tig * 2);
                ah[mt][1] = *(const uint32_t*)(Ah + (size_t)(r0 + 8) * XS_ + kk + tig * 2);
                ah[mt][2] = *(const uint32_t*)(Ah + (size_t)r0 * XS_ + kk + 8 + tig * 2);
                ah[mt][3] = *(const uint32_t*)(Ah + (size_t)(r0 + 8) * XS_ + kk + 8 + tig * 2);
                al[mt][0] = *(const uint32_t*)(Al + (size_t)r0 * XS_ + kk + tig * 2);
                al[mt][1] = *(const uint32_t*)(Al + (size_t)(r0 + 8) * XS_ + kk + tig * 2);
                al[mt][2] = *(const uint32_t*)(Al + (size_t)r0 * XS_ + kk + 8 + tig * 2);
                al[mt][3] = *(const uint32_t*)(Al + (size_t)(r0 + 8) * XS_ + kk + 8 + tig * 2);
            }
#pragma unroll
            for (int nt = 0; nt < 8; nt++) {
                int nr = wn + nt * 8 + grp;
                uint32_t bh[2], bl[2];
                bh[0] = *(const uint32_t*)(Bh + (size_t)nr * XS_ + kk + tig * 2);
                bh[1] = *(const uint32_t*)(Bh + (size_t)nr * XS_ + kk + 8 + tig * 2);
                bl[0] = *(const uint32_t*)(Bl + (size_t)nr * XS_ + kk + tig * 2);
                bl[1] = *(const uint32_t*)(Bl + (size_t)nr * XS_ + kk + 8 + tig * 2);
#pragma unroll
                for (int mt = 0; mt < 2; mt++) {
                    mma_bf16(acc[mt][nt], ah[mt], bh);
                    mma_bf16(acc[mt][nt], ah[mt], bl);
                    mma_bf16(acc[mt][nt], al[mt], bh);
                }
            }
        }
        __syncthreads();
    }

#pragma unroll
    for (int mt = 0; mt < 2; mt++) {
#pragma unroll
        for (int nt = 0; nt < 8; nt++) {
            int row0 = bm + wm + mt * 16 + grp;
            int col = bn + wn + nt * 8 + tig * 2;
            float2 bv = *(const float2*)(bih + col);
            float2 o0 = make_float2(acc[mt][nt][0] + bv.x, acc[mt][nt][1] + bv.y);
            float2 o1 = make_float2(acc[mt][nt][2] + bv.x, acc[mt][nt][3] + bv.y);
            *(float2*)(xgall + (size_t)row0 * H3_ + col) = o0;
            *(float2*)(xgall + (size_t)(row0 + 8) * H3_ + col) = o1;
        }
    }
}

// ---------------------------------------------------------------------------
// Fused GRU step, HMMA bf16x3. M=64 rows, N=64 cols x 3 gates, K=256.
// 8 warps (2m x 4n); each warp holds r/z/q fragments for identical (row,col)
// so the gate nonlinearity fuses in registers. W_hh comes pre-split (bf16),
// only h is split on the fly. Grid (4, NN/64). Dead-block skip on cnt[t].
// ---------------------------------------------------------------------------
#define GS_ 72
__global__ __launch_bounds__(256)
void gru_step_mma(const __nv_bfloat16* __restrict__ Whh_h,
                  const __nv_bfloat16* __restrict__ Whh_l,
                  const float* __restrict__ bhh,
                  const float* __restrict__ xgall,
                  const float* __restrict__ hin,
                  float* __restrict__ hout,
                  const int* __restrict__ perm,
                  const int* __restrict__ cnt,
                  float* __restrict__ last, int t)
{
    const int bm = blockIdx.y * 64;
    const int c0 = cnt[t];
    if (bm >= c0) return;
    const int c1 = cnt[t + 1];
    const int bn = blockIdx.x * 64;

    extern __shared__ __align__(16) __nv_bfloat16 smg[];
    __nv_bfloat16* Ah = smg;                          // [64][GS_]
    __nv_bfloat16* Al = smg + 64 * GS_;
    __nv_bfloat16* Bh = smg + 2 * 64 * GS_;           // [192][GS_]
    __nv_bfloat16* Bl = smg + 2 * 64 * GS_ + 192 * GS_;

    const int tid = threadIdx.x;
    const int wid = tid >> 5;
    const int lane = tid & 31;
    const int wm = (wid & 1) * 32;
    const int wn16 = (wid >> 1) * 16;
    const int grp = lane >> 2;
    const int tig = lane & 3;

    float acc[2][3][2][4];   // [mtile][gate][ntile][frag]
#pragma unroll
    for (int mt = 0; mt < 2; mt++)
#pragma unroll
        for (int g = 0; g < 3; g++)
#pragma unroll
            for (int nt = 0; nt < 2; nt++)
#pragma unroll
                for (int e = 0; e < 4; e++) acc[mt][g][nt][e] = 0.f;

    for (int kc = 0; kc < 4; kc++) {
        // A: split hin 64 rows x 64 floats (2 tasks/thread)
#pragma unroll
        for (int i = 0; i < 2; i++) {
            int u = i * 256 + tid;
            int r = u >> 3;
            int cg = u & 7;
            uint4 hi, lo;
            split8(hin + (size_t)(bm + r) * H_ + kc * 64 + cg * 8, hi, lo);
            *(uint4*)(Ah + r * GS_ + cg * 8) = hi;
            *(uint4*)(Al + r * GS_ + cg * 8) = lo;
        }
        // B: copy pre-split W_hh, 192 rows x 64 bf16 (6 tasks/thread)
#pragma unroll
        for (int i = 0; i < 6; i++) {
            int u = i * 256 + tid;
            int r = u >> 3;          // 0..191
            int cg = u & 7;
            int g = r >> 6;
            int br = r & 63;
            size_t goff = (size_t)(g * 256 + bn + br) * H_ + kc * 64 + cg * 8;
            *(uint4*)(Bh + r * GS_ + cg * 8) = *(const uint4*)(Whh_h + goff);
            *(uint4*)(Bl + r * GS_ + cg * 8) = *(const uint4*)(Whh_l + goff);
        }
        __syncthreads();

#pragma unroll
        for (int ks = 0; ks < 4; ks++) {
            const int kk = ks * 16;
            uint32_t ah[2][4], al[2][4];
#pragma unroll
            for (int mt = 0; mt < 2; mt++) {
                int r0 = wm + mt * 16 + grp;
                ah[mt][0] = *(const uint32_t*)(Ah + (size_t)r0 * GS_ + kk + tig * 2);
                ah[mt][1] = *(const uint32_t*)(Ah + (size_t)(r0 + 8) * GS_ + kk + tig * 2);
                ah[mt][2] = *(const uint32_t*)(Ah + (size_t)r0 * GS_ + kk + 8 + tig * 2);
                ah[mt][3] = *(const uint32_t*)(Ah + (size_t)(r0 + 8) * GS_ + kk + 8 + tig * 2);
                al[mt][0] = *(const uint32_t*)(Al + (size_t)r0 * GS_ + kk + tig * 2);
                al[mt][1] = *(const uint32_t*)(Al + (size_t)(r0 + 8) * GS_ + kk + tig * 2);
                al[mt][2] = *(const uint32_t*)(Al + (size_t)r0 * GS_ + kk + 8 + tig * 2);
                al[mt][3] = *(const uint32_t*)(Al + (size_t)(r0 + 8) * GS_ + kk + 8 + tig * 2);
            }
#pragma unroll
            for (int g = 0; g < 3; g++) {
#pragma unroll
                for (int nt = 0; nt < 2; nt++) {
                    int nr = g * 64 + wn16 + nt * 8 + grp;
                    uint32_t bh[2], bl[2];
                    bh[0] = *(const uint32_t*)(Bh + (size_t)nr * GS_ + kk + tig * 2);
                    bh[1] = *(const uint32_t*)(Bh + (size_t)nr * GS_ + kk + 8 + tig * 2);
                    bl[0] = *(const uint32_t*)(Bl + (size_t)nr * GS_ + kk + tig * 2);
                    bl[1] = *(const uint32_t*)(Bl + (size_t)nr * GS_ + kk + 8 + tig * 2);
#pragma unroll
                    for (int mt = 0; mt < 2; mt++) {
                        mma_bf16(acc[mt][g][nt], ah[mt], bh);
                        mma_bf16(acc[mt][g][nt], ah[mt], bl);
                        mma_bf16(acc[mt][g][nt], al[mt], bh);
                    }
                }
            }
        }
        __syncthreads();
    }

    // epilogue: gate math directly from fragments
#pragma unroll
    for (int mt = 0; mt < 2; mt++) {
        int rbase = bm + wm + mt * 16 + grp;
#pragma unroll
        for (int half = 0; half < 2; half++) {
            int row = rbase + half * 8;
            bool isLast = (row >= c1 && row < c0);
            int pr = isLast ? perm[row] : 0;
            size_t xb = ((size_t)t * NN_ + row) * H3_;
            size_t hb = (size_t)row * H_;
#pragma unroll
            for (int nt = 0; nt < 2; nt++) {
                int col = bn + wn16 + nt * 8 + tig * 2;
                float2 xr = *(const float2*)(xgall + xb + col);
                float2 xz = *(const float2*)(xgall + xb + 256 + col);
                float2 xq = *(const float2*)(xgall + xb + 512 + col);
                float2 ho = *(const float2*)(hin + hb + col);
                float2 br = *(const float2*)(bhh + col);
                float2 bz = *(const float2*)(bhh + 256 + col);
                float2 bq = *(const float2*)(bhh + 512 + col);
                float hr0 = acc[mt][0][nt][half * 2 + 0];
                float hr1 = acc[mt][0][nt][half * 2 + 1];
                float hz0 = acc[mt][1][nt][half * 2 + 0];
                float hz1 = acc[mt][1][nt][half * 2 + 1];
                float hq0 = acc[mt][2][nt][half * 2 + 0];
                float hq1 = acc[mt][2][nt][half * 2 + 1];
                float r0 = sigf(xr.x + hr0 + br.x);
                float z0 = sigf(xz.x + hz0 + bz.x);
                float q0 = tanhf(xq.x + r0 * (hq0 + bq.x));
                float r1 = sigf(xr.y + hr1 + br.y);
                float z1 = sigf(xz.y + hz1 + bz.y);
                float q1 = tanhf(xq.y + r1 * (hq1 + bq.y));
                float2 hn = make_float2((1.f - z0) * q0 + z0 * ho.x,
                                        (1.f - z1) * q1 + z1 * ho.y);
                *(float2*)(hout + hb + col) = hn;
                if (isLast)
                    *(float2*)(last + (size_t)pr * H_ + col) = hn;
            }
        }
    }
}

// ---------------------------------------------------------------------------
// Masked GCN GEMM, HMMA: A = mask (EXACT in bf16, 0/1), B = pre-split Y^T.
// out[i,d] = dis_i * sum_j mask_ij * Y[j,d] + bias[d].
// M=128, N=64, K=8192 in 64-chunks. 8 warps (4m x 2n). Grid (4, 64).
// ---------------------------------------------------------------------------
#define CS_ 72
__global__ __launch_bounds__(256, 2)
void gcn_gemm_mma(const unsigned char* __restrict__ mask,
                  const __nv_bfloat16* __restrict__ Yth,
                  const __nv_bfloat16* __restrict__ Ytl,
                  const float* __restrict__ dis,
                  const float* __restrict__ bias,
                  float* __restrict__ out)
{
    __shared__ __align__(16) __nv_bfloat16 Am[128 * CS_];
    __shared__ __align__(16) __nv_bfloat16 Bh[64 * CS_];
    __shared__ __align__(16) __nv_bfloat16 Bl[64 * CS_];

    const int bm = blockIdx.y * 128;
    const int bn = blockIdx.x * 64;
    const int tid = threadIdx.x;
    const int wid = tid >> 5;
    const int lane = tid & 31;
    const int wm = (wid & 3) * 32;
    const int wn = (wid >> 2) * 32;
    const int grp = lane >> 2;
    const int tig = lane & 3;

    float acc[2][4][4];
#pragma unroll
    for (int mt = 0; mt < 2; mt++)
#pragma unroll
        for (int nt = 0; nt < 4; nt++)
#pragma unroll
            for (int e = 0; e < 4; e++) acc[mt][nt][e] = 0.f;

    for (int kc = 0; kc < NN_ / 64; kc++) {
        // mask bytes -> bf16 0/1 (exact). 128 rows x 64 cols, 4 tasks/thread.
#pragma unroll
        for (int i = 0; i < 4; i++) {
            int u = i * 256 + tid;
            int r = u >> 3;
            int cg = u & 7;
            unsigned long long mb = *(const unsigned long long*)(
                mask + (size_t)(bm + r) * NN_ + kc * 64 + cg * 8);
            unsigned w[4];
#pragma unroll
            for (int p = 0; p < 4; p++) {
                unsigned lo16 = ((mb >> (16 * p)) & 0xFFull) ? 0x3F80u : 0u;
                unsigned hi16 = ((mb >> (16 * p + 8)) & 0xFFull) ? 0x3F80u : 0u;
                w[p] = lo16 | (hi16 << 16);
            }
            *(uint4*)(Am + r * CS_ + cg * 8) = make_uint4(w[0], w[1], w[2], w[3]);
        }
        // Y^T: 64 n-rows x 64 k bf16, hi+lo (2 tasks/thread each)
#pragma unroll
        for (int i = 0; i < 2; i++) {
            int u = i * 256 + tid;
            int r = u >> 3;
            int cg = u & 7;
            size_t goff = (size_t)(bn + r) * NN_ + kc * 64 + cg * 8;
            *(uint4*)(Bh + r * CS_ + cg * 8) = *(const uint4*)(Yth + goff);
            *(uint4*)(Bl + r * CS_ + cg * 8) = *(const uint4*)(Ytl + goff);
        }
        __syncthreads();

#pragma unroll
        for (int ks = 0; ks < 4; ks++) {
            const int kk = ks * 16;
            uint32_t am[2][4];
#pragma unroll
            for (int mt = 0; mt < 2; mt++) {
                int r0 = wm + mt * 16 + grp;
                am[mt][0] = *(const uint32_t*)(Am + (size_t)r0 * CS_ + kk + tig * 2);
                am[mt][1] = *(const uint32_t*)(Am + (size_t)(r0 + 8) * CS_ + kk + tig * 2);
                am[mt][2] = *(const uint32_t*)(Am + (size_t)r0 * CS_ + kk + 8 + tig * 2);
                am[mt][3] = *(const uint32_t*)(Am + (size_t)(r0 + 8) * CS_ + kk + 8 + tig * 2);
            }
#pragma unroll
            for (int nt = 0; nt < 4; nt++) {
                int nr = wn + nt * 8 + grp;
                uint32_t bh[2], bl[2];
                bh[0] = *(const uint32_t*)(Bh + (size_t)nr * CS_ + kk + tig * 2);
                bh[1] = *(const uint32_t*)(Bh + (size_t)nr * CS_ + kk + 8 + tig * 2);
                bl[0] = *(const uint32_t*)(Bl + (size_t)nr * CS_ + kk + tig * 2);
                bl[1] = *(const uint32_t*)(Bl + (size_t)nr * CS_ + kk + 8 + tig * 2);
#pragma unroll
                for (int mt = 0; mt < 2; mt++) {
                    mma_bf16(acc[mt][nt], am[mt], bh);
                    mma_bf16(acc[mt][nt], am[mt], bl);
                }
            }
        }
        __syncthreads();
    }

#pragma unroll
    for (int mt = 0; mt < 2; mt++) {
#pragma unroll
        for (int nt = 0; nt < 4; nt++) {
            int row0 = bm + wm + mt * 16 + grp;
            int col = bn + wn + nt * 8 + tig * 2;
            float2 bv = *(const float2*)(bias + col);
            float d0 = dis[row0];
            float d1 = dis[row0 + 8];
            float2 o0 = make_float2(d0 * acc[mt][nt][0] + bv.x,
                                    d0 * acc[mt][nt][1] + bv.y);
            float2 o1 = make_float2(d1 * acc[mt][nt][2] + bv.x,
                                    d1 * acc[mt][nt][3] + bv.y);
            *(float2*)(out + (size_t)row0 * GCN_ + col) = o0;
            *(float2*)(out + (size_t)(row0 + 8) * GCN_ + col) = o1;
        }
    }
}

// ---------------------------------------------------------------------------
// Tiled SGEMM with packed f32x2 FMA (fp32 path; HGC + x2)
// ---------------------------------------------------------------------------
template<bool TRANSB, bool BIAS>
__global__ __launch_bounds__(256, 2)
void sgemm_f2(const float* __restrict__ A, int lda,
              const float* __restrict__ B, int ldb,
              float* __restrict__ C, int ldc,
              int K, const float* __restrict__ bias)
{
    __shared__ __align__(16) float As[2][16][132];
    __shared__ __align__(16) float Bs[2][16][132];

    const int bm = blockIdx.y * 128;
    const int bn = blockIdx.x * 128;
    const int tid = threadIdx.x;
    const int tx = tid & 15;
    const int ty = tid >> 4;
    const int ar  = tid >> 2;
    const int ac4 = (tid & 3) * 4;
    const int bkr = tid >> 5;
    const int bc4 = (tid & 31) * 4;

    unsigned long long acc[8][4];
#pragma unroll
    for (int i = 0; i < 8; i++)
#pragma unroll
        for (int j = 0; j < 4; j++) acc[i][j] = 0ull;

    float4 a0v, a1v, b0v, b1v;

#define LOAD_TILE(k0)                                                         \
    do {                                                                      \
        const float* Ap = A + (size_t)(bm + ar) * lda + (k0) + ac4;          \
        a0v = *(const float4*)Ap;                                             \
        a1v = *(const float4*)(Ap + (size_t)64 * lda);                        \
        if (TRANSB) {                                                         \
            const float* Bp = B + (size_t)(bn + ar) * ldb + (k0) + ac4;      \
            b0v = *(const float4*)Bp;                                         \
            b1v = *(const float4*)(Bp + (size_t)64 * ldb);                    \
        } else {                                                              \
            const float* Bp = B + (size_t)((k0) + bkr) * ldb + bn + bc4;      \
            b0v = *(const float4*)Bp;                                         \
            b1v = *(const float4*)(Bp + (size_t)8 * ldb);                     \
        }                                                                     \
    } while (0)

#define STORE_TILE(buf)                                                       \
    do {                                                                      \
        As[buf][ac4 + 0][ar] = a0v.x; As[buf][ac4 + 1][ar] = a0v.y;           \
        As[buf][ac4 + 2][ar] = a0v.z; As[buf][ac4 + 3][ar] = a0v.w;           \
        As[buf][ac4 + 0][ar + 64] = a1v.x; As[buf][ac4 + 1][ar + 64] = a1v.y; \
        As[buf][ac4 + 2][ar + 64] = a1v.z; As[buf][ac4 + 3][ar + 64] = a1v.w; \
        if (TRANSB) {                                                         \
            Bs[buf][ac4 + 0][ar] = b0v.x; Bs[buf][ac4 + 1][ar] = b0v.y;       \
            Bs[buf][ac4 + 2][ar] = b0v.z; Bs[buf][ac4 + 3][ar] = b0v.w;       \
            Bs[buf][ac4 + 0][ar + 64] = b1v.x; Bs[buf][ac4 + 1][ar + 64] = b1v.y; \
            Bs[buf][ac4 + 2][ar + 64] = b1v.z; Bs[buf][ac4 + 3][ar + 64] = b1v.w; \
        } else {                                                              \
            *(float4*)&Bs[buf][bkr][bc4] = b0v;                               \
            *(float4*)&Bs[buf][bkr + 8][bc4] = b1v;                           \
        }                                                                     \
    } while (0)

    LOAD_TILE(0);
    STORE_TILE(0);
    __syncthreads();

    const int nk = K >> 4;
    for (int kt = 0; kt < nk; kt++) {
        const int cur = kt & 1;
        if (kt + 1 < nk) LOAD_TILE((kt + 1) * 16);

#pragma unroll
        for (int kk = 0; kk < 16; kk++) {
            float av[8];
            *(float4*)&av[0] = *(const float4*)&As[cur][kk][ty * 8];
            *(float4*)&av[4] = *(const float4*)&As[cur][kk][ty * 8 + 4];
            ulonglong2 bp0 = *(const ulonglong2*)&Bs[cur][kk][tx * 8];
            ulonglong2 bp1 = *(const ulonglong2*)&Bs[cur][kk][tx * 8 + 4];
#pragma unroll
            for (int i = 0; i < 8; i++) {
                unsigned long long ad = dup2(av[i]);
                fma2(acc[i][0], ad, bp0.x);
                fma2(acc[i][1], ad, bp0.y);
                fma2(acc[i][2], ad, bp1.x);
                fma2(acc[i][3], ad, bp1.y);
            }
        }
        if (kt + 1 < nk) STORE_TILE((kt + 1) & 1);
        __syncthreads();
    }
#undef LOAD_TILE
#undef STORE_TILE

    float bv[8];
    if (BIAS) {
        *(float4*)&bv[0] = *(const float4*)(bias + bn + tx * 8);
        *(float4*)&bv[4] = *(const float4*)(bias + bn + tx * 8 + 4);
    }

#pragma unroll
    for (int i = 0; i < 8; i++) {
        int row = bm + ty * 8 + i;
        float o[8];
#pragma unroll
        for (int j = 0; j < 4; j++) unpack2(acc[i][j], o[2 * j], o[2 * j + 1]);
        if (BIAS) {
#pragma unroll
            for (int j = 0; j < 8; j++) o[j] += bv[j];
        }
        float* Cp = C + (size_t)row * ldc + bn + tx * 8;
        *(float4*)Cp = *(float4*)&o[0];
        *(float4*)(Cp + 4) = *(float4*)&o[4];
    }
}

// ---------------------------------------------------------------------------
// Sorting by sequence length (counting sort, descending)
// ---------------------------------------------------------------------------
__global__ void zero_int_kernel(int* __restrict__ p, int n)
{
    int i = blockIdx.x * 256 + threadIdx.x;
    if (i < n) p[i] = 0;
}

__global__ void hist_kernel(const int* __restrict__ slen, int* __restrict__ hist)
{
    int i = blockIdx.x * 256 + threadIdx.x;
    if (i < NN_) atomicAdd(&hist[slen[i] - 1], 1);
}

__global__ void scan_kernel(const int* __restrict__ hist,
                            int* __restrict__ cnt, int* __restrict__ start)
{
    if (threadIdx.x == 0) {
        int run = 0;
        cnt[T_] = 0;
        for (int s = T_ - 1; s >= 0; s--) {
            start[s] = run;
            run += hist[s];
            cnt[s] = run;
        }
    }
}

__global__ void scatter_perm_kernel(const int* __restrict__ slen,
                                    const int* __restrict__ start,
                                    int* __restrict__ cur,
                                    int* __restrict__ perm)
{
    int i = blockIdx.x * 256 + threadIdx.x;
    if (i < NN_) {
        int s = slen[i] - 1;
        int pos = start[s] + atomicAdd(&cur[s], 1);
        perm[pos] = i;
    }
}

__global__ void init_h_kernel(float* __restrict__ h, const float* __restrict__ h0)
{
    int idx = blockIdx.x * 256 + threadIdx.x;
    h[idx] = h0[idx & (H_ - 1)];
}

// ---------------------------------------------------------------------------
// Hypergraph conv support
// ---------------------------------------------------------------------------
__global__ void zero_kernel(float* __restrict__ p, int n4)
{
    int i = blockIdx.x * 256 + threadIdx.x;
    if (i < n4) ((float4*)p)[i] = make_float4(0.f, 0.f, 0.f, 0.f);
}

__global__ void count_deg_kernel(const int* __restrict__ node_idx,
                                 const int* __restrict__ edge_idx,
                                 float* __restrict__ D, float* __restrict__ B)
{
    int i = blockIdx.x * 256 + threadIdx.x;
    if (i < NNZ_) {
        atomicAdd(&D[node_idx[i]], 1.f);
        atomicAdd(&B[edge_idx[i]], 1.f);
    }
}

__global__ void make_inv_kernel(const float* __restrict__ cnt, float* __restrict__ inv, int n)
{
    int i = blockIdx.x * 256 + threadIdx.x;
    if (i < n) {
        float c = cnt[i];
        inv[i] = c > 0.f ? 1.f / c : 0.f;
    }
}

__global__ void scatter_edge_kernel(const float* __restrict__ xw,
                                    const int* __restrict__ node_idx,
                                    const int* __restrict__ edge_idx,
                                    float* __restrict__ eb)
{
    int idx = blockIdx.x * 256 + threadIdx.x;
    int nz = idx >> 6;
    int c4 = (idx & 63) << 2;
    int n = node_idx[nz];
    int e = edge_idx[nz];
    float4 v = *(const float4*)(xw + (size_t)n * H_ + c4);
    float* dst = eb + (size_t)e * H_ + c4;
    atomicAdd(dst + 0, v.x); atomicAdd(dst + 1, v.y);
    atomicAdd(dst + 2, v.z); atomicAdd(dst + 3, v.w);
}

__global__ void scatter_node_kernel(const float* __restrict__ eb,
                                    const int* __restrict__ node_idx,
                                    const int* __restrict__ edge_idx,
                                    const float* __restrict__ Binv,
                                    float* __restrict__ agg)
{
    int idx = blockIdx.x * 256 + threadIdx.x;
    int nz = idx >> 6;
    int c4 = (idx & 63) << 2;
    int n = node_idx[nz];
    int e = edge_idx[nz];
    float be = Binv[e];
    float4 v = *(const float4*)(eb + (size_t)e * H_ + c4);
    float* dst = agg + (size_t)n * H_ + c4;
    atomicAdd(dst + 0, v.x * be); atomicAdd(dst + 1, v.y * be);
    atomicAdd(dst + 2, v.z * be); atomicAdd(dst + 3, v.w * be);
}

__global__ void hgc_finish_kernel(const float* __restrict__ agg,
                                  const float* __restrict__ Dinv,
                                  const float* __restrict__ bias,
                                  const float* __restrict__ resid,
                                  float* __restrict__ out)
{
    int idx = blockIdx.x * 256 + threadIdx.x;
    int n = idx >> 8;
    int c = idx & 255;
    out[idx] = agg[idx] * Dinv[n] + bias[c] + resid[idx];
}

// ---------------------------------------------------------------------------
// Symmetric gram + mask + degree (upper-triangle block tiles), fp32 exact.
// ---------------------------------------------------------------------------
__global__ __launch_bounds__(256, 2)
void gram_sym_kernel(const float* __restrict__ X,
                     unsigned char* __restrict__ mask,
                     float* __restrict__ deg,
                     const float* __restrict__ phi_p)
{
    __shared__ __align__(16) float As[2][16][132];
    __shared__ __align__(16) float Bs[2][16][132];

    int k = blockIdx.x;
    int bi = 0;
    while (k >= 64 - bi) { k -= 64 - bi; bi++; }
    const int bj = bi + k;
    const int bm = bi * 128;
    const int bn = bj * 128;

    const int tid = threadIdx.x;
    const int tx = tid & 15;
    const int ty = tid >> 4;
    const int ar  = tid >> 2;
    const int ac4 = (tid & 3) * 4;

    unsigned long long acc[8][4];
#pragma unroll
    for (int i = 0; i < 8; i++)
#pragma unroll
        for (int j = 0; j < 4; j++) acc[i][j] = 0ull;

    float4 a0v, a1v, b0v, b1v;

#define GRLOAD(k0)                                                            \
    do {                                                                      \
        const float* Ap = X + (size_t)(bm + ar) * H_ + (k0) + ac4;            \
        a0v = *(const float4*)Ap;                                             \
        a1v = *(const float4*)(Ap + (size_t)64 * H_);                         \
        const float* Bp = X + (size_t)(bn + ar) * H_ + (k0) + ac4;            \
        b0v = *(const float4*)Bp;                                             \
        b1v = *(const float4*)(Bp + (size_t)64 * H_);                         \
    } while (0)

#define GRSTORE(buf)                                                          \
    do {                                                                      \
        As[buf][ac4 + 0][ar] = a0v.x; As[buf][ac4 + 1][ar] = a0v.y;           \
        As[buf][ac4 + 2][ar] = a0v.z; As[buf][ac4 + 3][ar] = a0v.w;           \
        As[buf][ac4 + 0][ar + 64] = a1v.x; As[buf][ac4 + 1][ar + 64] = a1v.y; \
        As[buf][ac4 + 2][ar + 64] = a1v.z; As[buf][ac4 + 3][ar + 64] = a1v.w; \
        Bs[buf][ac4 + 0][ar] = b0v.x; Bs[buf][ac4 + 1][ar] = b0v.y;           \
        Bs[buf][ac4 + 2][ar] = b0v.z; Bs[buf][ac4 + 3][ar] = b0v.w;           \
        Bs[buf][ac4 + 0][ar + 64] = b1v.x; Bs[buf][ac4 + 1][ar + 64] = b1v.y; \
        Bs[buf][ac4 + 2][ar + 64] = b1v.z; Bs[buf][ac4 + 3][ar + 64] = b1v.w; \
    } while (0)

    GRLOAD(0);
    GRSTORE(0);
    __syncthreads();

    const int nk = H_ >> 4;
    for (int kt = 0; kt < nk; kt++) {
        const int cur = kt & 1;
        if (kt + 1 < nk) GRLOAD((kt + 1) * 16);
#pragma unroll
        for (int kk = 0; kk < 16; kk++) {
            float av[8];
            *(float4*)&av[0] = *(const float4*)&As[cur][kk][ty * 8];
            *(float4*)&av[4] = *(const float4*)&As[cur][kk][ty * 8 + 4];
            ulonglong2 bp0 = *(const ulonglong2*)&Bs[cur][kk][tx * 8];
            ulonglong2 bp1 = *(const ulonglong2*)&Bs[cur][kk][tx * 8 + 4];
#pragma unroll
            for (int i = 0; i < 8; i++) {
                unsigned long long ad = dup2(av[i]);
                fma2(acc[i][0], ad, bp0.x);
                fma2(acc[i][1], ad, bp0.y);
                fma2(acc[i][2], ad, bp1.x);
                fma2(acc[i][3], ad, bp1.y);
            }
        }
        if (kt + 1 < nk) GRSTORE((kt + 1) & 1);
        __syncthreads();
    }
#undef GRLOAD
#undef GRSTORE

    const float thr = phi_p[0] * 65536.0f;
    unsigned m[8][8];
    float colcnt[8];
#pragma unroll
    for (int j = 0; j < 8; j++) colcnt[j] = 0.f;

#pragma unroll
    for (int i = 0; i < 8; i++) {
        int row = bm + ty * 8 + i;
        float v[8];
#pragma unroll
        for (int j = 0; j < 4; j++) unpack2(acc[i][j], v[2 * j], v[2 * j + 1]);
        unsigned long long pack = 0ull;
        float rowcnt = 0.f;
#pragma unroll
        for (int j = 0; j < 8; j++) {
            int col = bn + tx * 8 + j;
            unsigned b = (v[j] >= thr || row == col) ? 1u : 0u;
            m[i][j] = b;
            pack |= (unsigned long long)b << (8 * j);
            rowcnt += (float)b;
            colcnt[j] += (float)b;
        }
        *(unsigned long long*)(mask + (size_t)row * NN_ + bn + tx * 8) = pack;
        atomicAdd(&deg[row], rowcnt);
    }

    if (bi != bj) {
#pragma unroll
        for (int j = 0; j < 8; j++) {
            int col = bn + tx * 8 + j;
            unsigned long long pack = 0ull;
#pragma unroll
            for (int i = 0; i < 8; i++)
                pack |= (unsigned long long)m[i][j] << (8 * i);
            *(unsigned long long*)(mask + (size_t)col * NN_ + bm + ty * 8) = pack;
            atomicAdd(&deg[col], colcnt[j]);
        }
    }
}

__global__ void dis_kernel(const float* __restrict__ deg, float* __restrict__ dis)
{
    int i = blockIdx.x * 256 + threadIdx.x;
    if (i < NN_) {
        float d = deg[i];
        dis[i] = d > 0.f ? rsqrtf(d) : 0.f;
    }
}

// ---------------------------------------------------------------------------
// Host orchestration
// ---------------------------------------------------------------------------
static void hgc_layer(const float* in, const float* W, const float* b,
                      const int* node_idx, const int* edge_idx,
                      float* xw, float* eb, float* agg,
                      const float* Dinv, const float* Binv, float* outbuf)
{
    sgemm_f2<false, false><<<dim3(H_ / 128, NN_ / 128), 256>>>(
        in, H_, W, H_, xw, H_, H_, nullptr);
    zero_kernel<<<(E_ * H_ / 4 + 255) / 256, 256>>>(eb, E_ * H_ / 4);
    scatter_edge_kernel<<<NNZ_ * 64 / 256, 256>>>(xw, node_idx, edge_idx, eb);
    zero_kernel<<<(NN_ * H_ / 4 + 255) / 256, 256>>>(agg, NN_ * H_ / 4);
    scatter_node_kernel<<<NNZ_ * 64 / 256, 256>>>(eb, node_idx, edge_idx, Binv, agg);
    hgc_finish_kernel<<<NN_ * H_ / 256, 256>>>(agg, Dinv, b, in, outbuf);
}

extern "C" void kernel_launch(void* const* d_in, const int* in_sizes, int n_in,
                              void* d_out, int out_size)
{
    (void)in_sizes; (void)n_in; (void)out_size;

    const float* x        = (const float*)d_in[0];
    const int*   hei      = (const int*)d_in[1];
    const int*   node_idx = hei;
    const int*   edge_idx = hei + NNZ_;
    const int*   slen     = (const int*)d_in[2];
    const float* h0       = (const float*)d_in[3];
    const float* W_ih     = (const float*)d_in[4];
    const float* W_hh     = (const float*)d_in[5];
    const float* b_ih     = (const float*)d_in[6];
    const float* b_hh     = (const float*)d_in[7];
    const float* w1 = (const float*)d_in[8];  const float* bb1 = (const float*)d_in[9];
    const float* w2 = (const float*)d_in[10]; const float* bb2 = (const float*)d_in[11];
    const float* w3 = (const float*)d_in[12]; const float* bb3 = (const float*)d_in[13];
    const float* phi = (const float*)d_in[14];
    const float* gw  = (const float*)d_in[15];
    const float* gb  = (const float*)d_in[16];
    float* out = (float*)d_out;

    float *xgall, *h, *h2, *fa, *fb, *xw, *eb, *agg, *x2;
    float *deg, *Dcnt, *Dinv, *Bcnt, *Binv, *dis;
    unsigned char* mask;
    __nv_bfloat16 *whh_h, *whh_l, *yth, *ytl;
    int *perm, *histb, *curb, *startb, *cntb;
    cudaGetSymbolAddress((void**)&xgall, g_xgall);
    cudaGetSymbolAddress((void**)&h,     g_h);
    cudaGetSymbolAddress((void**)&h2,    g_h2);
    cudaGetSymbolAddress((void**)&fa,    g_fa);
    cudaGetSymbolAddress((void**)&fb,    g_fb);
    cudaGetSymbolAddress((void**)&xw,    g_xw);
    cudaGetSymbolAddress((void**)&eb,    g_eb);
    cudaGetSymbolAddress((void**)&agg,   g_agg);
    cudaGetSymbolAddress((void**)&x2,    g_x2);
    cudaGetSymbolAddress((void**)&mask,  g_mask);
    cudaGetSymbolAddress((void**)&deg,   g_deg);
    cudaGetSymbolAddress((void**)&Dcnt,  g_Dcnt);
    cudaGetSymbolAddress((void**)&Dinv,  g_Dinv);
    cudaGetSymbolAddress((void**)&Bcnt,  g_Bcnt);
    cudaGetSymbolAddress((void**)&Binv,  g_Binv);
    cudaGetSymbolAddress((void**)&dis,   g_dis);
    cudaGetSymbolAddress((void**)&whh_h, g_whh_h);
    cudaGetSymbolAddress((void**)&whh_l, g_whh_l);
    cudaGetSymbolAddress((void**)&yth,   g_yth);
    cudaGetSymbolAddress((void**)&ytl,   g_ytl);
    cudaGetSymbolAddress((void**)&perm,  g_perm);
    cudaGetSymbolAddress((void**)&histb, g_hist);
    cudaGetSymbolAddress((void**)&curb,  g_cur);
    cudaGetSymbolAddress((void**)&startb,g_start);
    cudaGetSymbolAddress((void**)&cntb,  g_cnt);

    const int XG_SMEM  = 4 * 128 * XS_ * 2;                        // 90112 B
    const int GRU_SMEM = (2 * 64 * GS_ + 2 * 192 * GS_) * 2;        // 73728 B
    cudaFuncSetAttribute(xg_gemm_mma,
                         cudaFuncAttributeMaxDynamicSharedMemorySize, XG_SMEM);
    cudaFuncSetAttribute(gru_step_mma,
                         cudaFuncAttributeMaxDynamicSharedMemorySize, GRU_SMEM);

    // ---------------- sort rows by slen (descending) ----------------
    zero_int_kernel<<<1, 256>>>(histb, 32);
    zero_int_kernel<<<1, 256>>>(curb, 32);
    hist_kernel<<<NN_ / 256, 256>>>(slen, histb);
    scan_kernel<<<1, 32>>>(histb, cntb, startb);
    scatter_perm_kernel<<<NN_ / 256, 256>>>(slen, startb, curb, perm);

    // ---------------- GRU ----------------
    init_h_kernel<<<NN_ * H_ / 256, 256>>>(h, h0);
    split_w_kernel<<<(H3_ * H_ + 255) / 256, 256>>>(W_hh, whh_h, whh_l, H3_ * H_);

    xg_gemm_mma<<<dim3(H3_ / 128, T_ * NN_ / 128), 256, XG_SMEM>>>(
        x, W_ih, b_ih, perm, cntb, xgall);

    float* hrd = h;
    float* hwr = h2;
    for (int t = 0; t < T_; t++) {
        gru_step_mma<<<dim3(H_ / 64, NN_ / 64), 256, GRU_SMEM>>>(
            whh_h, whh_l, b_hh, xgall, hrd, hwr, perm, cntb, fa, t);
        float* tmp = hrd; hrd = hwr; hwr = tmp;
    }
    // fa now holds `last` [N,H] in ORIGINAL row order

    // ---------------- degrees (shared by 3 HGC layers) ----------------
    zero_kernel<<<(NN_ / 4 + 255) / 256, 256>>>(Dcnt, NN_ / 4);
    zero_kernel<<<(E_ / 4 + 255) / 256, 256>>>(Bcnt, E_ / 4);
    count_deg_kernel<<<NNZ_ / 256, 256>>>(node_idx, edge_idx, Dcnt, Bcnt);
    make_inv_kernel<<<(NN_ + 255) / 256, 256>>>(Dcnt, Dinv, NN_);
    make_inv_kernel<<<(E_ + 255) / 256, 256>>>(Bcnt, Binv, E_);

    // ---------------- 3 hypergraph conv layers with residuals ----------------
    hgc_layer(fa, w1, bb1, node_idx, edge_idx, xw, eb, agg, Dinv, Binv, fb); // o1
    hgc_layer(fb, w2, bb2, node_idx, edge_idx, xw, eb, agg, Dinv, Binv, fa); // o2
    hgc_layer(fa, w3, bb3, node_idx, edge_idx, xw, eb, agg, Dinv, Binv, fb); // o3

    // ---------------- final dense GCN ----------------
    sgemm_f2<false, false><<<dim3(GCN_ / 128, NN_ / 128), 256>>>(
        fb, H_, gw, GCN_, x2, GCN_, H_, nullptr);

    zero_kernel<<<(NN_ / 4 + 255) / 256, 256>>>(deg, NN_ / 4);
    gram_sym_kernel<<<64 * 65 / 2, 256>>>(fb, mask, deg, phi);
    dis_kernel<<<(NN_ + 255) / 256, 256>>>(deg, dis);
    yt_split_kernel<<<dim3(NN_ / 32, GCN_ / 32), dim3(32, 8)>>>(x2, dis, yth, ytl);
    gcn_gemm_mma<<<dim3(GCN_ / 64, NN_ / 128), 256>>>(mask, yth, ytl, dis, gb, out);
}

// round 8
// speedup vs baseline: 3.6842x; 1.2887x over previous
#include <cuda_runtime.h>
#include <cuda_bf16.h>
#include <cstdint>
#include <cstdio>

// Problem constants
#define NN_   8192
#define T_    32
#define IN_   256
#define H_    256
#define H3_   768
#define E_    1024
#define NNZ_  65536
#define GCN_  256

// ---------------------------------------------------------------------------
// Scratch (static device globals; no runtime allocation)
// ---------------------------------------------------------------------------
__device__ float g_xgall[(size_t)NN_ * T_ * H3_];   // [t][pos][768] t-major, sorted rows
__device__ float g_h [NN_ * H_];
__device__ float g_h2[NN_ * H_];
__device__ float g_fa[NN_ * H_];                    // feature ping (last / o2)
__device__ float g_fb[NN_ * H_];                    // feature pong (o1 / o3)
__device__ float g_xw[NN_ * H_];                    // HGC x@W
__device__ float g_eb[E_ * H_];                     // HGC edge accumulator
__device__ float g_x2[NN_ * GCN_];                  // o3 @ gcn_w
__device__ unsigned char g_mask[(size_t)NN_ * NN_]; // 64 MB adjacency mask bytes
__device__ float g_deg[NN_];
__device__ float g_Dinv[NN_];
__device__ float g_Binv[E_];
__device__ float g_dis[NN_];
// bf16 pre-split buffers
__device__ __nv_bfloat16 g_whh_h[H3_ * H_];
__device__ __nv_bfloat16 g_whh_l[H3_ * H_];
__device__ __nv_bfloat16 g_yth[(size_t)GCN_ * NN_];
__device__ __nv_bfloat16 g_ytl[(size_t)GCN_ * NN_];
__device__ __nv_bfloat16 g_wt_h[4 * H_ * H_];       // w1,w2,w3,gcn_w transposed+split
__device__ __nv_bfloat16 g_wt_l[4 * H_ * H_];
// sequence-length sort
__device__ int g_perm[NN_];
__device__ int g_hist[32];
__device__ int g_cur[32];
__device__ int g_start[32];
__device__ int g_cnt[T_ + 1];
// nnz segment sort (by edge, by node)
__device__ int g_ecnt[E_];
__device__ int g_ncnt[NN_];
__device__ int g_ecur[E_];
__device__ int g_ncur[NN_];
__device__ int g_eoff[E_ + 1];
__device__ int g_noff[NN_ + 1];
__device__ int g_eorder[NNZ_];
__device__ int g_norder[NNZ_];

// ---------------------------------------------------------------------------
// misc helpers
// ---------------------------------------------------------------------------
__device__ __forceinline__ float sigf(float x)
{
    return 1.f / (1.f + __expf(-x));
}

__device__ __forceinline__ void split8(const float* __restrict__ s, uint4& hi, uint4& lo)
{
    float4 v0 = *(const float4*)s;
    float4 v1 = *(const float4*)(s + 4);
    float vv[8] = {v0.x, v0.y, v0.z, v0.w, v1.x, v1.y, v1.z, v1.w};
    unsigned hw[4], lw[4];
#pragma unroll
    for (int p = 0; p < 4; p++) {
        __nv_bfloat16 h0 = __float2bfloat16(vv[2 * p]);
        __nv_bfloat16 h1 = __float2bfloat16(vv[2 * p + 1]);
        __nv_bfloat16 l0 = __float2bfloat16(vv[2 * p] - __bfloat162float(h0));
        __nv_bfloat16 l1 = __float2bfloat16(vv[2 * p + 1] - __bfloat162float(h1));
        __nv_bfloat162 hp = __halves2bfloat162(h0, h1);
        __nv_bfloat162 lp = __halves2bfloat162(l0, l1);
        hw[p] = *(unsigned*)&hp;
        lw[p] = *(unsigned*)&lp;
    }
    hi = make_uint4(hw[0], hw[1], hw[2], hw[3]);
    lo = make_uint4(lw[0], lw[1], lw[2], lw[3]);
}

__device__ __forceinline__ void mma_bf16(float* c, const uint32_t* a, const uint32_t* b)
{
    asm volatile(
        "mma.sync.aligned.m16n8k16.row.col.f32.bf16.bf16.f32 "
        "{%0,%1,%2,%3}, {%4,%5,%6,%7}, {%8,%9}, {%0,%1,%2,%3};"
        : "+f"(c[0]), "+f"(c[1]), "+f"(c[2]), "+f"(c[3])
        : "r"(a[0]), "r"(a[1]), "r"(a[2]), "r"(a[3]), "r"(b[0]), "r"(b[1]));
}

// ---------------------------------------------------------------------------
// One-time split kernels
// ---------------------------------------------------------------------------
__global__ void split_w_kernel(const float* __restrict__ W,
                               __nv_bfloat16* __restrict__ Wh,
                               __nv_bfloat16* __restrict__ Wl, int n)
{
    int i = blockIdx.x * 256 + threadIdx.x;
    if (i < n) {
        float v = W[i];
        __nv_bfloat16 h = __float2bfloat16(v);
        Wh[i] = h;
        Wl[i] = __float2bfloat16(v - __bfloat162float(h));
    }
}

// Transpose + split a [K=256][N=256] weight -> [n][k] bf16 hi/lo.
// grid (8,8), block (32,8).
__global__ void wt_split_kernel(const float* __restrict__ W,
                                __nv_bfloat16* __restrict__ Wth,
                                __nv_bfloat16* __restrict__ Wtl)
{
    __shared__ float tile[32][33];
    int kb = blockIdx.x * 32;
    int nb = blockIdx.y * 32;
    int tx = threadIdx.x, ty = threadIdx.y;
    for (int i = ty; i < 32; i += 8)
        tile[i][tx] = W[(size_t)(kb + i) * H_ + nb + tx];
    __syncthreads();
    for (int i = ty; i < 32; i += 8) {
        float v = tile[tx][i];
        __nv_bfloat16 h = __float2bfloat16(v);
        Wth[(size_t)(nb + i) * H_ + kb + tx] = h;
        Wtl[(size_t)(nb + i) * H_ + kb + tx] = __float2bfloat16(v - __bfloat162float(h));
    }
}

// Y^T build: Yt[n][k] = dis[k] * x2[k][n], split hi/lo bf16.
__global__ void yt_split_kernel(const float* __restrict__ x2,
                                const float* __restrict__ dis,
                                __nv_bfloat16* __restrict__ Yth,
                                __nv_bfloat16* __restrict__ Ytl)
{
    __shared__ float tile[32][33];
    int kb = blockIdx.x * 32;
    int nb = blockIdx.y * 32;
    int tx = threadIdx.x, ty = threadIdx.y;
    for (int i = ty; i < 32; i += 8)
        tile[i][tx] = x2[(size_t)(kb + i) * GCN_ + nb + tx] * dis[kb + i];
    __syncthreads();
    for (int i = ty; i < 32; i += 8) {
        float v = tile[tx][i];
        __nv_bfloat16 h = __float2bfloat16(v);
        Yth[(size_t)(nb + i) * NN_ + kb + tx] = h;
        Ytl[(size_t)(nb + i) * NN_ + kb + tx] = __float2bfloat16(v - __bfloat162float(h));
    }
}

// ---------------------------------------------------------------------------
// Tensor-core input-gate GEMM (round-6 proven).
// ---------------------------------------------------------------------------
#define XS_ 88
__global__ __launch_bounds__(256, 2)
void xg_gemm_mma(const float* __restrict__ x,
                 const float* __restrict__ Wih,
                 const float* __restrict__ bih,
                 const int* __restrict__ perm,
                 const int* __restrict__ cnt,
                 float* __restrict__ xgall)
{
    const int bm = blockIdx.y * 128;
    const int t = bm >> 13;
    const int pos0 = bm & (NN_ - 1);
    if (pos0 >= cnt[t]) return;
    const int bn = blockIdx.x * 128;

    extern __shared__ __align__(16) __nv_bfloat16 smx[];
    __nv_bfloat16* Ah = smx;
    __nv_bfloat16* Al = smx + 128 * XS_;
    __nv_bfloat16* Bh = smx + 2 * 128 * XS_;
    __nv_bfloat16* Bl = smx + 3 * 128 * XS_;

    const int tid = threadIdx.x;
    const int wid = tid >> 5;
    const int lane = tid & 31;
    const int wm = (wid & 3) * 32;
    const int wn = (wid >> 2) * 64;
    const int grp = lane >> 2;
    const int tig = lane & 3;

    float acc[2][8][4];
#pragma unroll
    for (int mt = 0; mt < 2; mt++)
#pragma unroll
        for (int nt = 0; nt < 8; nt++)
#pragma unroll
            for (int e = 0; e < 4; e++) acc[mt][nt][e] = 0.f;

    for (int kc = 0; kc < 4; kc++) {
#pragma unroll
        for (int i = 0; i < 8; i++) {
            int u = i * 256 + tid;
            int r = u >> 3;
            int cg = u & 7;
            const float* src;
            __nv_bfloat16 *dh, *dl;
            int lr;
            if (r < 128) {
                src = x + (size_t)perm[pos0 + r] * (T_ * IN_) + t * IN_ + kc * 64 + cg * 8;
                dh = Ah; dl = Al; lr = r;
            } else {
                lr = r - 128;
                src = Wih + (size_t)(bn + lr) * IN_ + kc * 64 + cg * 8;
                dh = Bh; dl = Bl;
            }
            uint4 hi, lo;
            split8(src, hi, lo);
            *(uint4*)(dh + lr * XS_ + cg * 8) = hi;
            *(uint4*)(dl + lr * XS_ + cg * 8) = lo;
        }
        __syncthreads();

#pragma unroll
        for (int ks = 0; ks < 4; ks++) {
            const int kk = ks * 16;
            uint32_t ah[2][4], al[2][4];
#pragma unroll
            for (int mt = 0; mt < 2; mt++) {
                int r0 = wm + mt * 16 + grp;
                ah[mt][0] = *(const uint32_t*)(Ah + (size_t)r0 * XS_ + kk + tig * 2);
                ah[mt][1] = *(const uint32_t*)(Ah + (size_t)(r0 + 8) * XS_ + kk + tig * 2);
                ah[mt][2] = *(const uint32_t*)(Ah + (size_t)r0 * XS_ + kk + 8 + tig * 2);
                ah[mt][3] = *(const uint32_t*)(Ah + (size_t)(r0 + 8) * XS_ + kk + 8 + tig * 2);
                al[mt][0] = *(const uint32_t*)(Al + (size_t)r0 * XS_ + kk + tig * 2);
                al[mt][1] = *(const uint32_t*)(Al + (size_t)(r0 + 8) * XS_ + kk + tig * 2);
                al[mt][2] = *(const uint32_t*)(Al + (size_t)r0 * XS_ + kk + 8 + tig * 2);
                al[mt][3] = *(const uint32_t*)(Al + (size_t)(r0 + 8) * XS_ + kk + 8 + tig * 2);
            }
#pragma unroll
            for (int nt = 0; nt < 8; nt++) {
                int nr = wn + nt * 8 + grp;
                uint32_t bh[2], bl[2];
                bh[0] = *(const uint32_t*)(Bh + (size_t)nr * XS_ + kk + tig * 2);
                bh[1] = *(const uint32_t*)(Bh + (size_t)nr * XS_ + kk + 8 + tig * 2);
                bl[0] = *(const uint32_t*)(Bl + (size_t)nr * XS_ + kk + tig * 2);
                bl[1] = *(const uint32_t*)(Bl + (size_t)nr * XS_ + kk + 8 + tig * 2);
#pragma unroll
                for (int mt = 0; mt < 2; mt++) {
                    mma_bf16(acc[mt][nt], ah[mt], bh);
                    mma_bf16(acc[mt][nt], ah[mt], bl);
                    mma_bf16(acc[mt][nt], al[mt], bh);
                }
            }
        }
        __syncthreads();
    }

#pragma unroll
    for (int mt = 0; mt < 2; mt++) {
#pragma unroll
        for (int nt = 0; nt < 8; nt++) {
            int row0 = bm + wm + mt * 16 + grp;
            int col = bn + wn + nt * 8 + tig * 2;
            float2 bv = *(const float2*)(bih + col);
            float2 o0 = make_float2(acc[mt][nt][0] + bv.x, acc[mt][nt][1] + bv.y);
            float2 o1 = make_float2(acc[mt][nt][2] + bv.x, acc[mt][nt][3] + bv.y);
            *(float2*)(xgall + (size_t)row0 * H3_ + col) = o0;
            *(float2*)(xgall + (size_t)(row0 + 8) * H3_ + col) = o1;
        }
    }
}

// ---------------------------------------------------------------------------
// Fused GRU step (round-7 proven).
// ---------------------------------------------------------------------------
#define GS_ 72
__global__ __launch_bounds__(256)
void gru_step_mma(const __nv_bfloat16* __restrict__ Whh_h,
                  const __nv_bfloat16* __restrict__ Whh_l,
                  const float* __restrict__ bhh,
                  const float* __restrict__ xgall,
                  const float* __restrict__ hin,
                  float* __restrict__ hout,
                  const int* __restrict__ perm,
                  const int* __restrict__ cnt,
                  float* __restrict__ last, int t)
{
    const int bm = blockIdx.y * 64;
    const int c0 = cnt[t];
    if (bm >= c0) return;
    const int c1 = cnt[t + 1];
    const int bn = blockIdx.x * 64;

    extern __shared__ __align__(16) __nv_bfloat16 smg[];
    __nv_bfloat16* Ah = smg;
    __nv_bfloat16* Al = smg + 64 * GS_;
    __nv_bfloat16* Bh = smg + 2 * 64 * GS_;
    __nv_bfloat16* Bl = smg + 2 * 64 * GS_ + 192 * GS_;

    const int tid = threadIdx.x;
    const int wid = tid >> 5;
    const int lane = tid & 31;
    const int wm = (wid & 1) * 32;
    const int wn16 = (wid >> 1) * 16;
    const int grp = lane >> 2;
    const int tig = lane & 3;

    float acc[2][3][2][4];
#pragma unroll
    for (int mt = 0; mt < 2; mt++)
#pragma unroll
        for (int g = 0; g < 3; g++)
#pragma unroll
            for (int nt = 0; nt < 2; nt++)
#pragma unroll
                for (int e = 0; e < 4; e++) acc[mt][g][nt][e] = 0.f;

    for (int kc = 0; kc < 4; kc++) {
#pragma unroll
        for (int i = 0; i < 2; i++) {
            int u = i * 256 + tid;
            int r = u >> 3;
            int cg = u & 7;
            uint4 hi, lo;
            split8(hin + (size_t)(bm + r) * H_ + kc * 64 + cg * 8, hi, lo);
            *(uint4*)(Ah + r * GS_ + cg * 8) = hi;
            *(uint4*)(Al + r * GS_ + cg * 8) = lo;
        }
#pragma unroll
        for (int i = 0; i < 6; i++) {
            int u = i * 256 + tid;
            int r = u >> 3;
            int cg = u & 7;
            int g = r >> 6;
            int br = r & 63;
            size_t goff = (size_t)(g * 256 + bn + br) * H_ + kc * 64 + cg * 8;
            *(uint4*)(Bh + r * GS_ + cg * 8) = *(const uint4*)(Whh_h + goff);
            *(uint4*)(Bl + r * GS_ + cg * 8) = *(const uint4*)(Whh_l + goff);
        }
        __syncthreads();

#pragma unroll
        for (int ks = 0; ks < 4; ks++) {
            const int kk = ks * 16;
            uint32_t ah[2][4], al[2][4];
#pragma unroll
            for (int mt = 0; mt < 2; mt++) {
                int r0 = wm + mt * 16 + grp;
                ah[mt][0] = *(const uint32_t*)(Ah + (size_t)r0 * GS_ + kk + tig * 2);
                ah[mt][1] = *(const uint32_t*)(Ah + (size_t)(r0 + 8) * GS_ + kk + tig * 2);
                ah[mt][2] = *(const uint32_t*)(Ah + (size_t)r0 * GS_ + kk + 8 + tig * 2);
                ah[mt][3] = *(const uint32_t*)(Ah + (size_t)(r0 + 8) * GS_ + kk + 8 + tig * 2);
                al[mt][0] = *(const uint32_t*)(Al + (size_t)r0 * GS_ + kk + tig * 2);
                al[mt][1] = *(const uint32_t*)(Al + (size_t)(r0 + 8) * GS_ + kk + tig * 2);
                al[mt][2] = *(const uint32_t*)(Al + (size_t)r0 * GS_ + kk + 8 + tig * 2);
                al[mt][3] = *(const uint32_t*)(Al + (size_t)(r0 + 8) * GS_ + kk + 8 + tig * 2);
            }
#pragma unroll
            for (int g = 0; g < 3; g++) {
#pragma unroll
                for (int nt = 0; nt < 2; nt++) {
                    int nr = g * 64 + wn16 + nt * 8 + grp;
                    uint32_t bh[2], bl[2];
                    bh[0] = *(const uint32_t*)(Bh + (size_t)nr * GS_ + kk + tig * 2);
                    bh[1] = *(const uint32_t*)(Bh + (size_t)nr * GS_ + kk + 8 + tig * 2);
                    bl[0] = *(const uint32_t*)(Bl + (size_t)nr * GS_ + kk + tig * 2);
                    bl[1] = *(const uint32_t*)(Bl + (size_t)nr * GS_ + kk + 8 + tig * 2);
#pragma unroll
                    for (int mt = 0; mt < 2; mt++) {
                        mma_bf16(acc[mt][g][nt], ah[mt], bh);
                        mma_bf16(acc[mt][g][nt], ah[mt], bl);
                        mma_bf16(acc[mt][g][nt], al[mt], bh);
                    }
                }
            }
        }
        __syncthreads();
    }

#pragma unroll
    for (int mt = 0; mt < 2; mt++) {
        int rbase = bm + wm + mt * 16 + grp;
#pragma unroll
        for (int half = 0; half < 2; half++) {
            int row = rbase + half * 8;
            bool isLast = (row >= c1 && row < c0);
            int pr = isLast ? perm[row] : 0;
            size_t xb = ((size_t)t * NN_ + row) * H3_;
            size_t hb = (size_t)row * H_;
#pragma unroll
            for (int nt = 0; nt < 2; nt++) {
                int col = bn + wn16 + nt * 8 + tig * 2;
                float2 xr = *(const float2*)(xgall + xb + col);
                float2 xz = *(const float2*)(xgall + xb + 256 + col);
                float2 xq = *(const float2*)(xgall + xb + 512 + col);
                float2 ho = *(const float2*)(hin + hb + col);
                float2 br = *(const float2*)(bhh + col);
                float2 bz = *(const float2*)(bhh + 256 + col);
                float2 bq = *(const float2*)(bhh + 512 + col);
                float hr0 = acc[mt][0][nt][half * 2 + 0];
                float hr1 = acc[mt][0][nt][half * 2 + 1];
                float hz0 = acc[mt][1][nt][half * 2 + 0];
                float hz1 = acc[mt][1][nt][half * 2 + 1];
                float hq0 = acc[mt][2][nt][half * 2 + 0];
                float hq1 = acc[mt][2][nt][half * 2 + 1];
                float r0 = sigf(xr.x + hr0 + br.x);
                float z0 = sigf(xz.x + hz0 + bz.x);
                float q0 = tanhf(xq.x + r0 * (hq0 + bq.x));
                float r1 = sigf(xr.y + hr1 + br.y);
                float z1 = sigf(xz.y + hz1 + bz.y);
                float q1 = tanhf(xq.y + r1 * (hq1 + bq.y));
                float2 hn = make_float2((1.f - z0) * q0 + z0 * ho.x,
                                        (1.f - z1) * q1 + z1 * ho.y);
                *(float2*)(hout + hb + col) = hn;
                if (isLast)
                    *(float2*)(last + (size_t)pr * H_ + col) = hn;
            }
        }
    }
}

// ---------------------------------------------------------------------------
// HMMA NT GEMM: C[M,256] = A[M,256] (fp32, split on fly) @ Wt (pre-split [n][k]).
// Tile 128x128, grid (2, M/128).
// ---------------------------------------------------------------------------
__global__ __launch_bounds__(256, 2)
void sgemm_nt_mma(const float* __restrict__ A,
                  const __nv_bfloat16* __restrict__ Wth,
                  const __nv_bfloat16* __restrict__ Wtl,
                  float* __restrict__ C)
{
    const int bm = blockIdx.y * 128;
    const int bn = blockIdx.x * 128;

    extern __shared__ __align__(16) __nv_bfloat16 smn[];
    __nv_bfloat16* Ah = smn;
    __nv_bfloat16* Al = smn + 128 * XS_;
    __nv_bfloat16* Bh = smn + 2 * 128 * XS_;
    __nv_bfloat16* Bl = smn + 3 * 128 * XS_;

    const int tid = threadIdx.x;
    const int wid = tid >> 5;
    const int lane = tid & 31;
    const int wm = (wid & 3) * 32;
    const int wn = (wid >> 2) * 64;
    const int grp = lane >> 2;
    const int tig = lane & 3;

    float acc[2][8][4];
#pragma unroll
    for (int mt = 0; mt < 2; mt++)
#pragma unroll
        for (int nt = 0; nt < 8; nt++)
#pragma unroll
            for (int e = 0; e < 4; e++) acc[mt][nt][e] = 0.f;

    for (int kc = 0; kc < 4; kc++) {
#pragma unroll
        for (int i = 0; i < 4; i++) {
            int u = i * 256 + tid;
            int r = u >> 3;
            int cg = u & 7;
            uint4 hi, lo;
            split8(A + (size_t)(bm + r) * H_ + kc * 64 + cg * 8, hi, lo);
            *(uint4*)(Ah + r * XS_ + cg * 8) = hi;
            *(uint4*)(Al + r * XS_ + cg * 8) = lo;
        }
#pragma unroll
        for (int i = 0; i < 4; i++) {
            int u = i * 256 + tid;
            int r = u >> 3;
            int cg = u & 7;
            size_t goff = (size_t)(bn + r) * H_ + kc * 64 + cg * 8;
            *(uint4*)(Bh + r * XS_ + cg * 8) = *(const uint4*)(Wth + goff);
            *(uint4*)(Bl + r * XS_ + cg * 8) = *(const uint4*)(Wtl + goff);
        }
        __syncthreads();

#pragma unroll
        for (int ks = 0; ks < 4; ks++) {
            const int kk = ks * 16;
            uint32_t ah[2][4], al[2][4];
#pragma unroll
            for (int mt = 0; mt < 2; mt++) {
                int r0 = wm + mt * 16 + grp;
                ah[mt][0] = *(const uint32_t*)(Ah + (size_t)r0 * XS_ + kk + tig * 2);
                ah[mt][1] = *(const uint32_t*)(Ah + (size_t)(r0 + 8) * XS_ + kk + tig * 2);
                ah[mt][2] = *(const uint32_t*)(Ah + (size_t)r0 * XS_ + kk + 8 + tig * 2);
                ah[mt][3] = *(const uint32_t*)(Ah + (size_t)(r0 + 8) * XS_ + kk + 8 + tig * 2);
                al[mt][0] = *(const uint32_t*)(Al + (size_t)r0 * XS_ + kk + tig * 2);
                al[mt][1] = *(const uint32_t*)(Al + (size_t)(r0 + 8) * XS_ + kk + tig * 2);
                al[mt][2] = *(const uint32_t*)(Al + (size_t)r0 * XS_ + kk + 8 + tig * 2);
                al[mt][3] = *(const uint32_t*)(Al + (size_t)(r0 + 8) * XS_ + kk + 8 + tig * 2);
            }
#pragma unroll
            for (int nt = 0; nt < 8; nt++) {
                int nr = wn + nt * 8 + grp;
                uint32_t bh[2], bl[2];
                bh[0] = *(const uint32_t*)(Bh + (size_t)nr * XS_ + kk + tig * 2);
                bh[1] = *(const uint32_t*)(Bh + (size_t)nr * XS_ + kk + 8 + tig * 2);
                bl[0] = *(const uint32_t*)(Bl + (size_t)nr * XS_ + kk + tig * 2);
                bl[1] = *(const uint32_t*)(Bl + (size_t)nr * XS_ + kk + 8 + tig * 2);
#pragma unroll
                for (int mt = 0; mt < 2; mt++) {
                    mma_bf16(acc[mt][nt], ah[mt], bh);
                    mma_bf16(acc[mt][nt], ah[mt], bl);
                    mma_bf16(acc[mt][nt], al[mt], bh);
                }
            }
        }
        __syncthreads();
    }

#pragma unroll
    for (int mt = 0; mt < 2; mt++) {
#pragma unroll
        for (int nt = 0; nt < 8; nt++) {
            int row0 = bm + wm + mt * 16 + grp;
            int col = bn + wn + nt * 8 + tig * 2;
            *(float2*)(C + (size_t)row0 * H_ + col) =
                make_float2(acc[mt][nt][0], acc[mt][nt][1]);
            *(float2*)(C + (size_t)(row0 + 8) * H_ + col) =
                make_float2(acc[mt][nt][2], acc[mt][nt][3]);
        }
    }
}

// ---------------------------------------------------------------------------
// Gram -> mask + deg, bf16x3 HMMA, upper-triangle blocks.
// ---------------------------------------------------------------------------
__global__ __launch_bounds__(256)
void gram_mma(const float* __restrict__ X,
              unsigned char* __restrict__ mask,
              float* __restrict__ deg,
              const float* __restrict__ phi_p)
{
    int k = blockIdx.x;
    int bi = 0;
    while (k >= 64 - bi) { k -= 64 - bi; bi++; }
    const int bj = bi + k;
    const int bm = bi * 128;
    const int bn = bj * 128;

    extern __shared__ __align__(16) __nv_bfloat16 smr[];
    __nv_bfloat16* Ah = smr;
    __nv_bfloat16* Al = smr + 128 * XS_;
    __nv_bfloat16* Bh = smr + 2 * 128 * XS_;
    __nv_bfloat16* Bl = smr + 3 * 128 * XS_;

    const int tid = threadIdx.x;
    const int wid = tid >> 5;
    const int lane = tid & 31;
    const int wm = (wid & 3) * 32;
    const int wn = (wid >> 2) * 64;
    const int grp = lane >> 2;
    const int tig = lane & 3;

    float acc[2][8][4];
#pragma unroll
    for (int mt = 0; mt < 2; mt++)
#pragma unroll
        for (int nt = 0; nt < 8; nt++)
#pragma unroll
            for (int e = 0; e < 4; e++) acc[mt][nt][e] = 0.f;

    for (int kc = 0; kc < 4; kc++) {
#pragma unroll
        for (int i = 0; i < 8; i++) {
            int u = i * 256 + tid;
            int r = u >> 3;
            int cg = u & 7;
            int grow = (r < 128) ? (bm + r) : (bn + r - 128);
            int lr = r & 127;
            __nv_bfloat16* dh = (r < 128) ? Ah : Bh;
            __nv_bfloat16* dl = (r < 128) ? Al : Bl;
            uint4 hi, lo;
            split8(X + (size_t)grow * H_ + kc * 64 + cg * 8, hi, lo);
            *(uint4*)(dh + lr * XS_ + cg * 8) = hi;
            *(uint4*)(dl + lr * XS_ + cg * 8) = lo;
        }
        __syncthreads();

#pragma unroll
        for (int ks = 0; ks < 4; ks++) {
            const int kk = ks * 16;
            uint32_t ah[2][4], al[2][4];
#pragma unroll
            for (int mt = 0; mt < 2; mt++) {
                int r0 = wm + mt * 16 + grp;
                ah[mt][0] = *(const uint32_t*)(Ah + (size_t)r0 * XS_ + kk + tig * 2);
                ah[mt][1] = *(const uint32_t*)(Ah + (size_t)(r0 + 8) * XS_ + kk + tig * 2);
                ah[mt][2] = *(const uint32_t*)(Ah + (size_t)r0 * XS_ + kk + 8 + tig * 2);
                ah[mt][3] = *(const uint32_t*)(Ah + (size_t)(r0 + 8) * XS_ + kk + 8 + tig * 2);
                al[mt][0] = *(const uint32_t*)(Al + (size_t)r0 * XS_ + kk + tig * 2);
                al[mt][1] = *(const uint32_t*)(Al + (size_t)(r0 + 8) * XS_ + kk + tig * 2);
                al[mt][2] = *(const uint32_t*)(Al + (size_t)r0 * XS_ + kk + 8 + tig * 2);
                al[mt][3] = *(const uint32_t*)(Al + (size_t)(r0 + 8) * XS_ + kk + 8 + tig * 2);
            }
#pragma unroll
            for (int nt = 0; nt < 8; nt++) {
                int nr = wn + nt * 8 + grp;
                uint32_t bh[2], bl[2];
                bh[0] = *(const uint32_t*)(Bh + (size_t)nr * XS_ + kk + tig * 2);
                bh[1] = *(const uint32_t*)(Bh + (size_t)nr * XS_ + kk + 8 + tig * 2);
                bl[0] = *(const uint32_t*)(Bl + (size_t)nr * XS_ + kk + tig * 2);
                bl[1] = *(const uint32_t*)(Bl + (size_t)nr * XS_ + kk + 8 + tig * 2);
#pragma unroll
                for (int mt = 0; mt < 2; mt++) {
                    mma_bf16(acc[mt][nt], ah[mt], bh);
                    mma_bf16(acc[mt][nt], ah[mt], bl);
                    mma_bf16(acc[mt][nt], al[mt], bh);
                }
            }
        }
        __syncthreads();
    }

    const float thr = phi_p[0] * 65536.0f;
    float cnt_r[2][2] = {{0.f, 0.f}, {0.f, 0.f}};
    float cnt_c[8][2];
#pragma unroll
    for (int nt = 0; nt < 8; nt++) { cnt_c[nt][0] = 0.f; cnt_c[nt][1] = 0.f; }
    unsigned bits[2][8];

#pragma unroll
    for (int mt = 0; mt < 2; mt++) {
        int r0 = bm + wm + mt * 16 + grp;
#pragma unroll
        for (int nt = 0; nt < 8; nt++) {
            int c0 = bn + wn + nt * 8 + tig * 2;
            unsigned b00 = (acc[mt][nt][0] >= thr || r0 == c0) ? 1u : 0u;
            unsigned b01 = (acc[mt][nt][1] >= thr || r0 == c0 + 1) ? 1u : 0u;
            unsigned b10 = (acc[mt][nt][2] >= thr || r0 + 8 == c0) ? 1u : 0u;
            unsigned b11 = (acc[mt][nt][3] >= thr || r0 + 8 == c0 + 1) ? 1u : 0u;
            *(unsigned short*)(mask + (size_t)r0 * NN_ + c0) =
                (unsigned short)(b00 | (b01 << 8));
            *(unsigned short*)(mask + (size_t)(r0 + 8) * NN_ + c0) =
                (unsigned short)(b10 | (b11 << 8));
            cnt_r[mt][0] += (float)(b00 + b01);
            cnt_r[mt][1] += (float)(b10 + b11);
            cnt_c[nt][0] += (float)(b00 + b10);
            cnt_c[nt][1] += (float)(b01 + b11);
            bits[mt][nt] = b00 | (b01 << 1) | (b10 << 2) | (b11 << 3);
        }
    }

    // row degree atomics (reduce across tig lanes)
#pragma unroll
    for (int mt = 0; mt < 2; mt++)
#pragma unroll
        for (int half = 0; half < 2; half++) {
            float v = cnt_r[mt][half];
            v += __shfl_xor_sync(0xffffffffu, v, 1);
            v += __shfl_xor_sync(0xffffffffu, v, 2);
            if (tig == 0)
                atomicAdd(&deg[bm + wm + mt * 16 + grp + half * 8], v);
        }

    if (bi != bj) {
        // col degree atomics (reduce across grp lanes)
#pragma unroll
        for (int nt = 0; nt < 8; nt++)
#pragma unroll
            for (int cb = 0; cb < 2; cb++) {
                float v = cnt_c[nt][cb];
                v += __shfl_xor_sync(0xffffffffu, v, 4);
                v += __shfl_xor_sync(0xffffffffu, v, 8);
                v += __shfl_xor_sync(0xffffffffu, v, 16);
                if (grp == 0)
                    atomicAdd(&deg[bn + wn + nt * 8 + tig * 2 + cb], v);
            }
        // transposed mask writes
#pragma unroll
        for (int nt = 0; nt < 8; nt++) {
            int c0 = bn + wn + nt * 8 + tig * 2;
#pragma unroll
            for (int cb = 0; cb < 2; cb++) {
                int col = c0 + cb;
#pragma unroll
                for (int mt = 0; mt < 2; mt++) {
                    int r0 = bm + wm + mt * 16 + grp;
                    mask[(size_t)col * NN_ + r0] =
                        (unsigned char)((bits[mt][nt] >> cb) & 1u);
                    mask[(size_t)col * NN_ + r0 + 8] =
                        (unsigned char)((bits[mt][nt] >> (2 + cb)) & 1u);
                }
            }
        }
    }
}

// ---------------------------------------------------------------------------
// Masked GCN GEMM (round-7 proven)
// ---------------------------------------------------------------------------
#define CS_ 72
__global__ __launch_bounds__(256, 2)
void gcn_gemm_mma(const unsigned char* __restrict__ mask,
                  const __nv_bfloat16* __restrict__ Yth,
                  const __nv_bfloat16* __restrict__ Ytl,
                  const float* __restrict__ dis,
                  const float* __restrict__ bias,
                  float* __restrict__ out)
{
    __shared__ __align__(16) __nv_bfloat16 Am[128 * CS_];
    __shared__ __align__(16) __nv_bfloat16 Bh[64 * CS_];
    __shared__ __align__(16) __nv_bfloat16 Bl[64 * CS_];

    const int bm = blockIdx.y * 128;
    const int bn = blockIdx.x * 64;
    const int tid = threadIdx.x;
    const int wid = tid >> 5;
    const int lane = tid & 31;
    const int wm = (wid & 3) * 32;
    const int wn = (wid >> 2) * 32;
    const int grp = lane >> 2;
    const int tig = lane & 3;

    float acc[2][4][4];
#pragma unroll
    for (int mt = 0; mt < 2; mt++)
#pragma unroll
        for (int nt = 0; nt < 4; nt++)
#pragma unroll
            for (int e = 0; e < 4; e++) acc[mt][nt][e] = 0.f;

    for (int kc = 0; kc < NN_ / 64; kc++) {
#pragma unroll
        for (int i = 0; i < 4; i++) {
            int u = i * 256 + tid;
            int r = u >> 3;
            int cg = u & 7;
            unsigned long long mb = *(const unsigned long long*)(
                mask + (size_t)(bm + r) * NN_ + kc * 64 + cg * 8);
            unsigned w[4];
#pragma unroll
            for (int p = 0; p < 4; p++) {
                unsigned lo16 = ((mb >> (16 * p)) & 0xFFull) ? 0x3F80u : 0u;
                unsigned hi16 = ((mb >> (16 * p + 8)) & 0xFFull) ? 0x3F80u : 0u;
                w[p] = lo16 | (hi16 << 16);
            }
            *(uint4*)(Am + r * CS_ + cg * 8) = make_uint4(w[0], w[1], w[2], w[3]);
        }
#pragma unroll
        for (int i = 0; i < 2; i++) {
            int u = i * 256 + tid;
            int r = u >> 3;
            int cg = u & 7;
            size_t goff = (size_t)(bn + r) * NN_ + kc * 64 + cg * 8;
            *(uint4*)(Bh + r * CS_ + cg * 8) = *(const uint4*)(Yth + goff);
            *(uint4*)(Bl + r * CS_ + cg * 8) = *(const uint4*)(Ytl + goff);
        }
        __syncthreads();

#pragma unroll
        for (int ks = 0; ks < 4; ks++) {
            const int kk = ks * 16;
            uint32_t am[2][4];
#pragma unroll
            for (int mt = 0; mt < 2; mt++) {
                int r0 = wm + mt * 16 + grp;
                am[mt][0] = *(const uint32_t*)(Am + (size_t)r0 * CS_ + kk + tig * 2);
                am[mt][1] = *(const uint32_t*)(Am + (size_t)(r0 + 8) * CS_ + kk + tig * 2);
                am[mt][2] = *(const uint32_t*)(Am + (size_t)r0 * CS_ + kk + 8 + tig * 2);
                am[mt][3] = *(const uint32_t*)(Am + (size_t)(r0 + 8) * CS_ + kk + 8 + tig * 2);
            }
#pragma unroll
            for (int nt = 0; nt < 4; nt++) {
                int nr = wn + nt * 8 + grp;
                uint32_t bh[2], bl[2];
                bh[0] = *(const uint32_t*)(Bh + (size_t)nr * CS_ + kk + tig * 2);
                bh[1] = *(const uint32_t*)(Bh + (size_t)nr * CS_ + kk + 8 + tig * 2);
                bl[0] = *(const uint32_t*)(Bl + (size_t)nr * CS_ + kk + tig * 2);
                bl[1] = *(const uint32_t*)(Bl + (size_t)nr * CS_ + kk + 8 + tig * 2);
#pragma unroll
                for (int mt = 0; mt < 2; mt++) {
                    mma_bf16(acc[mt][nt], am[mt], bh);
                    mma_bf16(acc[mt][nt], am[mt], bl);
                }
            }
        }
        __syncthreads();
    }

#pragma unroll
    for (int mt = 0; mt < 2; mt++) {
#pragma unroll
        for (int nt = 0; nt < 4; nt++) {
            int row0 = bm + wm + mt * 16 + grp;
            int col = bn + wn + nt * 8 + tig * 2;
            float2 bv = *(const float2*)(bias + col);
            float d0 = dis[row0];
            float d1 = dis[row0 + 8];
            float2 o0 = make_float2(d0 * acc[mt][nt][0] + bv.x,
                                    d0 * acc[mt][nt][1] + bv.y);
            float2 o1 = make_float2(d1 * acc[mt][nt][2] + bv.x,
                                    d1 * acc[mt][nt][3] + bv.y);
            *(float2*)(out + (size_t)row0 * GCN_ + col) = o0;
            *(float2*)(out + (size_t)(row0 + 8) * GCN_ + col) = o1;
        }
    }
}

// ---------------------------------------------------------------------------
// Sorting: rows by slen; nnz by edge and by node
// ---------------------------------------------------------------------------
__global__ void zero_int_kernel(int* __restrict__ p, int n)
{
    int i = blockIdx.x * 256 + threadIdx.x;
    if (i < n) p[i] = 0;
}

__global__ void hist_kernel(const int* __restrict__ slen, int* __restrict__ hist)
{
    int i = blockIdx.x * 256 + threadIdx.x;
    if (i < NN_) atomicAdd(&hist[slen[i] - 1], 1);
}

__global__ void scan_kernel(const int* __restrict__ hist,
                            int* __restrict__ cnt, int* __restrict__ start)
{
    if (threadIdx.x == 0) {
        int run = 0;
        cnt[T_] = 0;
        for (int s = T_ - 1; s >= 0; s--) {
            start[s] = run;
            run += hist[s];
            cnt[s] = run;
        }
    }
}

__global__ void scatter_perm_kernel(const int* __restrict__ slen,
                                    const int* __restrict__ start,
                                    int* __restrict__ cur,
                                    int* __restrict__ perm)
{
    int i = blockIdx.x * 256 + threadIdx.x;
    if (i < NN_) {
        int s = slen[i] - 1;
        int pos = start[s] + atomicAdd(&cur[s], 1);
        perm[pos] = i;
    }
}

__global__ void hist_nz_kernel(const int* __restrict__ node_idx,
                               const int* __restrict__ edge_idx,
                               int* __restrict__ ncnt, int* __restrict__ ecnt)
{
    int i = blockIdx.x * 256 + threadIdx.x;
    if (i < NNZ_) {
        atomicAdd(&ncnt[node_idx[i]], 1);
        atomicAdd(&ecnt[edge_idx[i]], 1);
    }
}

// Exclusive scan over n bins (n divisible by 1024), single block of 1024.
__global__ void scan_bins_kernel(const int* __restrict__ cnt,
                                 int* __restrict__ off, int n)
{
    __shared__ int part[1024];
    int tid = threadIdx.x;
    int per = n / 1024;
    int base = tid * per;
    int s = 0;
    for (int i = 0; i < per; i++) s += cnt[base + i];
    part[tid] = s;
    __syncthreads();
    for (int d = 1; d < 1024; d <<= 1) {
        int v = (tid >= d) ? part[tid - d] : 0;
        __syncthreads();
        part[tid] += v;
        __syncthreads();
    }
    int run = part[tid] - s;
    for (int i = 0; i < per; i++) {
        off[base + i] = run;
        run += cnt[base + i];
    }
    if (tid == 1023) off[n] = run;
}

__global__ void scatter_order_kernel(const int* __restrict__ idx,
                                     const int* __restrict__ off,
                                     int* __restrict__ cur,
                                     int* __restrict__ order)
{
    int i = blockIdx.x * 256 + threadIdx.x;
    if (i < NNZ_) {
        int b = idx[i];
        int pos = off[b] + atomicAdd(&cur[b], 1);
        order[pos] = i;
    }
}

__global__ void inv_int_kernel(const int* __restrict__ cnt,
                               float* __restrict__ inv, int n)
{
    int i = blockIdx.x * 256 + threadIdx.x;
    if (i < n) {
        int c = cnt[i];
        inv[i] = c > 0 ? 1.f / (float)c : 0.f;
    }
}

__global__ void init_h_kernel(float* __restrict__ h, const float* __restrict__ h0)
{
    int idx = blockIdx.x * 256 + threadIdx.x;
    h[idx] = h0[idx & (H_ - 1)];
}

__global__ void zero_kernel(float* __restrict__ p, int n4)
{
    int i = blockIdx.x * 256 + threadIdx.x;
    if (i < n4) ((float4*)p)[i] = make_float4(0.f, 0.f, 0.f, 0.f);
}

// ---------------------------------------------------------------------------
// HGC segment sums (atomic-free): block per edge; warp per node (fused finish)
// ---------------------------------------------------------------------------
__global__ void edge_sum_kernel(const float* __restrict__ xw,
                                const int* __restrict__ node_idx,
                                const int* __restrict__ eorder,
                                const int* __restrict__ eoff,
                                const float* __restrict__ Binv,
                                float* __restrict__ eb)
{
    int e = blockIdx.x;
    int c = threadIdx.x;
    int s0 = eoff[e], s1 = eoff[e + 1];
    float s = 0.f;
    for (int j = s0; j < s1; j++) {
        int nz = eorder[j];
        s += xw[(size_t)node_idx[nz] * H_ + c];
    }
    eb[(size_t)e * H_ + c] = s * Binv[e];
}

__global__ void node_sum_kernel(const float* __restrict__ eb,
                                const int* __restrict__ edge_idx,
                                const int* __restrict__ norder,
                                const int* __restrict__ noff,
                                const float* __restrict__ Dinv,
                                const float* __restrict__ bias,
                                const float* __restrict__ resid,
                                float* __restrict__ out)
{
    int n = blockIdx.x * 8 + (threadIdx.x >> 5);
    int lane = threadIdx.x & 31;
    int s0 = noff[n], s1 = noff[n + 1];
    float s[8];
#pragma unroll
    for (int k = 0; k < 8; k++) s[k] = 0.f;
    for (int j = s0; j < s1; j++) {
        int e = edge_idx[norder[j]];
        const float* er = eb + (size_t)e * H_;
#pragma unroll
        for (int k = 0; k < 8; k++) s[k] += er[lane + k * 32];
    }
    float di = Dinv[n];
#pragma unroll
    for (int k = 0; k < 8; k++) {
        int c = lane + k * 32;
        out[(size_t)n * H_ + c] = s[k] * di + bias[c] + resid[(size_t)n * H_ + c];
    }
}

__global__ void dis_kernel(const float* __restrict__ deg, float* __restrict__ dis)
{
    int i = blockIdx.x * 256 + threadIdx.x;
    if (i < NN_) {
        float d = deg[i];
        dis[i] = d > 0.f ? rsqrtf(d) : 0.f;
    }
}

// ---------------------------------------------------------------------------
// Host orchestration
// ---------------------------------------------------------------------------
extern "C" void kernel_launch(void* const* d_in, const int* in_sizes, int n_in,
                              void* d_out, int out_size)
{
    (void)in_sizes; (void)n_in; (void)out_size;

    const float* x        = (const float*)d_in[0];
    const int*   hei      = (const int*)d_in[1];
    const int*   node_idx = hei;
    const int*   edge_idx = hei + NNZ_;
    const int*   slen     = (const int*)d_in[2];
    const float* h0       = (const float*)d_in[3];
    const float* W_ih     = (const float*)d_in[4];
    const float* W_hh     = (const float*)d_in[5];
    const float* b_ih     = (const float*)d_in[6];
    const float* b_hh     = (const float*)d_in[7];
    const float* w1 = (const float*)d_in[8];  const float* bb1 = (const float*)d_in[9];
    const float* w2 = (const float*)d_in[10]; const float* bb2 = (const float*)d_in[11];
    const float* w3 = (const float*)d_in[12]; const float* bb3 = (const float*)d_in[13];
    const float* phi = (const float*)d_in[14];
    const float* gw  = (const float*)d_in[15];
    const float* gb  = (const float*)d_in[16];
    float* out = (float*)d_out;

    float *xgall, *h, *h2, *fa, *fb, *xw, *eb, *x2, *deg, *Dinv, *Binv, *dis;
    unsigned char* mask;
    __nv_bfloat16 *whh_h, *whh_l, *yth, *ytl, *wt_h, *wt_l;
    int *perm, *histb, *curb, *startb, *cntb;
    int *ecnt, *ncnt, *ecur, *ncur, *eoff, *noff, *eorder, *norder;
    cudaGetSymbolAddress((void**)&xgall, g_xgall);
    cudaGetSymbolAddress((void**)&h,     g_h);
    cudaGetSymbolAddress((void**)&h2,    g_h2);
    cudaGetSymbolAddress((void**)&fa,    g_fa);
    cudaGetSymbolAddress((void**)&fb,    g_fb);
    cudaGetSymbolAddress((void**)&xw,    g_xw);
    cudaGetSymbolAddress((void**)&eb,    g_eb);
    cudaGetSymbolAddress((void**)&x2,    g_x2);
    cudaGetSymbolAddress((void**)&mask,  g_mask);
    cudaGetSymbolAddress((void**)&deg,   g_deg);
    cudaGetSymbolAddress((void**)&Dinv,  g_Dinv);
    cudaGetSymbolAddress((void**)&Binv,  g_Binv);
    cudaGetSymbolAddress((void**)&dis,   g_dis);
    cudaGetSymbolAddress((void**)&whh_h, g_whh_h);
    cudaGetSymbolAddress((void**)&whh_l, g_whh_l);
    cudaGetSymbolAddress((void**)&yth,   g_yth);
    cudaGetSymbolAddress((void**)&ytl,   g_ytl);
    cudaGetSymbolAddress((void**)&wt_h,  g_wt_h);
    cudaGetSymbolAddress((void**)&wt_l,  g_wt_l);
    cudaGetSymbolAddress((void**)&perm,  g_perm);
    cudaGetSymbolAddress((void**)&histb, g_hist);
    cudaGetSymbolAddress((void**)&curb,  g_cur);
    cudaGetSymbolAddress((void**)&startb,g_start);
    cudaGetSymbolAddress((void**)&cntb,  g_cnt);
    cudaGetSymbolAddress((void**)&ecnt,  g_ecnt);
    cudaGetSymbolAddress((void**)&ncnt,  g_ncnt);
    cudaGetSymbolAddress((void**)&ecur,  g_ecur);
    cudaGetSymbolAddress((void**)&ncur,  g_ncur);
    cudaGetSymbolAddress((void**)&eoff,  g_eoff);
    cudaGetSymbolAddress((void**)&noff,  g_noff);
    cudaGetSymbolAddress((void**)&eorder,g_eorder);
    cudaGetSymbolAddress((void**)&norder,g_norder);

    const int XG_SMEM  = 4 * 128 * XS_ * 2;                  // 90112 B
    const int GRU_SMEM = (2 * 64 * GS_ + 2 * 192 * GS_) * 2; // 73728 B
    cudaFuncSetAttribute(xg_gemm_mma,
                         cudaFuncAttributeMaxDynamicSharedMemorySize, XG_SMEM);
    cudaFuncSetAttribute(gru_step_mma,
                         cudaFuncAttributeMaxDynamicSharedMemorySize, GRU_SMEM);
    cudaFuncSetAttribute(sgemm_nt_mma,
                         cudaFuncAttributeMaxDynamicSharedMemorySize, XG_SMEM);
    cudaFuncSetAttribute(gram_mma,
                         cudaFuncAttributeMaxDynamicSharedMemorySize, XG_SMEM);

    // ---------------- sorts ----------------
    zero_int_kernel<<<1, 256>>>(histb, 32);
    zero_int_kernel<<<1, 256>>>(curb, 32);
    hist_kernel<<<NN_ / 256, 256>>>(slen, histb);
    scan_kernel<<<1, 32>>>(histb, cntb, startb);
    scatter_perm_kernel<<<NN_ / 256, 256>>>(slen, startb, curb, perm);

    zero_int_kernel<<<(E_ + 255) / 256, 256>>>(ecnt, E_);
    zero_int_kernel<<<(NN_ + 255) / 256, 256>>>(ncnt, NN_);
    zero_int_kernel<<<(E_ + 255) / 256, 256>>>(ecur, E_);
    zero_int_kernel<<<(NN_ + 255) / 256, 256>>>(ncur, NN_);
    hist_nz_kernel<<<NNZ_ / 256, 256>>>(node_idx, edge_idx, ncnt, ecnt);
    scan_bins_kernel<<<1, 1024>>>(ecnt, eoff, E_);
    scan_bins_kernel<<<1, 1024>>>(ncnt, noff, NN_);
    scatter_order_kernel<<<NNZ_ / 256, 256>>>(edge_idx, eoff, ecur, eorder);
    scatter_order_kernel<<<NNZ_ / 256, 256>>>(node_idx, noff, ncur, norder);
    inv_int_kernel<<<(E_ + 255) / 256, 256>>>(ecnt, Binv, E_);
    inv_int_kernel<<<(NN_ + 255) / 256, 256>>>(ncnt, Dinv, NN_);

    // ---------------- one-time weight splits ----------------
    split_w_kernel<<<(H3_ * H_ + 255) / 256, 256>>>(W_hh, whh_h, whh_l, H3_ * H_);
    wt_split_kernel<<<dim3(8, 8), dim3(32, 8)>>>(w1, wt_h, wt_l);
    wt_split_kernel<<<dim3(8, 8), dim3(32, 8)>>>(w2, wt_h + H_ * H_, wt_l + H_ * H_);
    wt_split_kernel<<<dim3(8, 8), dim3(32, 8)>>>(w3, wt_h + 2 * H_ * H_, wt_l + 2 * H_ * H_);
    wt_split_kernel<<<dim3(8, 8), dim3(32, 8)>>>(gw, wt_h + 3 * H_ * H_, wt_l + 3 * H_ * H_);

    // ---------------- GRU ----------------
    init_h_kernel<<<NN_ * H_ / 256, 256>>>(h, h0);
    xg_gemm_mma<<<dim3(H3_ / 128, T_ * NN_ / 128), 256, XG_SMEM>>>(
        x, W_ih, b_ih, perm, cntb, xgall);

    float* hrd = h;
    float* hwr = h2;
    for (int t = 0; t < T_; t++) {
        gru_step_mma<<<dim3(H_ / 64, NN_ / 64), 256, GRU_SMEM>>>(
            whh_h, whh_l, b_hh, xgall, hrd, hwr, perm, cntb, fa, t);
        float* tmp = hrd; hrd = hwr; hwr = tmp;
    }
    // fa holds `last` in original row order

    // ---------------- 3 hypergraph conv layers (atomic-free) ----------------
    const float* hgc_in[3]  = {fa, fb, fa};
    float*       hgc_out[3] = {fb, fa, fb};
    const float* hgc_b[3]   = {bb1, bb2, bb3};
    for (int l = 0; l < 3; l++) {
        sgemm_nt_mma<<<dim3(2, NN_ / 128), 256, XG_SMEM>>>(
            hgc_in[l], wt_h + l * H_ * H_, wt_l + l * H_ * H_, xw);
        edge_sum_kernel<<<E_, 256>>>(xw, node_idx, eorder, eoff, Binv, eb);
        node_sum_kernel<<<NN_ / 8, 256>>>(eb, edge_idx, norder, noff, Dinv,
                                          hgc_b[l], hgc_in[l], hgc_out[l]);
    }
    // fb holds o3

    // ---------------- final dense GCN ----------------
    sgemm_nt_mma<<<dim3(2, NN_ / 128), 256, XG_SMEM>>>(
        fb, wt_h + 3 * H_ * H_, wt_l + 3 * H_ * H_, x2);

    zero_kernel<<<(NN_ / 4 + 255) / 256, 256>>>(deg, NN_ / 4);
    gram_mma<<<64 * 65 / 2, 256, XG_SMEM>>>(fb, mask, deg, phi);
    dis_kernel<<<(NN_ + 255) / 256, 256>>>(deg, dis);
    yt_split_kernel<<<dim3(NN_ / 32, GCN_ / 32), dim3(32, 8)>>>(x2, dis, yth, ytl);
    gcn_gemm_mma<<<dim3(GCN_ / 64, NN_ / 128), 256>>>(mask, yth, ytl, dis, gb, out);
}